// round 1
// baseline (speedup 1.0000x reference)
#include <cuda_runtime.h>
#include <math.h>

// Problem constants
#define NB   16
#define LEN  512
#define DIM  1024
#define HEADS 16
#define DK   64
#define FF   4096
#define TOK  (NB * LEN)          // 8192 rows

// Scratch layout (floats)
#define OFF_Q 0ull
#define OFF_K (OFF_Q + (size_t)TOK * DIM)
#define OFF_V (OFF_K + (size_t)TOK * DIM)
#define OFF_C (OFF_V + (size_t)TOK * DIM)
#define OFF_F (OFF_C + (size_t)TOK * DIM)
#define OFF_S (OFF_F + (size_t)TOK * FF)
#define SCRATCH_FLOATS (OFF_S + (size_t)NB * HEADS * LEN * LEN)

__device__ float g_scratch[SCRATCH_FLOATS];

// ---------------------------------------------------------------------------
// Generic tiled SGEMM: C[M,N] = A[M,K] @ B[K,N] + bias (+gelu) (+resid)
// 128x128 tile, BK=16, 256 threads, 8x8 per thread. M,N,K multiples of 128/16.
// ---------------------------------------------------------------------------
__device__ __forceinline__ float gelu_exact(float v) {
    return 0.5f * v * (1.0f + erff(v * 0.70710678118654752f));
}

__global__ __launch_bounds__(256) void gemm_bias_kernel(
    const float* __restrict__ A, const float* __restrict__ B,
    const float* __restrict__ bias, const float* __restrict__ resid,
    float* __restrict__ C, int M, int N, int K, int act)
{
    __shared__ float As[16][128];
    __shared__ float Bs[16][128];
    const int tid = threadIdx.x;
    const int bm = blockIdx.y * 128;
    const int bn = blockIdx.x * 128;
    const int tx = tid & 15;
    const int ty = tid >> 4;
    float acc[8][8] = {};

    for (int k0 = 0; k0 < K; k0 += 16) {
        #pragma unroll
        for (int i = 0; i < 2; i++) {
            int id = tid * 2 + i;
            // A tile: 128 rows x 16 cols, store transposed As[k][m]
            int ra = id >> 2;
            int ca = (id & 3) << 2;
            float4 av = *(const float4*)(A + (size_t)(bm + ra) * K + k0 + ca);
            As[ca + 0][ra] = av.x;
            As[ca + 1][ra] = av.y;
            As[ca + 2][ra] = av.z;
            As[ca + 3][ra] = av.w;
            // B tile: 16 rows x 128 cols
            int rb = id >> 5;
            int cb = (id & 31) << 2;
            *(float4*)(&Bs[rb][cb]) = *(const float4*)(B + (size_t)(k0 + rb) * N + bn + cb);
        }
        __syncthreads();
        #pragma unroll
        for (int k = 0; k < 16; k++) {
            float a[8], b[8];
            *(float4*)&a[0] = *(float4*)&As[k][ty * 8];
            *(float4*)&a[4] = *(float4*)&As[k][ty * 8 + 4];
            *(float4*)&b[0] = *(float4*)&Bs[k][tx * 8];
            *(float4*)&b[4] = *(float4*)&Bs[k][tx * 8 + 4];
            #pragma unroll
            for (int i = 0; i < 8; i++)
                #pragma unroll
                for (int j = 0; j < 8; j++)
                    acc[i][j] = fmaf(a[i], b[j], acc[i][j]);
        }
        __syncthreads();
    }

    #pragma unroll
    for (int i = 0; i < 8; i++) {
        int row = bm + ty * 8 + i;
        #pragma unroll
        for (int j = 0; j < 8; j += 4) {
            int col = bn + tx * 8 + j;
            float4 o;
            o.x = acc[i][j + 0] + bias[col + 0];
            o.y = acc[i][j + 1] + bias[col + 1];
            o.z = acc[i][j + 2] + bias[col + 2];
            o.w = acc[i][j + 3] + bias[col + 3];
            if (act) {
                o.x = gelu_exact(o.x);
                o.y = gelu_exact(o.y);
                o.z = gelu_exact(o.z);
                o.w = gelu_exact(o.w);
            }
            if (resid) {
                float4 rv = *(const float4*)(resid + (size_t)row * N + col);
                o.x += rv.x; o.y += rv.y; o.z += rv.z; o.w += rv.w;
            }
            *(float4*)(C + (size_t)row * N + col) = o;
        }
    }
}

// ---------------------------------------------------------------------------
// Attention scores: S[b,q,k] = (Q[b,q,:] . K[b,k,:]) / 8, masked -> -inf
// Q,K stored as [n*L, DIM] with head slice at h*DK. Batch b = n*HEADS + h.
// Block: 64x64 score tile, 256 threads, 4x4 each. Full DK=64 in one pass.
// ---------------------------------------------------------------------------
__global__ __launch_bounds__(256) void attn_scores_kernel(
    const float* __restrict__ Q, const float* __restrict__ Kb,
    const unsigned char* __restrict__ mask, float* __restrict__ S)
{
    int b = blockIdx.z;
    int n = b >> 4;
    int h = b & 15;
    int q0 = blockIdx.y * 64;
    int k0 = blockIdx.x * 64;
    const float* Qp = Q + (size_t)n * LEN * DIM + h * DK;
    const float* Kp = Kb + (size_t)n * LEN * DIM + h * DK;
    __shared__ float Qs[64][DK + 1];
    __shared__ float Ks[64][DK + 1];
    int tid = threadIdx.x;

    #pragma unroll
    for (int i = 0; i < 4; i++) {
        int id = tid + i * 256;
        int r = id >> 4;
        int c = (id & 15) << 2;
        float4 qv = *(const float4*)(Qp + (size_t)(q0 + r) * DIM + c);
        Qs[r][c + 0] = qv.x; Qs[r][c + 1] = qv.y; Qs[r][c + 2] = qv.z; Qs[r][c + 3] = qv.w;
        float4 kv = *(const float4*)(Kp + (size_t)(k0 + r) * DIM + c);
        Ks[r][c + 0] = kv.x; Ks[r][c + 1] = kv.y; Ks[r][c + 2] = kv.z; Ks[r][c + 3] = kv.w;
    }
    __syncthreads();

    int tx = tid & 15;
    int ty = tid >> 4;
    float acc[4][4] = {};
    #pragma unroll 8
    for (int d = 0; d < DK; d++) {
        float a[4], bb[4];
        #pragma unroll
        for (int i = 0; i < 4; i++) a[i]  = Qs[ty * 4 + i][d];
        #pragma unroll
        for (int j = 0; j < 4; j++) bb[j] = Ks[tx * 4 + j][d];
        #pragma unroll
        for (int i = 0; i < 4; i++)
            #pragma unroll
            for (int j = 0; j < 4; j++)
                acc[i][j] = fmaf(a[i], bb[j], acc[i][j]);
    }

    const unsigned char* mp = mask + (size_t)n * LEN * LEN;
    float* Sp = S + (size_t)b * LEN * LEN;
    #pragma unroll
    for (int i = 0; i < 4; i++) {
        int q = q0 + ty * 4 + i;
        #pragma unroll
        for (int j = 0; j < 4; j++) {
            int k = k0 + tx * 4 + j;
            float v = acc[i][j] * 0.125f;
            if (mp[(size_t)q * LEN + k]) v = -INFINITY;
            Sp[(size_t)q * LEN + k] = v;
        }
    }
}

// ---------------------------------------------------------------------------
// Row softmax over L=512 (in place). Fully-masked rows produce zeros
// (matches jnp.nan_to_num after softmax of all -inf).
// ---------------------------------------------------------------------------
__global__ __launch_bounds__(128) void softmax_kernel(float* __restrict__ S)
{
    size_t row = blockIdx.x;
    float4* p = (float4*)(S + row * LEN);
    int tid = threadIdx.x;
    float4 v = p[tid];
    __shared__ float ra[4], rb[4];

    float mx = fmaxf(fmaxf(v.x, v.y), fmaxf(v.z, v.w));
    #pragma unroll
    for (int o = 16; o; o >>= 1) mx = fmaxf(mx, __shfl_xor_sync(0xffffffffu, mx, o));
    if ((tid & 31) == 0) ra[tid >> 5] = mx;
    __syncthreads();
    mx = fmaxf(fmaxf(ra[0], ra[1]), fmaxf(ra[2], ra[3]));

    float4 e;
    if (mx == -INFINITY) {
        e.x = e.y = e.z = e.w = 0.0f;
    } else {
        e.x = expf(v.x - mx); e.y = expf(v.y - mx);
        e.z = expf(v.z - mx); e.w = expf(v.w - mx);
    }
    float s = e.x + e.y + e.z + e.w;
    #pragma unroll
    for (int o = 16; o; o >>= 1) s += __shfl_xor_sync(0xffffffffu, s, o);
    if ((tid & 31) == 0) rb[tid >> 5] = s;
    __syncthreads();
    s = rb[0] + rb[1] + rb[2] + rb[3];

    float inv = (s > 0.0f) ? 1.0f / s : 0.0f;
    e.x *= inv; e.y *= inv; e.z *= inv; e.w *= inv;
    p[tid] = e;
}

// ---------------------------------------------------------------------------
// Context: ctx[b,q,d] = sum_k attn[b,q,k] * V[b,k,d]; written back to the
// interleaved [n*L, DIM] layout at head slice h*DK.
// Block: 64 q-rows x 64 d, 256 threads, 4x4 each, K-loop in 64-chunks.
// ---------------------------------------------------------------------------
__global__ __launch_bounds__(256) void attn_ctx_kernel(
    const float* __restrict__ S, const float* __restrict__ V,
    float* __restrict__ C)
{
    int b = blockIdx.y;
    int n = b >> 4;
    int h = b & 15;
    int q0 = blockIdx.x * 64;
    const float* Sp = S + (size_t)b * LEN * LEN;
    const float* Vp = V + (size_t)n * LEN * DIM + h * DK;
    __shared__ float As[64][65];
    __shared__ float Vs[64][DK];
    int tid = threadIdx.x;
    int tx = tid & 15;
    int ty = tid >> 4;
    float acc[4][4] = {};

    for (int kc = 0; kc < LEN; kc += 64) {
        #pragma unroll
        for (int i = 0; i < 4; i++) {
            int id = tid + i * 256;
            int r = id >> 4;
            int c = (id & 15) << 2;
            float4 av = *(const float4*)(Sp + (size_t)(q0 + r) * LEN + kc + c);
            As[r][c + 0] = av.x; As[r][c + 1] = av.y; As[r][c + 2] = av.z; As[r][c + 3] = av.w;
            float4 vv = *(const float4*)(Vp + (size_t)(kc + r) * DIM + c);
            *(float4*)(&Vs[r][c]) = vv;
        }
        __syncthreads();
        #pragma unroll 8
        for (int k = 0; k < 64; k++) {
            float a[4], bb[4];
            #pragma unroll
            for (int i = 0; i < 4; i++) a[i] = As[ty * 4 + i][k];
            *(float4*)&bb[0] = *(float4*)&Vs[k][tx * 4];
            #pragma unroll
            for (int i = 0; i < 4; i++)
                #pragma unroll
                for (int j = 0; j < 4; j++)
                    acc[i][j] = fmaf(a[i], bb[j], acc[i][j]);
        }
        __syncthreads();
    }

    #pragma unroll
    for (int i = 0; i < 4; i++) {
        size_t row = (size_t)n * LEN + q0 + ty * 4 + i;
        float4 o = make_float4(acc[i][0], acc[i][1], acc[i][2], acc[i][3]);
        *(float4*)(C + row * DIM + h * DK + tx * 4) = o;
    }
}

// ---------------------------------------------------------------------------
// LayerNorm over last dim (1024), two-pass, 256 threads x float4.
// ---------------------------------------------------------------------------
__global__ __launch_bounds__(256) void layernorm_kernel(
    const float* __restrict__ X, const float* __restrict__ gg,
    const float* __restrict__ bb, float* __restrict__ Y)
{
    int row = blockIdx.x;
    int tid = threadIdx.x;
    const float4* Xp = (const float4*)(X + (size_t)row * DIM);
    float4 x = Xp[tid];
    __shared__ float red[8];

    float s = x.x + x.y + x.z + x.w;
    #pragma unroll
    for (int o = 16; o; o >>= 1) s += __shfl_xor_sync(0xffffffffu, s, o);
    if ((tid & 31) == 0) red[tid >> 5] = s;
    __syncthreads();
    float mean = (red[0] + red[1] + red[2] + red[3] +
                  red[4] + red[5] + red[6] + red[7]) * (1.0f / DIM);

    float d0 = x.x - mean, d1 = x.y - mean, d2 = x.z - mean, d3 = x.w - mean;
    float s2 = d0 * d0 + d1 * d1 + d2 * d2 + d3 * d3;
    __syncthreads();
    #pragma unroll
    for (int o = 16; o; o >>= 1) s2 += __shfl_xor_sync(0xffffffffu, s2, o);
    if ((tid & 31) == 0) red[tid >> 5] = s2;
    __syncthreads();
    float var = (red[0] + red[1] + red[2] + red[3] +
                 red[4] + red[5] + red[6] + red[7]) * (1.0f / DIM);
    float rs = rsqrtf(var + 1e-5f);

    float4 gv = ((const float4*)gg)[tid];
    float4 bv = ((const float4*)bb)[tid];
    float4 y;
    y.x = d0 * rs * gv.x + bv.x;
    y.y = d1 * rs * gv.y + bv.y;
    y.z = d2 * rs * gv.z + bv.z;
    y.w = d3 * rs * gv.w + bv.w;
    ((float4*)(Y + (size_t)row * DIM))[tid] = y;
}

// ---------------------------------------------------------------------------
// Launcher
// ---------------------------------------------------------------------------
extern "C" void kernel_launch(void* const* d_in, const int* in_sizes, int n_in,
                              void* d_out, int out_size)
{
    const float*         x     = (const float*)d_in[0];
    const unsigned char* mask  = (const unsigned char*)d_in[1];
    const float* WQ = (const float*)d_in[2];
    const float* bQ = (const float*)d_in[3];
    const float* WK = (const float*)d_in[4];
    const float* bK = (const float*)d_in[5];
    const float* WV = (const float*)d_in[6];
    const float* bV = (const float*)d_in[7];
    const float* WO = (const float*)d_in[8];
    const float* bO = (const float*)d_in[9];
    const float* g0 = (const float*)d_in[10];
    const float* b0 = (const float*)d_in[11];
    const float* W1 = (const float*)d_in[12];
    const float* b1 = (const float*)d_in[13];
    const float* W2 = (const float*)d_in[14];
    const float* b2 = (const float*)d_in[15];
    const float* g1 = (const float*)d_in[16];
    const float* b1n = (const float*)d_in[17];
    float* out = (float*)d_out;

    float* base = nullptr;
    cudaGetSymbolAddress((void**)&base, g_scratch);
    float* Q  = base + OFF_Q;
    float* K  = base + OFF_K;
    float* V  = base + OFF_V;
    float* C  = base + OFF_C;
    float* F  = base + OFF_F;
    float* S  = base + OFF_S;
    float* T0 = Q;   // mha + x (Q dead after scores)
    float* H  = K;   // ln0 output (K dead after scores)
    float* T1 = V;   // ffn + h (V dead after ctx)

    dim3 gD(DIM / 128, TOK / 128);   // N=1024 GEMMs
    dim3 gF(FF  / 128, TOK / 128);   // N=4096 GEMM

    // QKV projections
    gemm_bias_kernel<<<gD, 256>>>(x, WQ, bQ, nullptr, Q, TOK, DIM, DIM, 0);
    gemm_bias_kernel<<<gD, 256>>>(x, WK, bK, nullptr, K, TOK, DIM, DIM, 0);
    gemm_bias_kernel<<<gD, 256>>>(x, WV, bV, nullptr, V, TOK, DIM, DIM, 0);

    // Attention
    attn_scores_kernel<<<dim3(LEN / 64, LEN / 64, NB * HEADS), 256>>>(Q, K, mask, S);
    softmax_kernel<<<NB * HEADS * LEN, 128>>>(S);
    attn_ctx_kernel<<<dim3(LEN / 64, NB * HEADS), 256>>>(S, V, C);

    // O projection + residual, layernorm0
    gemm_bias_kernel<<<gD, 256>>>(C, WO, bO, x, T0, TOK, DIM, DIM, 0);
    layernorm_kernel<<<TOK, 256>>>(T0, g0, b0, H);

    // FFN
    gemm_bias_kernel<<<gF, 256>>>(H, W1, b1, nullptr, F, TOK, FF, DIM, 1);
    gemm_bias_kernel<<<gD, 256>>>(F, W2, b2, H, T1, TOK, DIM, FF, 0);

    // Final layernorm -> output
    layernorm_kernel<<<TOK, 256>>>(T1, g1, b1n, out);
}

// round 3
// speedup vs baseline: 1.2058x; 1.2058x over previous
#include <cuda_runtime.h>
#include <cuda_bf16.h>
#include <math.h>
#include <stdint.h>

// Problem constants
#define NB    16
#define LEN   512
#define DIM   1024
#define HEADS 16
#define DK    64
#define FF    4096
#define TOK   (NB * LEN)          // 8192 rows

// ---------------------------------------------------------------------------
// Scratch layout (units: floats). bf16 regions take half the float count.
// ---------------------------------------------------------------------------
#define MFe ((size_t)1 << 20)
#define OFF_Q    (0 * MFe)            // fp32 8192x1024   (reused as T0)
#define OFF_KK   (8 * MFe)            // fp32 8192x1024   (reused as H)
#define OFF_V    (16 * MFe)           // fp32 8192x1024   (reused as T1)
#define OFF_S    (24 * MFe)           // fp32 16*16*512*512 = 64M
#define OFF_XH   (88 * MFe)           // bf16 8192x1024 -> 4M floats
#define OFF_XL   (92 * MFe)
#define OFF_WQH  (96 * MFe)           // each bf16 1024x1024 -> 0.5M floats
#define OFF_WQL  (OFF_WQH + MFe/2)
#define OFF_WKH  (97 * MFe)
#define OFF_WKL  (OFF_WKH + MFe/2)
#define OFF_WVH  (98 * MFe)
#define OFF_WVL  (OFF_WVH + MFe/2)
#define OFF_WOH  (99 * MFe)
#define OFF_WOL  (OFF_WOH + MFe/2)
#define OFF_W1H  (100 * MFe)          // bf16 4096x1024 -> 2M floats
#define OFF_W1L  (102 * MFe)
#define OFF_W2H  (104 * MFe)          // bf16 1024x4096 -> 2M floats
#define OFF_W2L  (106 * MFe)
#define OFF_CH   (108 * MFe)          // bf16 8192x1024 -> 4M floats
#define OFF_CL   (112 * MFe)
#define OFF_HH   (116 * MFe)
#define OFF_HL   (120 * MFe)
#define OFF_FH   (124 * MFe)          // bf16 8192x4096 -> 16M floats
#define OFF_FL   (140 * MFe)
#define SCRATCH_FLOATS (156 * MFe)

__device__ float g_scratch[SCRATCH_FLOATS];

// ---------------------------------------------------------------------------
// PTX helpers (sm_80-baseline instructions only: cp.async, ldmatrix, mma.sync)
// ---------------------------------------------------------------------------
__device__ __forceinline__ uint32_t s2u(const void* p) {
    uint32_t r;
    asm("{ .reg .u64 t; cvta.to.shared.u64 t, %1; cvt.u32.u64 %0, t; }"
        : "=r"(r) : "l"(p));
    return r;
}

__device__ __forceinline__ void cp16(uint32_t dst, const void* src) {
    asm volatile("cp.async.cg.shared.global [%0], [%1], 16;" :: "r"(dst), "l"(src));
}
__device__ __forceinline__ void cp_commit() {
    asm volatile("cp.async.commit_group;" ::: "memory");
}
template <int N> __device__ __forceinline__ void cp_wait() {
    asm volatile("cp.async.wait_group %0;" :: "n"(N) : "memory");
}

__device__ __forceinline__ void ldsm4(uint32_t* r, uint32_t addr) {
    asm volatile("ldmatrix.sync.aligned.m8n8.x4.shared.b16 {%0,%1,%2,%3}, [%4];"
                 : "=r"(r[0]), "=r"(r[1]), "=r"(r[2]), "=r"(r[3]) : "r"(addr));
}

__device__ __forceinline__ void mma_bf16(float* d, const uint32_t* a,
                                         uint32_t b0, uint32_t b1) {
    asm volatile(
        "mma.sync.aligned.m16n8k16.row.col.f32.bf16.bf16.f32 "
        "{%0,%1,%2,%3}, {%4,%5,%6,%7}, {%8,%9}, {%0,%1,%2,%3};"
        : "+f"(d[0]), "+f"(d[1]), "+f"(d[2]), "+f"(d[3])
        : "r"(a[0]), "r"(a[1]), "r"(a[2]), "r"(a[3]), "r"(b0), "r"(b1));
}

__device__ __forceinline__ float gelu_exact(float v) {
    return 0.5f * v * (1.0f + erff(v * 0.70710678118654752f));
}

__device__ __forceinline__ uint32_t pack_hi(float a, float b, float* ra, float* rb) {
    __nv_bfloat16 ha = __float2bfloat16(a);
    __nv_bfloat16 hb = __float2bfloat16(b);
    *ra = a - __bfloat162float(ha);
    *rb = b - __bfloat162float(hb);
    return (uint32_t)__bfloat16_as_ushort(ha) |
           ((uint32_t)__bfloat16_as_ushort(hb) << 16);
}
__device__ __forceinline__ uint32_t pack_bf(float a, float b) {
    __nv_bfloat16 ha = __float2bfloat16(a);
    __nv_bfloat16 hb = __float2bfloat16(b);
    return (uint32_t)__bfloat16_as_ushort(ha) |
           ((uint32_t)__bfloat16_as_ushort(hb) << 16);
}

// ---------------------------------------------------------------------------
// bf16-split GEMM via mma.sync:
//   out = act( Ahi/lo[M,K] @ (Bhi/lo[N,K])^T + bias ) (+ resid)
// CTA tile 128x128, BK=32, 8 warps (64x32 each), 3-stage cp.async pipeline.
// outputs: fp32 (outF) and/or bf16 hi/lo split (outHi/outLo). Null = skip.
// ---------------------------------------------------------------------------
#define G_STAGES 3
#define SA_STRIDE 40                          // bf16 units per smem row (80 B)
#define G_TILE_B (128 * SA_STRIDE * 2)        // 10240 B per 128x32 tile
#define G_STAGE_B (4 * G_TILE_B)              // Ahi, Alo, Bhi, Blo
#define G_SMEM_DYN (G_STAGES * G_STAGE_B)     // 122880 B

__device__ __forceinline__ void load_tile(uint32_t sbase, const __nv_bfloat16* g,
                                          int K, int k0, int tid) {
    #pragma unroll
    for (int i = 0; i < 2; i++) {
        int c = tid + i * 256;                // 0..511 : 128 rows x 4 chunks
        int row = c >> 2;
        int col = c & 3;
        cp16(sbase + (uint32_t)(row * (SA_STRIDE * 2) + col * 16),
             g + (size_t)row * K + k0 + col * 8);
    }
}

extern __shared__ char g_dsm[];

__global__ void __launch_bounds__(256, 1) gemm_mma_kernel(
    const __nv_bfloat16* __restrict__ Ahi, const __nv_bfloat16* __restrict__ Alo,
    const __nv_bfloat16* __restrict__ Bhi, const __nv_bfloat16* __restrict__ Blo,
    const float* __restrict__ bias, const float* __restrict__ resid,
    float* __restrict__ outF,
    __nv_bfloat16* __restrict__ outHi, __nv_bfloat16* __restrict__ outLo,
    int M, int N, int K, int gelu)
{
    const int tid = threadIdx.x;
    const int wid = tid >> 5;
    const int lane = tid & 31;
    const int wr = wid >> 2;       // warp row 0-1 (64 rows each)
    const int wc = wid & 3;        // warp col 0-3 (32 cols each)
    const int bm = blockIdx.y * 128;
    const int bn = blockIdx.x * 128;

    uint32_t db = s2u(g_dsm);

    const __nv_bfloat16* Ah = Ahi + (size_t)bm * K;
    const __nv_bfloat16* Al = Alo + (size_t)bm * K;
    const __nv_bfloat16* Bh = Bhi + (size_t)bn * K;
    const __nv_bfloat16* Bl = Blo + (size_t)bn * K;

    float acc[4][4][4] = {};

    const int nk = K / 32;

    // Prologue: stages 0,1
    #pragma unroll
    for (int s = 0; s < 2; s++) {
        uint32_t sb = db + s * G_STAGE_B;
        load_tile(sb + 0 * G_TILE_B, Ah, K, s * 32, tid);
        load_tile(sb + 1 * G_TILE_B, Al, K, s * 32, tid);
        load_tile(sb + 2 * G_TILE_B, Bh, K, s * 32, tid);
        load_tile(sb + 3 * G_TILE_B, Bl, K, s * 32, tid);
        cp_commit();
    }

    // ldmatrix lane addressing (byte offsets within a tile)
    const int a_row = (lane & 15);                 // + m0
    const int a_ko  = (lane >> 4) * 8;             // k offset within k16
    const int b_row = ((lane >> 4) * 8) + (lane & 7);  // + n0
    const int b_ko  = ((lane >> 3) & 1) * 8;

    for (int kt = 0; kt < nk; kt++) {
        uint32_t sb = db + (uint32_t)(kt % G_STAGES) * G_STAGE_B;
        cp_wait<1>();
        __syncthreads();

        uint32_t sAh = sb + 0 * G_TILE_B;
        uint32_t sAl = sb + 1 * G_TILE_B;
        uint32_t sBh = sb + 2 * G_TILE_B;
        uint32_t sBl = sb + 3 * G_TILE_B;

        #pragma unroll
        for (int k16 = 0; k16 < 2; k16++) {
            uint32_t ah[4][4], al[4][4], bh[2][4], bl[2][4];
            #pragma unroll
            for (int mi = 0; mi < 4; mi++) {
                uint32_t off = (uint32_t)((wr * 64 + mi * 16 + a_row) * (SA_STRIDE * 2)
                                          + (k16 * 16 + a_ko) * 2);
                ldsm4(ah[mi], sAh + off);
                ldsm4(al[mi], sAl + off);
            }
            #pragma unroll
            for (int nf = 0; nf < 2; nf++) {
                uint32_t off = (uint32_t)((wc * 32 + nf * 16 + b_row) * (SA_STRIDE * 2)
                                          + (k16 * 16 + b_ko) * 2);
                ldsm4(bh[nf], sBh + off);
                ldsm4(bl[nf], sBl + off);
            }
            #pragma unroll
            for (int mi = 0; mi < 4; mi++) {
                #pragma unroll
                for (int ni = 0; ni < 4; ni++) {
                    int nf = ni >> 1, o = (ni & 1) * 2;
                    mma_bf16(acc[mi][ni], ah[mi], bh[nf][o], bh[nf][o + 1]);
                    mma_bf16(acc[mi][ni], ah[mi], bl[nf][o], bl[nf][o + 1]);
                    mma_bf16(acc[mi][ni], al[mi], bh[nf][o], bh[nf][o + 1]);
                }
            }
        }
        __syncthreads();

        if (kt + 2 < nk) {
            uint32_t nb = db + (uint32_t)((kt + 2) % G_STAGES) * G_STAGE_B;
            int k0 = (kt + 2) * 32;
            load_tile(nb + 0 * G_TILE_B, Ah, K, k0, tid);
            load_tile(nb + 1 * G_TILE_B, Al, K, k0, tid);
            load_tile(nb + 2 * G_TILE_B, Bh, K, k0, tid);
            load_tile(nb + 3 * G_TILE_B, Bl, K, k0, tid);
        }
        cp_commit();
    }

    // Epilogue
    const int tq = lane >> 2;
    const int tc = (lane & 3) * 2;
    #pragma unroll
    for (int mi = 0; mi < 4; mi++) {
        #pragma unroll
        for (int ni = 0; ni < 4; ni++) {
            int col = bn + wc * 32 + ni * 8 + tc;
            float bx = bias[col], by = bias[col + 1];
            #pragma unroll
            for (int half = 0; half < 2; half++) {
                int row = bm + wr * 64 + mi * 16 + tq + half * 8;
                float v0 = acc[mi][ni][half * 2 + 0] + bx;
                float v1 = acc[mi][ni][half * 2 + 1] + by;
                if (gelu) { v0 = gelu_exact(v0); v1 = gelu_exact(v1); }
                if (resid) {
                    float2 rv = *(const float2*)(resid + (size_t)row * N + col);
                    v0 += rv.x; v1 += rv.y;
                }
                if (outF)
                    *(float2*)(outF + (size_t)row * N + col) = make_float2(v0, v1);
                if (outHi) {
                    float ra, rb;
                    uint32_t hv = pack_hi(v0, v1, &ra, &rb);
                    *(uint32_t*)(outHi + (size_t)row * N + col) = hv;
                    *(uint32_t*)(outLo + (size_t)row * N + col) = pack_bf(ra, rb);
                }
            }
        }
    }
}

// ---------------------------------------------------------------------------
// Elementwise fp32 -> bf16 hi/lo split
// ---------------------------------------------------------------------------
__global__ __launch_bounds__(256) void split_kernel(
    const float4* __restrict__ X, uint2* __restrict__ Hh, uint2* __restrict__ Ll, int n4)
{
    int i = blockIdx.x * 256 + threadIdx.x;
    if (i >= n4) return;
    float4 v = X[i];
    float r0, r1, r2, r3;
    uint32_t h0 = pack_hi(v.x, v.y, &r0, &r1);
    uint32_t h1 = pack_hi(v.z, v.w, &r2, &r3);
    Hh[i] = make_uint2(h0, h1);
    Ll[i] = make_uint2(pack_bf(r0, r1), pack_bf(r2, r3));
}

// ---------------------------------------------------------------------------
// Transposed split: W[Kr,Nc] fp32 -> TH/TL [Nc,Kr] bf16 (K-major for mma B)
// ---------------------------------------------------------------------------
__global__ __launch_bounds__(256) void transpose_split_kernel(
    const float* __restrict__ W, __nv_bfloat16* __restrict__ TH,
    __nv_bfloat16* __restrict__ TL, int Kr, int Nc)
{
    __shared__ float t[32][33];
    int n0 = blockIdx.x * 32, k0 = blockIdx.y * 32;
    int tx = threadIdx.x, ty = threadIdx.y;     // 32 x 8
    #pragma unroll
    for (int i = 0; i < 4; i++)
        t[ty + i * 8][tx] = W[(size_t)(k0 + ty + i * 8) * Nc + n0 + tx];
    __syncthreads();
    #pragma unroll
    for (int i = 0; i < 4; i++) {
        int n = n0 + ty + i * 8;
        int k = k0 + tx;
        float v = t[tx][ty + i * 8];
        __nv_bfloat16 h = __float2bfloat16(v);
        TH[(size_t)n * Kr + k] = h;
        TL[(size_t)n * Kr + k] = __float2bfloat16(v - __bfloat162float(h));
    }
}

// ---------------------------------------------------------------------------
// Attention scores (fp32): S[b,q,k] = (Q.K)/8, mask -> -inf
// ---------------------------------------------------------------------------
__global__ __launch_bounds__(256) void attn_scores_kernel(
    const float* __restrict__ Q, const float* __restrict__ Kb,
    const unsigned char* __restrict__ mask, float* __restrict__ S)
{
    int b = blockIdx.z;
    int n = b >> 4;
    int h = b & 15;
    int q0 = blockIdx.y * 64;
    int k0 = blockIdx.x * 64;
    const float* Qp = Q + (size_t)n * LEN * DIM + h * DK;
    const float* Kp = Kb + (size_t)n * LEN * DIM + h * DK;
    __shared__ float Qs[64][68];
    __shared__ float Ks[64][68];
    int tid = threadIdx.x;

    #pragma unroll
    for (int i = 0; i < 4; i++) {
        int id = tid + i * 256;
        int r = id >> 4;
        int c = (id & 15) << 2;
        *(float4*)&Qs[r][c] = *(const float4*)(Qp + (size_t)(q0 + r) * DIM + c);
        *(float4*)&Ks[r][c] = *(const float4*)(Kp + (size_t)(k0 + r) * DIM + c);
    }
    __syncthreads();

    int tx = tid & 15;
    int ty = tid >> 4;
    float acc[4][4] = {};
    #pragma unroll
    for (int d = 0; d < DK; d += 4) {
        float4 a[4], bb[4];
        #pragma unroll
        for (int i = 0; i < 4; i++) a[i]  = *(const float4*)&Qs[ty * 4 + i][d];
        #pragma unroll
        for (int j = 0; j < 4; j++) bb[j] = *(const float4*)&Ks[tx * 4 + j][d];
        #pragma unroll
        for (int i = 0; i < 4; i++)
            #pragma unroll
            for (int j = 0; j < 4; j++)
                acc[i][j] += a[i].x * bb[j].x + a[i].y * bb[j].y +
                             a[i].z * bb[j].z + a[i].w * bb[j].w;
    }

    const unsigned char* mp = mask + (size_t)n * LEN * LEN;
    float* Sp = S + (size_t)b * LEN * LEN;
    #pragma unroll
    for (int i = 0; i < 4; i++) {
        int q = q0 + ty * 4 + i;
        #pragma unroll
        for (int j = 0; j < 4; j++) {
            int k = k0 + tx * 4 + j;
            float v = acc[i][j] * 0.125f;
            if (mp[(size_t)q * LEN + k]) v = -INFINITY;
            Sp[(size_t)q * LEN + k] = v;
        }
    }
}

// ---------------------------------------------------------------------------
// Row softmax over L=512 (in place); fully-masked rows -> 0
// ---------------------------------------------------------------------------
__global__ __launch_bounds__(128) void softmax_kernel(float* __restrict__ S)
{
    size_t row = blockIdx.x;
    float4* p = (float4*)(S + row * LEN);
    int tid = threadIdx.x;
    float4 v = p[tid];
    __shared__ float ra[4], rb[4];

    float mx = fmaxf(fmaxf(v.x, v.y), fmaxf(v.z, v.w));
    #pragma unroll
    for (int o = 16; o; o >>= 1) mx = fmaxf(mx, __shfl_xor_sync(0xffffffffu, mx, o));
    if ((tid & 31) == 0) ra[tid >> 5] = mx;
    __syncthreads();
    mx = fmaxf(fmaxf(ra[0], ra[1]), fmaxf(ra[2], ra[3]));

    float4 e;
    if (mx == -INFINITY) {
        e.x = e.y = e.z = e.w = 0.0f;
    } else {
        e.x = expf(v.x - mx); e.y = expf(v.y - mx);
        e.z = expf(v.z - mx); e.w = expf(v.w - mx);
    }
    float s = e.x + e.y + e.z + e.w;
    #pragma unroll
    for (int o = 16; o; o >>= 1) s += __shfl_xor_sync(0xffffffffu, s, o);
    if ((tid & 31) == 0) rb[tid >> 5] = s;
    __syncthreads();
    s = rb[0] + rb[1] + rb[2] + rb[3];

    float inv = (s > 0.0f) ? 1.0f / s : 0.0f;
    e.x *= inv; e.y *= inv; e.z *= inv; e.w *= inv;
    p[tid] = e;
}

// ---------------------------------------------------------------------------
// Context: ctx[b,q,d] = sum_k attn * V; writes bf16 hi/lo split directly.
// ---------------------------------------------------------------------------
__global__ __launch_bounds__(256) void attn_ctx_kernel(
    const float* __restrict__ S, const float* __restrict__ V,
    __nv_bfloat16* __restrict__ Chi, __nv_bfloat16* __restrict__ Clo)
{
    int b = blockIdx.y;
    int n = b >> 4;
    int h = b & 15;
    int q0 = blockIdx.x * 64;
    const float* Sp = S + (size_t)b * LEN * LEN;
    const float* Vp = V + (size_t)n * LEN * DIM + h * DK;
    __shared__ float As[64][68];
    __shared__ float Vs[64][68];
    int tid = threadIdx.x;
    int tx = tid & 15;
    int ty = tid >> 4;
    float acc[4][4] = {};

    for (int kc = 0; kc < LEN; kc += 64) {
        #pragma unroll
        for (int i = 0; i < 4; i++) {
            int id = tid + i * 256;
            int r = id >> 4;
            int c = (id & 15) << 2;
            *(float4*)&As[r][c] = *(const float4*)(Sp + (size_t)(q0 + r) * LEN + kc + c);
            *(float4*)&Vs[r][c] = *(const float4*)(Vp + (size_t)(kc + r) * DIM + c);
        }
        __syncthreads();
        #pragma unroll
        for (int k = 0; k < 64; k += 4) {
            float4 a[4];
            float bb[4][4];
            #pragma unroll
            for (int i = 0; i < 4; i++) a[i] = *(const float4*)&As[ty * 4 + i][k];
            #pragma unroll
            for (int kk = 0; kk < 4; kk++)
                *(float4*)&bb[kk][0] = *(const float4*)&Vs[k + kk][tx * 4];
            #pragma unroll
            for (int i = 0; i < 4; i++)
                #pragma unroll
                for (int j = 0; j < 4; j++)
                    acc[i][j] += a[i].x * bb[0][j] + a[i].y * bb[1][j] +
                                 a[i].z * bb[2][j] + a[i].w * bb[3][j];
        }
        __syncthreads();
    }

    #pragma unroll
    for (int i = 0; i < 4; i++) {
        size_t row = (size_t)n * LEN + q0 + ty * 4 + i;
        size_t base = row * DIM + h * DK + tx * 4;
        float r0, r1, r2, r3;
        uint32_t h0 = pack_hi(acc[i][0], acc[i][1], &r0, &r1);
        uint32_t h1 = pack_hi(acc[i][2], acc[i][3], &r2, &r3);
        *(uint2*)(Chi + base) = make_uint2(h0, h1);
        *(uint2*)(Clo + base) = make_uint2(pack_bf(r0, r1), pack_bf(r2, r3));
    }
}

// ---------------------------------------------------------------------------
// LayerNorm over last dim (1024); optional bf16 hi/lo split output
// ---------------------------------------------------------------------------
__global__ __launch_bounds__(256) void layernorm_kernel(
    const float* __restrict__ X, const float* __restrict__ gg,
    const float* __restrict__ bb, float* __restrict__ Y,
    __nv_bfloat16* __restrict__ Yhi, __nv_bfloat16* __restrict__ Ylo)
{
    int row = blockIdx.x;
    int tid = threadIdx.x;
    const float4* Xp = (const float4*)(X + (size_t)row * DIM);
    float4 x = Xp[tid];
    __shared__ float red[8];

    float s = x.x + x.y + x.z + x.w;
    #pragma unroll
    for (int o = 16; o; o >>= 1) s += __shfl_xor_sync(0xffffffffu, s, o);
    if ((tid & 31) == 0) red[tid >> 5] = s;
    __syncthreads();
    float mean = (red[0] + red[1] + red[2] + red[3] +
                  red[4] + red[5] + red[6] + red[7]) * (1.0f / DIM);

    float d0 = x.x - mean, d1 = x.y - mean, d2 = x.z - mean, d3 = x.w - mean;
    float s2 = d0 * d0 + d1 * d1 + d2 * d2 + d3 * d3;
    __syncthreads();
    #pragma unroll
    for (int o = 16; o; o >>= 1) s2 += __shfl_xor_sync(0xffffffffu, s2, o);
    if ((tid & 31) == 0) red[tid >> 5] = s2;
    __syncthreads();
    float var = (red[0] + red[1] + red[2] + red[3] +
                 red[4] + red[5] + red[6] + red[7]) * (1.0f / DIM);
    float rs = rsqrtf(var + 1e-5f);

    float4 gv = ((const float4*)gg)[tid];
    float4 bv = ((const float4*)bb)[tid];
    float4 y;
    y.x = d0 * rs * gv.x + bv.x;
    y.y = d1 * rs * gv.y + bv.y;
    y.z = d2 * rs * gv.z + bv.z;
    y.w = d3 * rs * gv.w + bv.w;
    ((float4*)(Y + (size_t)row * DIM))[tid] = y;
    if (Yhi) {
        size_t base = (size_t)row * DIM + tid * 4;
        float r0, r1, r2, r3;
        uint32_t h0 = pack_hi(y.x, y.y, &r0, &r1);
        uint32_t h1 = pack_hi(y.z, y.w, &r2, &r3);
        *(uint2*)(Yhi + base) = make_uint2(h0, h1);
        *(uint2*)(Ylo + base) = make_uint2(pack_bf(r0, r1), pack_bf(r2, r3));
    }
}

// ---------------------------------------------------------------------------
// Launcher
// ---------------------------------------------------------------------------
extern "C" void kernel_launch(void* const* d_in, const int* in_sizes, int n_in,
                              void* d_out, int out_size)
{
    const float*         x    = (const float*)d_in[0];
    const unsigned char* mask = (const unsigned char*)d_in[1];
    const float* WQ = (const float*)d_in[2];
    const float* bQ = (const float*)d_in[3];
    const float* WK = (const float*)d_in[4];
    const float* bK = (const float*)d_in[5];
    const float* WV = (const float*)d_in[6];
    const float* bV = (const float*)d_in[7];
    const float* WO = (const float*)d_in[8];
    const float* bO = (const float*)d_in[9];
    const float* g0 = (const float*)d_in[10];
    const float* b0 = (const float*)d_in[11];
    const float* W1 = (const float*)d_in[12];
    const float* b1 = (const float*)d_in[13];
    const float* W2 = (const float*)d_in[14];
    const float* b2 = (const float*)d_in[15];
    const float* g1 = (const float*)d_in[16];
    const float* b1n = (const float*)d_in[17];
    float* out = (float*)d_out;

    float* base = nullptr;
    cudaGetSymbolAddress((void**)&base, g_scratch);
    float* Q  = base + OFF_Q;
    float* K  = base + OFF_KK;
    float* V  = base + OFF_V;
    float* S  = base + OFF_S;
    __nv_bfloat16* XH  = (__nv_bfloat16*)(base + OFF_XH);
    __nv_bfloat16* XL  = (__nv_bfloat16*)(base + OFF_XL);
    __nv_bfloat16* WQH = (__nv_bfloat16*)(base + OFF_WQH);
    __nv_bfloat16* WQL = (__nv_bfloat16*)(base + OFF_WQL);
    __nv_bfloat16* WKH = (__nv_bfloat16*)(base + OFF_WKH);
    __nv_bfloat16* WKL = (__nv_bfloat16*)(base + OFF_WKL);
    __nv_bfloat16* WVH = (__nv_bfloat16*)(base + OFF_WVH);
    __nv_bfloat16* WVL = (__nv_bfloat16*)(base + OFF_WVL);
    __nv_bfloat16* WOH = (__nv_bfloat16*)(base + OFF_WOH);
    __nv_bfloat16* WOL = (__nv_bfloat16*)(base + OFF_WOL);
    __nv_bfloat16* W1H = (__nv_bfloat16*)(base + OFF_W1H);
    __nv_bfloat16* W1L = (__nv_bfloat16*)(base + OFF_W1L);
    __nv_bfloat16* W2H = (__nv_bfloat16*)(base + OFF_W2H);
    __nv_bfloat16* W2L = (__nv_bfloat16*)(base + OFF_W2L);
    __nv_bfloat16* CH  = (__nv_bfloat16*)(base + OFF_CH);
    __nv_bfloat16* CL  = (__nv_bfloat16*)(base + OFF_CL);
    __nv_bfloat16* HH  = (__nv_bfloat16*)(base + OFF_HH);
    __nv_bfloat16* HL  = (__nv_bfloat16*)(base + OFF_HL);
    __nv_bfloat16* FH  = (__nv_bfloat16*)(base + OFF_FH);
    __nv_bfloat16* FL  = (__nv_bfloat16*)(base + OFF_FL);
    float* T0 = Q;   // mha + x (Q dead after scores)
    float* Hf = K;   // ln0 output (K dead after scores)
    float* T1 = V;   // ffn + h (V dead after ctx)

    cudaFuncSetAttribute(gemm_mma_kernel,
                         cudaFuncAttributeMaxDynamicSharedMemorySize, G_SMEM_DYN);

    dim3 tb(32, 8);

    // Split x; transpose+split weights
    split_kernel<<<(TOK * DIM / 4 + 255) / 256, 256>>>(
        (const float4*)x, (uint2*)XH, (uint2*)XL, TOK * DIM / 4);
    transpose_split_kernel<<<dim3(DIM / 32, DIM / 32), tb>>>(WQ, WQH, WQL, DIM, DIM);
    transpose_split_kernel<<<dim3(DIM / 32, DIM / 32), tb>>>(WK, WKH, WKL, DIM, DIM);
    transpose_split_kernel<<<dim3(DIM / 32, DIM / 32), tb>>>(WV, WVH, WVL, DIM, DIM);
    transpose_split_kernel<<<dim3(DIM / 32, DIM / 32), tb>>>(WO, WOH, WOL, DIM, DIM);
    transpose_split_kernel<<<dim3(FF / 32, DIM / 32), tb>>>(W1, W1H, W1L, DIM, FF);
    transpose_split_kernel<<<dim3(DIM / 32, FF / 32), tb>>>(W2, W2H, W2L, FF, DIM);

    dim3 gD(DIM / 128, TOK / 128);
    dim3 gF(FF / 128, TOK / 128);

    // QKV projections
    gemm_mma_kernel<<<gD, 256, G_SMEM_DYN>>>(XH, XL, WQH, WQL, bQ, nullptr,
                                             Q, nullptr, nullptr, TOK, DIM, DIM, 0);
    gemm_mma_kernel<<<gD, 256, G_SMEM_DYN>>>(XH, XL, WKH, WKL, bK, nullptr,
                                             K, nullptr, nullptr, TOK, DIM, DIM, 0);
    gemm_mma_kernel<<<gD, 256, G_SMEM_DYN>>>(XH, XL, WVH, WVL, bV, nullptr,
                                             V, nullptr, nullptr, TOK, DIM, DIM, 0);

    // Attention
    attn_scores_kernel<<<dim3(LEN / 64, LEN / 64, NB * HEADS), 256>>>(Q, K, mask, S);
    softmax_kernel<<<NB * HEADS * LEN, 128>>>(S);
    attn_ctx_kernel<<<dim3(LEN / 64, NB * HEADS), 256>>>(S, V, CH, CL);

    // O projection + residual(x), layernorm0 (emits split for FFN1)
    gemm_mma_kernel<<<gD, 256, G_SMEM_DYN>>>(CH, CL, WOH, WOL, bO, x,
                                             T0, nullptr, nullptr, TOK, DIM, DIM, 0);
    layernorm_kernel<<<TOK, 256>>>(T0, g0, b0, Hf, HH, HL);

    // FFN
    gemm_mma_kernel<<<gF, 256, G_SMEM_DYN>>>(HH, HL, W1H, W1L, b1, nullptr,
                                             nullptr, FH, FL, TOK, FF, DIM, 1);
    gemm_mma_kernel<<<gD, 256, G_SMEM_DYN>>>(FH, FL, W2H, W2L, b2, Hf,
                                             T1, nullptr, nullptr, TOK, DIM, FF, 0);

    // Final layernorm -> output
    layernorm_kernel<<<TOK, 256>>>(T1, g1, b1n, out, nullptr, nullptr);
}

// round 4
// speedup vs baseline: 1.8952x; 1.5718x over previous
#include <cuda_runtime.h>
#include <cuda_bf16.h>
#include <math.h>
#include <stdint.h>

// Problem constants
#define NB    16
#define LEN   512
#define DIM   1024
#define HEADS 16
#define DK    64
#define FF    4096
#define TOK   (NB * LEN)          // 8192 rows
#define QKVS  3072                // fused QKV row stride

// ---------------------------------------------------------------------------
// Scratch layout (units: floats)
// ---------------------------------------------------------------------------
#define MFe ((size_t)1 << 20)
#define OFF_QKV   (0 * MFe)          // fp32 8192x3072
#define OFF_S     (24 * MFe)         // fp32 256x512x512
#define OFF_T0    (88 * MFe)         // fp32 8192x1024
#define OFF_H     (96 * MFe)         // fp32 8192x1024
#define OFF_T1    (104 * MFe)        // fp32 8192x1024
#define OFF_XH    (112 * MFe)        // bf16 8192x1024
#define OFF_XL    (116 * MFe)
#define OFF_WQKVH (120 * MFe)        // bf16 3072x1024
#define OFF_WQKVL (122 * MFe)
#define OFF_WOH   (124 * MFe)        // bf16 1024x1024
#define OFF_WOL   (125 * MFe)
#define OFF_W1H   (126 * MFe)        // bf16 4096x1024
#define OFF_W1L   (128 * MFe)
#define OFF_W2H   (130 * MFe)        // bf16 1024x4096
#define OFF_W2L   (132 * MFe)
#define OFF_CH    (134 * MFe)        // bf16 8192x1024
#define OFF_CL    (138 * MFe)
#define OFF_HH    (142 * MFe)
#define OFF_HL    (146 * MFe)
#define OFF_FH    (150 * MFe)        // bf16 8192x4096
#define OFF_FL    (166 * MFe)
#define OFF_BQKV  (182 * MFe)        // fp32 3072
#define SCRATCH_FLOATS (183 * MFe)

__device__ float g_scratch[SCRATCH_FLOATS];

// ---------------------------------------------------------------------------
// PTX helpers (sm_80-baseline: cp.async, ldmatrix, mma.sync)
// ---------------------------------------------------------------------------
__device__ __forceinline__ uint32_t s2u(const void* p) {
    uint32_t r;
    asm("{ .reg .u64 t; cvta.to.shared.u64 t, %1; cvt.u32.u64 %0, t; }"
        : "=r"(r) : "l"(p));
    return r;
}

__device__ __forceinline__ void cp16(uint32_t dst, const void* src) {
    asm volatile("cp.async.cg.shared.global [%0], [%1], 16;" :: "r"(dst), "l"(src));
}
__device__ __forceinline__ void cp_commit() {
    asm volatile("cp.async.commit_group;" ::: "memory");
}
template <int N> __device__ __forceinline__ void cp_wait() {
    asm volatile("cp.async.wait_group %0;" :: "n"(N) : "memory");
}

__device__ __forceinline__ void ldsm4(uint32_t* r, uint32_t addr) {
    asm volatile("ldmatrix.sync.aligned.m8n8.x4.shared.b16 {%0,%1,%2,%3}, [%4];"
                 : "=r"(r[0]), "=r"(r[1]), "=r"(r[2]), "=r"(r[3]) : "r"(addr));
}

__device__ __forceinline__ void mma_bf16(float* d, const uint32_t* a,
                                         uint32_t b0, uint32_t b1) {
    asm volatile(
        "mma.sync.aligned.m16n8k16.row.col.f32.bf16.bf16.f32 "
        "{%0,%1,%2,%3}, {%4,%5,%6,%7}, {%8,%9}, {%0,%1,%2,%3};"
        : "+f"(d[0]), "+f"(d[1]), "+f"(d[2]), "+f"(d[3])
        : "r"(a[0]), "r"(a[1]), "r"(a[2]), "r"(a[3]), "r"(b0), "r"(b1));
}

__device__ __forceinline__ float gelu_exact(float v) {
    return 0.5f * v * (1.0f + erff(v * 0.70710678118654752f));
}

__device__ __forceinline__ uint32_t pack_hi(float a, float b, float* ra, float* rb) {
    __nv_bfloat16 ha = __float2bfloat16(a);
    __nv_bfloat16 hb = __float2bfloat16(b);
    *ra = a - __bfloat162float(ha);
    *rb = b - __bfloat162float(hb);
    return (uint32_t)__bfloat16_as_ushort(ha) |
           ((uint32_t)__bfloat16_as_ushort(hb) << 16);
}
__device__ __forceinline__ uint32_t pack_bf(float a, float b) {
    __nv_bfloat16 ha = __float2bfloat16(a);
    __nv_bfloat16 hb = __float2bfloat16(b);
    return (uint32_t)__bfloat16_as_ushort(ha) |
           ((uint32_t)__bfloat16_as_ushort(hb) << 16);
}

// ---------------------------------------------------------------------------
// bf16-split GEMM via mma.sync, 5-stage cp.async pipeline.
//   out = act( Ahi/lo[M,K] @ (Bhi/lo[N,K])^T + bias ) (+ resid)
// CTA tile 128x128, BK=32, 8 warps (64x32 each).
// ---------------------------------------------------------------------------
#define G_STAGES 5
#define SA_STRIDE 40                          // bf16 units per smem row (80 B)
#define G_TILE_B (128 * SA_STRIDE * 2)        // 10240 B per 128x32 tile
#define G_STAGE_B (4 * G_TILE_B)              // Ahi, Alo, Bhi, Blo = 40960 B
#define G_SMEM_DYN (G_STAGES * G_STAGE_B)     // 204800 B

__device__ __forceinline__ void load_tile(uint32_t sbase, const __nv_bfloat16* g,
                                          int K, int k0, int tid) {
    #pragma unroll
    for (int i = 0; i < 2; i++) {
        int c = tid + i * 256;                // 0..511 : 128 rows x 4 chunks
        int row = c >> 2;
        int col = c & 3;
        cp16(sbase + (uint32_t)(row * (SA_STRIDE * 2) + col * 16),
             g + (size_t)row * K + k0 + col * 8);
    }
}

extern __shared__ char g_dsm[];

__global__ void __launch_bounds__(256, 1) gemm_mma_kernel(
    const __nv_bfloat16* __restrict__ Ahi, const __nv_bfloat16* __restrict__ Alo,
    const __nv_bfloat16* __restrict__ Bhi, const __nv_bfloat16* __restrict__ Blo,
    const float* __restrict__ bias, const float* __restrict__ resid,
    float* __restrict__ outF,
    __nv_bfloat16* __restrict__ outHi, __nv_bfloat16* __restrict__ outLo,
    int M, int N, int K, int gelu)
{
    const int tid = threadIdx.x;
    const int wid = tid >> 5;
    const int lane = tid & 31;
    const int wr = wid >> 2;       // warp row 0-1 (64 rows each)
    const int wc = wid & 3;        // warp col 0-3 (32 cols each)
    const int bm = blockIdx.y * 128;
    const int bn = blockIdx.x * 128;

    uint32_t db = s2u(g_dsm);

    const __nv_bfloat16* Ah = Ahi + (size_t)bm * K;
    const __nv_bfloat16* Al = Alo + (size_t)bm * K;
    const __nv_bfloat16* Bh = Bhi + (size_t)bn * K;
    const __nv_bfloat16* Bl = Blo + (size_t)bn * K;

    float acc[4][4][4] = {};

    const int nk = K / 32;

    // Prologue: issue stages 0..G_STAGES-2
    #pragma unroll
    for (int s = 0; s < G_STAGES - 1; s++) {
        if (s < nk) {
            uint32_t sb = db + (uint32_t)s * G_STAGE_B;
            load_tile(sb + 0 * G_TILE_B, Ah, K, s * 32, tid);
            load_tile(sb + 1 * G_TILE_B, Al, K, s * 32, tid);
            load_tile(sb + 2 * G_TILE_B, Bh, K, s * 32, tid);
            load_tile(sb + 3 * G_TILE_B, Bl, K, s * 32, tid);
        }
        cp_commit();
    }

    // ldmatrix lane addressing
    const int a_row = (lane & 15);
    const int a_ko  = (lane >> 4) * 8;
    const int b_row = ((lane >> 4) * 8) + (lane & 7);
    const int b_ko  = ((lane >> 3) & 1) * 8;

    for (int kt = 0; kt < nk; kt++) {
        cp_wait<G_STAGES - 2>();               // stage kt ready
        __syncthreads();                       // buffer (kt-1)%S free for reuse

        // Prefetch stage kt+G_STAGES-1 BEFORE computing kt
        int pf = kt + G_STAGES - 1;
        if (pf < nk) {
            uint32_t nb = db + (uint32_t)(pf % G_STAGES) * G_STAGE_B;
            int k0 = pf * 32;
            load_tile(nb + 0 * G_TILE_B, Ah, K, k0, tid);
            load_tile(nb + 1 * G_TILE_B, Al, K, k0, tid);
            load_tile(nb + 2 * G_TILE_B, Bh, K, k0, tid);
            load_tile(nb + 3 * G_TILE_B, Bl, K, k0, tid);
        }
        cp_commit();

        uint32_t sb = db + (uint32_t)(kt % G_STAGES) * G_STAGE_B;
        uint32_t sAh = sb + 0 * G_TILE_B;
        uint32_t sAl = sb + 1 * G_TILE_B;
        uint32_t sBh = sb + 2 * G_TILE_B;
        uint32_t sBl = sb + 3 * G_TILE_B;

        #pragma unroll
        for (int k16 = 0; k16 < 2; k16++) {
            uint32_t ah[4][4], al[4][4], bh[2][4], bl[2][4];
            #pragma unroll
            for (int mi = 0; mi < 4; mi++) {
                uint32_t off = (uint32_t)((wr * 64 + mi * 16 + a_row) * (SA_STRIDE * 2)
                                          + (k16 * 16 + a_ko) * 2);
                ldsm4(ah[mi], sAh + off);
                ldsm4(al[mi], sAl + off);
            }
            #pragma unroll
            for (int nf = 0; nf < 2; nf++) {
                uint32_t off = (uint32_t)((wc * 32 + nf * 16 + b_row) * (SA_STRIDE * 2)
                                          + (k16 * 16 + b_ko) * 2);
                ldsm4(bh[nf], sBh + off);
                ldsm4(bl[nf], sBl + off);
            }
            #pragma unroll
            for (int mi = 0; mi < 4; mi++) {
                #pragma unroll
                for (int ni = 0; ni < 4; ni++) {
                    int nf = ni >> 1, o = (ni & 1) * 2;
                    mma_bf16(acc[mi][ni], ah[mi], bh[nf][o], bh[nf][o + 1]);
                    mma_bf16(acc[mi][ni], ah[mi], bl[nf][o], bl[nf][o + 1]);
                    mma_bf16(acc[mi][ni], al[mi], bh[nf][o], bh[nf][o + 1]);
                }
            }
        }
    }

    // Epilogue
    const int tq = lane >> 2;
    const int tc = (lane & 3) * 2;
    #pragma unroll
    for (int mi = 0; mi < 4; mi++) {
        #pragma unroll
        for (int ni = 0; ni < 4; ni++) {
            int col = bn + wc * 32 + ni * 8 + tc;
            float bx = bias[col], by = bias[col + 1];
            #pragma unroll
            for (int half = 0; half < 2; half++) {
                int row = bm + wr * 64 + mi * 16 + tq + half * 8;
                float v0 = acc[mi][ni][half * 2 + 0] + bx;
                float v1 = acc[mi][ni][half * 2 + 1] + by;
                if (gelu) { v0 = gelu_exact(v0); v1 = gelu_exact(v1); }
                if (resid) {
                    float2 rv = *(const float2*)(resid + (size_t)row * N + col);
                    v0 += rv.x; v1 += rv.y;
                }
                if (outF)
                    *(float2*)(outF + (size_t)row * N + col) = make_float2(v0, v1);
                if (outHi) {
                    float ra, rb;
                    uint32_t hv = pack_hi(v0, v1, &ra, &rb);
                    *(uint32_t*)(outHi + (size_t)row * N + col) = hv;
                    *(uint32_t*)(outLo + (size_t)row * N + col) = pack_bf(ra, rb);
                }
            }
        }
    }
}

// ---------------------------------------------------------------------------
// Elementwise fp32 -> bf16 hi/lo split
// ---------------------------------------------------------------------------
__global__ __launch_bounds__(256) void split_kernel(
    const float4* __restrict__ X, uint2* __restrict__ Hh, uint2* __restrict__ Ll, int n4)
{
    int i = blockIdx.x * 256 + threadIdx.x;
    if (i >= n4) return;
    float4 v = X[i];
    float r0, r1, r2, r3;
    uint32_t h0 = pack_hi(v.x, v.y, &r0, &r1);
    uint32_t h1 = pack_hi(v.z, v.w, &r2, &r3);
    Hh[i] = make_uint2(h0, h1);
    Ll[i] = make_uint2(pack_bf(r0, r1), pack_bf(r2, r3));
}

// ---------------------------------------------------------------------------
// Transposed split: W[Kr,Nc] fp32 -> TH/TL [Nc,Kr] bf16 (K-major for mma B)
// ---------------------------------------------------------------------------
__global__ __launch_bounds__(256) void transpose_split_kernel(
    const float* __restrict__ W, __nv_bfloat16* __restrict__ TH,
    __nv_bfloat16* __restrict__ TL, int Kr, int Nc)
{
    __shared__ float t[32][33];
    int n0 = blockIdx.x * 32, k0 = blockIdx.y * 32;
    int tx = threadIdx.x, ty = threadIdx.y;     // 32 x 8
    #pragma unroll
    for (int i = 0; i < 4; i++)
        t[ty + i * 8][tx] = W[(size_t)(k0 + ty + i * 8) * Nc + n0 + tx];
    __syncthreads();
    #pragma unroll
    for (int i = 0; i < 4; i++) {
        int n = n0 + ty + i * 8;
        int k = k0 + tx;
        float v = t[tx][ty + i * 8];
        __nv_bfloat16 h = __float2bfloat16(v);
        TH[(size_t)n * Kr + k] = h;
        TL[(size_t)n * Kr + k] = __float2bfloat16(v - __bfloat162float(h));
    }
}

// ---------------------------------------------------------------------------
// Concat 3 bias vectors of 1024 into one 3072 buffer
// ---------------------------------------------------------------------------
__global__ __launch_bounds__(256) void concat_bias_kernel(
    const float* __restrict__ a, const float* __restrict__ b,
    const float* __restrict__ c, float* __restrict__ o)
{
    int i = blockIdx.x * 256 + threadIdx.x;
    if (i < 1024) o[i] = a[i];
    else if (i < 2048) o[i] = b[i - 1024];
    else if (i < 3072) o[i] = c[i - 2048];
}

// ---------------------------------------------------------------------------
// Attention scores: S[b,q,k] = (Q.K)/8, mask -> -inf. Q/K in fused QKV buffer.
// ---------------------------------------------------------------------------
__global__ __launch_bounds__(256) void attn_scores_kernel(
    const float* __restrict__ QKV, const unsigned char* __restrict__ mask,
    float* __restrict__ S)
{
    int b = blockIdx.z;
    int n = b >> 4;
    int h = b & 15;
    int q0 = blockIdx.y * 64;
    int k0 = blockIdx.x * 64;
    const float* Qp = QKV + (size_t)n * LEN * QKVS + h * DK;
    const float* Kp = QKV + (size_t)n * LEN * QKVS + DIM + h * DK;
    __shared__ float Qs[64][68];
    __shared__ float Ks[64][68];
    int tid = threadIdx.x;

    #pragma unroll
    for (int i = 0; i < 4; i++) {
        int id = tid + i * 256;
        int r = id >> 4;
        int c = (id & 15) << 2;
        *(float4*)&Qs[r][c] = *(const float4*)(Qp + (size_t)(q0 + r) * QKVS + c);
        *(float4*)&Ks[r][c] = *(const float4*)(Kp + (size_t)(k0 + r) * QKVS + c);
    }
    __syncthreads();

    int tx = tid & 15;
    int ty = tid >> 4;
    float acc[4][4] = {};
    #pragma unroll
    for (int d = 0; d < DK; d += 4) {
        float4 a[4], bb[4];
        #pragma unroll
        for (int i = 0; i < 4; i++) a[i]  = *(const float4*)&Qs[ty * 4 + i][d];
        #pragma unroll
        for (int j = 0; j < 4; j++) bb[j] = *(const float4*)&Ks[tx * 4 + j][d];
        #pragma unroll
        for (int i = 0; i < 4; i++)
            #pragma unroll
            for (int j = 0; j < 4; j++)
                acc[i][j] += a[i].x * bb[j].x + a[i].y * bb[j].y +
                             a[i].z * bb[j].z + a[i].w * bb[j].w;
    }

    const unsigned char* mp = mask + (size_t)n * LEN * LEN;
    float* Sp = S + (size_t)b * LEN * LEN;
    #pragma unroll
    for (int i = 0; i < 4; i++) {
        int q = q0 + ty * 4 + i;
        #pragma unroll
        for (int j = 0; j < 4; j++) {
            int k = k0 + tx * 4 + j;
            float v = acc[i][j] * 0.125f;
            if (mp[(size_t)q * LEN + k]) v = -INFINITY;
            Sp[(size_t)q * LEN + k] = v;
        }
    }
}

// ---------------------------------------------------------------------------
// Row softmax over L=512 (in place); fully-masked rows -> 0
// ---------------------------------------------------------------------------
__global__ __launch_bounds__(128) void softmax_kernel(float* __restrict__ S)
{
    size_t row = blockIdx.x;
    float4* p = (float4*)(S + row * LEN);
    int tid = threadIdx.x;
    float4 v = p[tid];
    __shared__ float ra[4], rb[4];

    float mx = fmaxf(fmaxf(v.x, v.y), fmaxf(v.z, v.w));
    #pragma unroll
    for (int o = 16; o; o >>= 1) mx = fmaxf(mx, __shfl_xor_sync(0xffffffffu, mx, o));
    if ((tid & 31) == 0) ra[tid >> 5] = mx;
    __syncthreads();
    mx = fmaxf(fmaxf(ra[0], ra[1]), fmaxf(ra[2], ra[3]));

    float4 e;
    if (mx == -INFINITY) {
        e.x = e.y = e.z = e.w = 0.0f;
    } else {
        e.x = expf(v.x - mx); e.y = expf(v.y - mx);
        e.z = expf(v.z - mx); e.w = expf(v.w - mx);
    }
    float s = e.x + e.y + e.z + e.w;
    #pragma unroll
    for (int o = 16; o; o >>= 1) s += __shfl_xor_sync(0xffffffffu, s, o);
    if ((tid & 31) == 0) rb[tid >> 5] = s;
    __syncthreads();
    s = rb[0] + rb[1] + rb[2] + rb[3];

    float inv = (s > 0.0f) ? 1.0f / s : 0.0f;
    e.x *= inv; e.y *= inv; e.z *= inv; e.w *= inv;
    p[tid] = e;
}

// ---------------------------------------------------------------------------
// Context: ctx[b,q,d] = sum_k attn * V; writes bf16 hi/lo split directly.
// ---------------------------------------------------------------------------
__global__ __launch_bounds__(256) void attn_ctx_kernel(
    const float* __restrict__ S, const float* __restrict__ QKV,
    __nv_bfloat16* __restrict__ Chi, __nv_bfloat16* __restrict__ Clo)
{
    int b = blockIdx.y;
    int n = b >> 4;
    int h = b & 15;
    int q0 = blockIdx.x * 64;
    const float* Sp = S + (size_t)b * LEN * LEN;
    const float* Vp = QKV + (size_t)n * LEN * QKVS + 2 * DIM + h * DK;
    __shared__ float As[64][68];
    __shared__ float Vs[64][68];
    int tid = threadIdx.x;
    int tx = tid & 15;
    int ty = tid >> 4;
    float acc[4][4] = {};

    for (int kc = 0; kc < LEN; kc += 64) {
        #pragma unroll
        for (int i = 0; i < 4; i++) {
            int id = tid + i * 256;
            int r = id >> 4;
            int c = (id & 15) << 2;
            *(float4*)&As[r][c] = *(const float4*)(Sp + (size_t)(q0 + r) * LEN + kc + c);
            *(float4*)&Vs[r][c] = *(const float4*)(Vp + (size_t)(kc + r) * QKVS + c);
        }
        __syncthreads();
        #pragma unroll
        for (int k = 0; k < 64; k += 4) {
            float4 a[4];
            float bb[4][4];
            #pragma unroll
            for (int i = 0; i < 4; i++) a[i] = *(const float4*)&As[ty * 4 + i][k];
            #pragma unroll
            for (int kk = 0; kk < 4; kk++)
                *(float4*)&bb[kk][0] = *(const float4*)&Vs[k + kk][tx * 4];
            #pragma unroll
            for (int i = 0; i < 4; i++)
                #pragma unroll
                for (int j = 0; j < 4; j++)
                    acc[i][j] += a[i].x * bb[0][j] + a[i].y * bb[1][j] +
                                 a[i].z * bb[2][j] + a[i].w * bb[3][j];
        }
        __syncthreads();
    }

    #pragma unroll
    for (int i = 0; i < 4; i++) {
        size_t row = (size_t)n * LEN + q0 + ty * 4 + i;
        size_t base = row * DIM + h * DK + tx * 4;
        float r0, r1, r2, r3;
        uint32_t h0 = pack_hi(acc[i][0], acc[i][1], &r0, &r1);
        uint32_t h1 = pack_hi(acc[i][2], acc[i][3], &r2, &r3);
        *(uint2*)(Chi + base) = make_uint2(h0, h1);
        *(uint2*)(Clo + base) = make_uint2(pack_bf(r0, r1), pack_bf(r2, r3));
    }
}

// ---------------------------------------------------------------------------
// LayerNorm over last dim (1024); optional bf16 hi/lo split output
// ---------------------------------------------------------------------------
__global__ __launch_bounds__(256) void layernorm_kernel(
    const float* __restrict__ X, const float* __restrict__ gg,
    const float* __restrict__ bb, float* __restrict__ Y,
    __nv_bfloat16* __restrict__ Yhi, __nv_bfloat16* __restrict__ Ylo)
{
    int row = blockIdx.x;
    int tid = threadIdx.x;
    const float4* Xp = (const float4*)(X + (size_t)row * DIM);
    float4 x = Xp[tid];
    __shared__ float red[8];

    float s = x.x + x.y + x.z + x.w;
    #pragma unroll
    for (int o = 16; o; o >>= 1) s += __shfl_xor_sync(0xffffffffu, s, o);
    if ((tid & 31) == 0) red[tid >> 5] = s;
    __syncthreads();
    float mean = (red[0] + red[1] + red[2] + red[3] +
                  red[4] + red[5] + red[6] + red[7]) * (1.0f / DIM);

    float d0 = x.x - mean, d1 = x.y - mean, d2 = x.z - mean, d3 = x.w - mean;
    float s2 = d0 * d0 + d1 * d1 + d2 * d2 + d3 * d3;
    __syncthreads();
    #pragma unroll
    for (int o = 16; o; o >>= 1) s2 += __shfl_xor_sync(0xffffffffu, s2, o);
    if ((tid & 31) == 0) red[tid >> 5] = s2;
    __syncthreads();
    float var = (red[0] + red[1] + red[2] + red[3] +
                 red[4] + red[5] + red[6] + red[7]) * (1.0f / DIM);
    float rs = rsqrtf(var + 1e-5f);

    float4 gv = ((const float4*)gg)[tid];
    float4 bv = ((const float4*)bb)[tid];
    float4 y;
    y.x = d0 * rs * gv.x + bv.x;
    y.y = d1 * rs * gv.y + bv.y;
    y.z = d2 * rs * gv.z + bv.z;
    y.w = d3 * rs * gv.w + bv.w;
    ((float4*)(Y + (size_t)row * DIM))[tid] = y;
    if (Yhi) {
        size_t base = (size_t)row * DIM + tid * 4;
        float r0, r1, r2, r3;
        uint32_t h0 = pack_hi(y.x, y.y, &r0, &r1);
        uint32_t h1 = pack_hi(y.z, y.w, &r2, &r3);
        *(uint2*)(Yhi + base) = make_uint2(h0, h1);
        *(uint2*)(Ylo + base) = make_uint2(pack_bf(r0, r1), pack_bf(r2, r3));
    }
}

// ---------------------------------------------------------------------------
// Launcher
// ---------------------------------------------------------------------------
extern "C" void kernel_launch(void* const* d_in, const int* in_sizes, int n_in,
                              void* d_out, int out_size)
{
    const float*         x    = (const float*)d_in[0];
    const unsigned char* mask = (const unsigned char*)d_in[1];
    const float* WQ = (const float*)d_in[2];
    const float* bQ = (const float*)d_in[3];
    const float* WK = (const float*)d_in[4];
    const float* bK = (const float*)d_in[5];
    const float* WV = (const float*)d_in[6];
    const float* bV = (const float*)d_in[7];
    const float* WO = (const float*)d_in[8];
    const float* bO = (const float*)d_in[9];
    const float* g0 = (const float*)d_in[10];
    const float* b0 = (const float*)d_in[11];
    const float* W1 = (const float*)d_in[12];
    const float* b1 = (const float*)d_in[13];
    const float* W2 = (const float*)d_in[14];
    const float* b2 = (const float*)d_in[15];
    const float* g1 = (const float*)d_in[16];
    const float* b1n = (const float*)d_in[17];
    float* out = (float*)d_out;

    float* base = nullptr;
    cudaGetSymbolAddress((void**)&base, g_scratch);
    float* QKV = base + OFF_QKV;
    float* S   = base + OFF_S;
    float* T0  = base + OFF_T0;
    float* Hf  = base + OFF_H;
    float* T1  = base + OFF_T1;
    float* bqkv = base + OFF_BQKV;
    __nv_bfloat16* XH  = (__nv_bfloat16*)(base + OFF_XH);
    __nv_bfloat16* XL  = (__nv_bfloat16*)(base + OFF_XL);
    __nv_bfloat16* WQKVH = (__nv_bfloat16*)(base + OFF_WQKVH);
    __nv_bfloat16* WQKVL = (__nv_bfloat16*)(base + OFF_WQKVL);
    __nv_bfloat16* WOH = (__nv_bfloat16*)(base + OFF_WOH);
    __nv_bfloat16* WOL = (__nv_bfloat16*)(base + OFF_WOL);
    __nv_bfloat16* W1H = (__nv_bfloat16*)(base + OFF_W1H);
    __nv_bfloat16* W1L = (__nv_bfloat16*)(base + OFF_W1L);
    __nv_bfloat16* W2H = (__nv_bfloat16*)(base + OFF_W2H);
    __nv_bfloat16* W2L = (__nv_bfloat16*)(base + OFF_W2L);
    __nv_bfloat16* CH  = (__nv_bfloat16*)(base + OFF_CH);
    __nv_bfloat16* CL  = (__nv_bfloat16*)(base + OFF_CL);
    __nv_bfloat16* HH  = (__nv_bfloat16*)(base + OFF_HH);
    __nv_bfloat16* HL  = (__nv_bfloat16*)(base + OFF_HL);
    __nv_bfloat16* FH  = (__nv_bfloat16*)(base + OFF_FH);
    __nv_bfloat16* FL  = (__nv_bfloat16*)(base + OFF_FL);

    cudaFuncSetAttribute(gemm_mma_kernel,
                         cudaFuncAttributeMaxDynamicSharedMemorySize, G_SMEM_DYN);

    dim3 tb(32, 8);

    // Launches 0-4: split x, transpose QKV weights, concat QKV bias
    split_kernel<<<(TOK * DIM / 4 + 255) / 256, 256>>>(
        (const float4*)x, (uint2*)XH, (uint2*)XL, TOK * DIM / 4);
    transpose_split_kernel<<<dim3(DIM / 32, DIM / 32), tb>>>(
        WQ, WQKVH + (size_t)0 * DIM * DIM, WQKVL + (size_t)0 * DIM * DIM, DIM, DIM);
    transpose_split_kernel<<<dim3(DIM / 32, DIM / 32), tb>>>(
        WK, WQKVH + (size_t)1 * DIM * DIM, WQKVL + (size_t)1 * DIM * DIM, DIM, DIM);
    transpose_split_kernel<<<dim3(DIM / 32, DIM / 32), tb>>>(
        WV, WQKVH + (size_t)2 * DIM * DIM, WQKVL + (size_t)2 * DIM * DIM, DIM, DIM);
    concat_bias_kernel<<<12, 256>>>(bQ, bK, bV, bqkv);

    // Launch 5 (ncu-profiled): fused QKV GEMM, N=3072
    gemm_mma_kernel<<<dim3(QKVS / 128, TOK / 128), 256, G_SMEM_DYN>>>(
        XH, XL, WQKVH, WQKVL, bqkv, nullptr,
        QKV, nullptr, nullptr, TOK, QKVS, DIM, 0);

    // Remaining weight transposes (independent of QKV GEMM)
    transpose_split_kernel<<<dim3(DIM / 32, DIM / 32), tb>>>(WO, WOH, WOL, DIM, DIM);
    transpose_split_kernel<<<dim3(FF / 32, DIM / 32), tb>>>(W1, W1H, W1L, DIM, FF);
    transpose_split_kernel<<<dim3(DIM / 32, FF / 32), tb>>>(W2, W2H, W2L, FF, DIM);

    // Attention
    attn_scores_kernel<<<dim3(LEN / 64, LEN / 64, NB * HEADS), 256>>>(QKV, mask, S);
    softmax_kernel<<<NB * HEADS * LEN, 128>>>(S);
    attn_ctx_kernel<<<dim3(LEN / 64, NB * HEADS), 256>>>(S, QKV, CH, CL);

    dim3 gD(DIM / 128, TOK / 128);
    dim3 gF(FF / 128, TOK / 128);

    // O projection + residual(x), layernorm0 (emits split for FFN1)
    gemm_mma_kernel<<<gD, 256, G_SMEM_DYN>>>(CH, CL, WOH, WOL, bO, x,
                                             T0, nullptr, nullptr, TOK, DIM, DIM, 0);
    layernorm_kernel<<<TOK, 256>>>(T0, g0, b0, Hf, HH, HL);

    // FFN
    gemm_mma_kernel<<<gF, 256, G_SMEM_DYN>>>(HH, HL, W1H, W1L, b1, nullptr,
                                             nullptr, FH, FL, TOK, FF, DIM, 1);
    gemm_mma_kernel<<<gD, 256, G_SMEM_DYN>>>(FH, FL, W2H, W2L, b2, Hf,
                                             T1, nullptr, nullptr, TOK, DIM, FF, 0);

    // Final layernorm -> output
    layernorm_kernel<<<TOK, 256>>>(T1, g1, b1n, out, nullptr, nullptr);
}

// round 5
// speedup vs baseline: 2.3239x; 1.2262x over previous
#include <cuda_runtime.h>
#include <cuda_bf16.h>
#include <math.h>
#include <stdint.h>

// Problem constants
#define NB    16
#define LEN   512
#define DIM   1024
#define HEADS 16
#define DK    64
#define FF    4096
#define TOK   (NB * LEN)          // 8192 rows
#define QKVS  3072                // fused QKV row stride

// ---------------------------------------------------------------------------
// Scratch layout (units: floats)
// ---------------------------------------------------------------------------
#define MFe ((size_t)1 << 20)
#define OFF_S     (0 * MFe)           // fp32 256x512x512 (scores pre-softmax)
#define OFF_SH    (64 * MFe)          // bf16 probs hi
#define OFF_SL    (96 * MFe)          // bf16 probs lo
#define OFF_QKVH  (128 * MFe)         // bf16 8192x3072
#define OFF_QKVL  (140 * MFe)
#define OFF_T0    (152 * MFe)         // fp32 8192x1024
#define OFF_H     (160 * MFe)
#define OFF_T1    (168 * MFe)
#define OFF_XH    (176 * MFe)         // bf16 8192x1024
#define OFF_XL    (180 * MFe)
#define OFF_WQKVH (184 * MFe)         // bf16 3072x1024
#define OFF_WQKVL (186 * MFe)
#define OFF_WOH   (188 * MFe)         // bf16 1024x1024 (0.5 MFe)
#define OFF_WOL   (OFF_WOH + MFe / 2)
#define OFF_W1H   (189 * MFe)         // bf16 4096x1024
#define OFF_W1L   (191 * MFe)
#define OFF_W2H   (193 * MFe)         // bf16 1024x4096
#define OFF_W2L   (195 * MFe)
#define OFF_CH    (197 * MFe)         // bf16 8192x1024
#define OFF_CL    (201 * MFe)
#define OFF_HH    (205 * MFe)
#define OFF_HL    (209 * MFe)
#define OFF_FH    (213 * MFe)         // bf16 8192x4096
#define OFF_FL    (229 * MFe)
#define OFF_BQKV  (245 * MFe)         // fp32 3072
#define SCRATCH_FLOATS (246 * MFe)

__device__ float g_scratch[SCRATCH_FLOATS];

// ---------------------------------------------------------------------------
// PTX helpers (sm_80-baseline: cp.async, ldmatrix, mma.sync)
// ---------------------------------------------------------------------------
__device__ __forceinline__ uint32_t s2u(const void* p) {
    uint32_t r;
    asm("{ .reg .u64 t; cvta.to.shared.u64 t, %1; cvt.u32.u64 %0, t; }"
        : "=r"(r) : "l"(p));
    return r;
}

__device__ __forceinline__ void cp16(uint32_t dst, const void* src) {
    asm volatile("cp.async.cg.shared.global [%0], [%1], 16;" :: "r"(dst), "l"(src));
}
__device__ __forceinline__ void cp_commit() {
    asm volatile("cp.async.commit_group;" ::: "memory");
}
template <int N> __device__ __forceinline__ void cp_wait() {
    asm volatile("cp.async.wait_group %0;" :: "n"(N) : "memory");
}

__device__ __forceinline__ void ldsm4(uint32_t* r, uint32_t addr) {
    asm volatile("ldmatrix.sync.aligned.m8n8.x4.shared.b16 {%0,%1,%2,%3}, [%4];"
                 : "=r"(r[0]), "=r"(r[1]), "=r"(r[2]), "=r"(r[3]) : "r"(addr));
}
__device__ __forceinline__ void ldsm4t(uint32_t* r, uint32_t addr) {
    asm volatile("ldmatrix.sync.aligned.m8n8.x4.trans.shared.b16 {%0,%1,%2,%3}, [%4];"
                 : "=r"(r[0]), "=r"(r[1]), "=r"(r[2]), "=r"(r[3]) : "r"(addr));
}

__device__ __forceinline__ void mma_bf16(float* d, const uint32_t* a,
                                         uint32_t b0, uint32_t b1) {
    asm volatile(
        "mma.sync.aligned.m16n8k16.row.col.f32.bf16.bf16.f32 "
        "{%0,%1,%2,%3}, {%4,%5,%6,%7}, {%8,%9}, {%0,%1,%2,%3};"
        : "+f"(d[0]), "+f"(d[1]), "+f"(d[2]), "+f"(d[3])
        : "r"(a[0]), "r"(a[1]), "r"(a[2]), "r"(a[3]), "r"(b0), "r"(b1));
}

__device__ __forceinline__ float gelu_exact(float v) {
    return 0.5f * v * (1.0f + erff(v * 0.70710678118654752f));
}

__device__ __forceinline__ uint32_t pack_hi(float a, float b, float* ra, float* rb) {
    __nv_bfloat16 ha = __float2bfloat16(a);
    __nv_bfloat16 hb = __float2bfloat16(b);
    *ra = a - __bfloat162float(ha);
    *rb = b - __bfloat162float(hb);
    return (uint32_t)__bfloat16_as_ushort(ha) |
           ((uint32_t)__bfloat16_as_ushort(hb) << 16);
}
__device__ __forceinline__ uint32_t pack_bf(float a, float b) {
    __nv_bfloat16 ha = __float2bfloat16(a);
    __nv_bfloat16 hb = __float2bfloat16(b);
    return (uint32_t)__bfloat16_as_ushort(ha) |
           ((uint32_t)__bfloat16_as_ushort(hb) << 16);
}

// ---------------------------------------------------------------------------
// bf16-split GEMM via mma.sync, 5-stage cp.async pipeline, 512 threads.
// CTA tile 128x128, BK=32, 16 warps (32x32 each).
// ---------------------------------------------------------------------------
#define G_STAGES 5
#define SA_STRIDE 40                          // bf16 units per smem row (80 B)
#define G_TILE_B (128 * SA_STRIDE * 2)        // 10240 B per 128x32 tile
#define G_STAGE_B (4 * G_TILE_B)              // 40960 B
#define G_SMEM_DYN (G_STAGES * G_STAGE_B)     // 204800 B

__device__ __forceinline__ void load_tile512(uint32_t sbase, const __nv_bfloat16* g,
                                             int K, int k0, int tid) {
    int row = tid >> 2;
    int col = tid & 3;
    cp16(sbase + (uint32_t)(row * (SA_STRIDE * 2) + col * 16),
         g + (size_t)row * K + k0 + col * 8);
}

extern __shared__ char g_dsm[];

__global__ void __launch_bounds__(512, 1) gemm_mma_kernel(
    const __nv_bfloat16* __restrict__ Ahi, const __nv_bfloat16* __restrict__ Alo,
    const __nv_bfloat16* __restrict__ Bhi, const __nv_bfloat16* __restrict__ Blo,
    const float* __restrict__ bias, const float* __restrict__ resid,
    float* __restrict__ outF,
    __nv_bfloat16* __restrict__ outHi, __nv_bfloat16* __restrict__ outLo,
    int M, int N, int K, int gelu)
{
    const int tid = threadIdx.x;
    const int wid = tid >> 5;
    const int lane = tid & 31;
    const int wr = wid >> 2;       // warp row 0-3 (32 rows each)
    const int wc = wid & 3;        // warp col 0-3 (32 cols each)
    const int bm = blockIdx.y * 128;
    const int bn = blockIdx.x * 128;

    uint32_t db = s2u(g_dsm);

    const __nv_bfloat16* Ah = Ahi + (size_t)bm * K;
    const __nv_bfloat16* Al = Alo + (size_t)bm * K;
    const __nv_bfloat16* Bh = Bhi + (size_t)bn * K;
    const __nv_bfloat16* Bl = Blo + (size_t)bn * K;

    float acc[2][4][4] = {};

    const int nk = K / 32;

    #pragma unroll
    for (int s = 0; s < G_STAGES - 1; s++) {
        if (s < nk) {
            uint32_t sb = db + (uint32_t)s * G_STAGE_B;
            load_tile512(sb + 0 * G_TILE_B, Ah, K, s * 32, tid);
            load_tile512(sb + 1 * G_TILE_B, Al, K, s * 32, tid);
            load_tile512(sb + 2 * G_TILE_B, Bh, K, s * 32, tid);
            load_tile512(sb + 3 * G_TILE_B, Bl, K, s * 32, tid);
        }
        cp_commit();
    }

    const int a_row = (lane & 15);
    const int a_ko  = (lane >> 4) * 8;
    const int b_row = ((lane >> 4) * 8) + (lane & 7);
    const int b_ko  = ((lane >> 3) & 1) * 8;

    for (int kt = 0; kt < nk; kt++) {
        cp_wait<G_STAGES - 2>();
        __syncthreads();

        int pf = kt + G_STAGES - 1;
        if (pf < nk) {
            uint32_t nb = db + (uint32_t)(pf % G_STAGES) * G_STAGE_B;
            int k0 = pf * 32;
            load_tile512(nb + 0 * G_TILE_B, Ah, K, k0, tid);
            load_tile512(nb + 1 * G_TILE_B, Al, K, k0, tid);
            load_tile512(nb + 2 * G_TILE_B, Bh, K, k0, tid);
            load_tile512(nb + 3 * G_TILE_B, Bl, K, k0, tid);
        }
        cp_commit();

        uint32_t sb = db + (uint32_t)(kt % G_STAGES) * G_STAGE_B;
        uint32_t sAh = sb + 0 * G_TILE_B;
        uint32_t sAl = sb + 1 * G_TILE_B;
        uint32_t sBh = sb + 2 * G_TILE_B;
        uint32_t sBl = sb + 3 * G_TILE_B;

        #pragma unroll
        for (int k16 = 0; k16 < 2; k16++) {
            uint32_t ah[2][4], al[2][4], bh[2][4], bl[2][4];
            #pragma unroll
            for (int mi = 0; mi < 2; mi++) {
                uint32_t off = (uint32_t)((wr * 32 + mi * 16 + a_row) * (SA_STRIDE * 2)
                                          + (k16 * 16 + a_ko) * 2);
                ldsm4(ah[mi], sAh + off);
                ldsm4(al[mi], sAl + off);
            }
            #pragma unroll
            for (int nf = 0; nf < 2; nf++) {
                uint32_t off = (uint32_t)((wc * 32 + nf * 16 + b_row) * (SA_STRIDE * 2)
                                          + (k16 * 16 + b_ko) * 2);
                ldsm4(bh[nf], sBh + off);
                ldsm4(bl[nf], sBl + off);
            }
            #pragma unroll
            for (int mi = 0; mi < 2; mi++) {
                #pragma unroll
                for (int ni = 0; ni < 4; ni++) {
                    int nf = ni >> 1, o = (ni & 1) * 2;
                    mma_bf16(acc[mi][ni], ah[mi], bh[nf][o], bh[nf][o + 1]);
                    mma_bf16(acc[mi][ni], ah[mi], bl[nf][o], bl[nf][o + 1]);
                    mma_bf16(acc[mi][ni], al[mi], bh[nf][o], bh[nf][o + 1]);
                }
            }
        }
    }

    const int tq = lane >> 2;
    const int tc = (lane & 3) * 2;
    #pragma unroll
    for (int mi = 0; mi < 2; mi++) {
        #pragma unroll
        for (int ni = 0; ni < 4; ni++) {
            int col = bn + wc * 32 + ni * 8 + tc;
            float bx = bias[col], by = bias[col + 1];
            #pragma unroll
            for (int half = 0; half < 2; half++) {
                int row = bm + wr * 32 + mi * 16 + tq + half * 8;
                float v0 = acc[mi][ni][half * 2 + 0] + bx;
                float v1 = acc[mi][ni][half * 2 + 1] + by;
                if (gelu) { v0 = gelu_exact(v0); v1 = gelu_exact(v1); }
                if (resid) {
                    float2 rv = *(const float2*)(resid + (size_t)row * N + col);
                    v0 += rv.x; v1 += rv.y;
                }
                if (outF)
                    *(float2*)(outF + (size_t)row * N + col) = make_float2(v0, v1);
                if (outHi) {
                    float ra, rb;
                    uint32_t hv = pack_hi(v0, v1, &ra, &rb);
                    *(uint32_t*)(outHi + (size_t)row * N + col) = hv;
                    *(uint32_t*)(outLo + (size_t)row * N + col) = pack_bf(ra, rb);
                }
            }
        }
    }
}

// ---------------------------------------------------------------------------
// Attention scores via mma: S[b,q,k] = (Qhi/lo . Khi/lo)/8, mask -> -inf
// Block: 128q x 128k tile, 256 threads (8 warps, 64x32 each), dk=64 one shot.
// ---------------------------------------------------------------------------
#define SC_STRIDE_B 144                         // 64 bf16 data + pad
#define SC_TILE_B (128 * SC_STRIDE_B)           // 18432
#define SC_SMEM (4 * SC_TILE_B)                 // 73728

__global__ void __launch_bounds__(256, 1) attn_scores_mma_kernel(
    const __nv_bfloat16* __restrict__ QKVH, const __nv_bfloat16* __restrict__ QKVL,
    const unsigned char* __restrict__ mask, float* __restrict__ S)
{
    const int tid = threadIdx.x;
    const int wid = tid >> 5;
    const int lane = tid & 31;
    const int b = blockIdx.z;
    const int n = b >> 4;
    const int h = b & 15;
    const int q0 = blockIdx.y * 128;
    const int k0 = blockIdx.x * 128;

    uint32_t db = s2u(g_dsm);
    uint32_t sQh = db, sQl = db + SC_TILE_B, sKh = db + 2 * SC_TILE_B,
             sKl = db + 3 * SC_TILE_B;

    const __nv_bfloat16* Qh = QKVH + (size_t)n * LEN * QKVS + h * DK;
    const __nv_bfloat16* Ql = QKVL + (size_t)n * LEN * QKVS + h * DK;
    const __nv_bfloat16* Kh = QKVH + (size_t)n * LEN * QKVS + DIM + h * DK;
    const __nv_bfloat16* Kl = QKVL + (size_t)n * LEN * QKVS + DIM + h * DK;

    #pragma unroll
    for (int i = 0; i < 4; i++) {
        int c = tid + i * 256;                  // 0..1023
        int row = c >> 3;
        int col = c & 7;
        uint32_t doff = (uint32_t)(row * SC_STRIDE_B + col * 16);
        cp16(sQh + doff, Qh + (size_t)(q0 + row) * QKVS + col * 8);
        cp16(sQl + doff, Ql + (size_t)(q0 + row) * QKVS + col * 8);
        cp16(sKh + doff, Kh + (size_t)(k0 + row) * QKVS + col * 8);
        cp16(sKl + doff, Kl + (size_t)(k0 + row) * QKVS + col * 8);
    }
    cp_commit();
    cp_wait<0>();
    __syncthreads();

    const int wr = wid >> 2;       // 0-1 : 64 q rows
    const int wc = wid & 3;        // 0-3 : 32 k cols
    const int a_row = (lane & 15);
    const int a_ko  = (lane >> 4) * 8;
    const int b_row = ((lane >> 4) * 8) + (lane & 7);
    const int b_ko  = ((lane >> 3) & 1) * 8;

    float acc[4][4][4] = {};
    #pragma unroll
    for (int k16 = 0; k16 < 4; k16++) {
        uint32_t ah[4][4], al[4][4], bh[2][4], bl[2][4];
        #pragma unroll
        for (int mi = 0; mi < 4; mi++) {
            uint32_t off = (uint32_t)((wr * 64 + mi * 16 + a_row) * SC_STRIDE_B
                                      + (k16 * 16 + a_ko) * 2);
            ldsm4(ah[mi], sQh + off);
            ldsm4(al[mi], sQl + off);
        }
        #pragma unroll
        for (int nf = 0; nf < 2; nf++) {
            uint32_t off = (uint32_t)((wc * 32 + nf * 16 + b_row) * SC_STRIDE_B
                                      + (k16 * 16 + b_ko) * 2);
            ldsm4(bh[nf], sKh + off);
            ldsm4(bl[nf], sKl + off);
        }
        #pragma unroll
        for (int mi = 0; mi < 4; mi++) {
            #pragma unroll
            for (int ni = 0; ni < 4; ni++) {
                int nf = ni >> 1, o = (ni & 1) * 2;
                mma_bf16(acc[mi][ni], ah[mi], bh[nf][o], bh[nf][o + 1]);
                mma_bf16(acc[mi][ni], ah[mi], bl[nf][o], bl[nf][o + 1]);
                mma_bf16(acc[mi][ni], al[mi], bh[nf][o], bh[nf][o + 1]);
            }
        }
    }

    const unsigned char* mp = mask + (size_t)n * LEN * LEN;
    float* Sp = S + (size_t)b * LEN * LEN;
    const int tq = lane >> 2;
    const int tc = (lane & 3) * 2;
    #pragma unroll
    for (int mi = 0; mi < 4; mi++) {
        #pragma unroll
        for (int ni = 0; ni < 4; ni++) {
            int col = k0 + wc * 32 + ni * 8 + tc;
            #pragma unroll
            for (int half = 0; half < 2; half++) {
                int row = q0 + wr * 64 + mi * 16 + tq + half * 8;
                float v0 = acc[mi][ni][half * 2 + 0] * 0.125f;
                float v1 = acc[mi][ni][half * 2 + 1] * 0.125f;
                const unsigned char* mrow = mp + (size_t)row * LEN + col;
                if (mrow[0]) v0 = -INFINITY;
                if (mrow[1]) v1 = -INFINITY;
                *(float2*)(Sp + (size_t)row * LEN + col) = make_float2(v0, v1);
            }
        }
    }
}

// ---------------------------------------------------------------------------
// Row softmax over L=512; reads fp32 S, writes bf16 hi/lo probs.
// ---------------------------------------------------------------------------
__global__ __launch_bounds__(128) void softmax_kernel(
    const float* __restrict__ S,
    __nv_bfloat16* __restrict__ SH, __nv_bfloat16* __restrict__ SL)
{
    size_t row = blockIdx.x;
    const float4* p = (const float4*)(S + row * LEN);
    int tid = threadIdx.x;
    float4 v = p[tid];
    __shared__ float ra[4], rb[4];

    float mx = fmaxf(fmaxf(v.x, v.y), fmaxf(v.z, v.w));
    #pragma unroll
    for (int o = 16; o; o >>= 1) mx = fmaxf(mx, __shfl_xor_sync(0xffffffffu, mx, o));
    if ((tid & 31) == 0) ra[tid >> 5] = mx;
    __syncthreads();
    mx = fmaxf(fmaxf(ra[0], ra[1]), fmaxf(ra[2], ra[3]));

    float4 e;
    if (mx == -INFINITY) {
        e.x = e.y = e.z = e.w = 0.0f;
    } else {
        e.x = expf(v.x - mx); e.y = expf(v.y - mx);
        e.z = expf(v.z - mx); e.w = expf(v.w - mx);
    }
    float s = e.x + e.y + e.z + e.w;
    #pragma unroll
    for (int o = 16; o; o >>= 1) s += __shfl_xor_sync(0xffffffffu, s, o);
    if ((tid & 31) == 0) rb[tid >> 5] = s;
    __syncthreads();
    s = rb[0] + rb[1] + rb[2] + rb[3];

    float inv = (s > 0.0f) ? 1.0f / s : 0.0f;
    e.x *= inv; e.y *= inv; e.z *= inv; e.w *= inv;

    size_t base = row * LEN + tid * 4;
    float r0, r1, r2, r3;
    uint32_t h0 = pack_hi(e.x, e.y, &r0, &r1);
    uint32_t h1 = pack_hi(e.z, e.w, &r2, &r3);
    *(uint2*)(SH + base) = make_uint2(h0, h1);
    *(uint2*)(SL + base) = make_uint2(pack_bf(r0, r1), pack_bf(r2, r3));
}

// ---------------------------------------------------------------------------
// Context via mma: ctx[b,q,d] = sum_k probs * V, 3-stage pipeline.
// Block: 128q x 64d, 256 threads (8 warps, 32q x 32d each), BK=64.
// V fragments via ldmatrix.trans on [s][d] layout.
// ---------------------------------------------------------------------------
#define CX_STAGES 3
#define CX_A_TILE (128 * SC_STRIDE_B)            // 18432 (128q x 64k)
#define CX_V_TILE (64 * SC_STRIDE_B)             // 9216  (64s x 64d)
#define CX_STAGE_B (2 * CX_A_TILE + 2 * CX_V_TILE)   // 55296
#define CX_SMEM (CX_STAGES * CX_STAGE_B)             // 165888

__global__ void __launch_bounds__(256, 1) attn_ctx_mma_kernel(
    const __nv_bfloat16* __restrict__ SH, const __nv_bfloat16* __restrict__ SL,
    const __nv_bfloat16* __restrict__ QKVH, const __nv_bfloat16* __restrict__ QKVL,
    __nv_bfloat16* __restrict__ Chi, __nv_bfloat16* __restrict__ Clo)
{
    const int tid = threadIdx.x;
    const int wid = tid >> 5;
    const int lane = tid & 31;
    const int b = blockIdx.y;
    const int n = b >> 4;
    const int h = b & 15;
    const int q0 = blockIdx.x * 128;

    uint32_t db = s2u(g_dsm);

    const __nv_bfloat16* Ah = SH + (size_t)b * LEN * LEN;
    const __nv_bfloat16* Al = SL + (size_t)b * LEN * LEN;
    const __nv_bfloat16* Vh = QKVH + (size_t)n * LEN * QKVS + 2 * DIM + h * DK;
    const __nv_bfloat16* Vl = QKVL + (size_t)n * LEN * QKVS + 2 * DIM + h * DK;

    // Stage loader: A rows 128 x 8 chunks (4/thread), V rows 64 x 8 (2/thread)
    auto load_stage = [&](int st, int kc) {
        uint32_t sb = db + (uint32_t)st * CX_STAGE_B;
        #pragma unroll
        for (int i = 0; i < 4; i++) {
            int c = tid + i * 256;
            int row = c >> 3;
            int col = c & 7;
            uint32_t doff = (uint32_t)(row * SC_STRIDE_B + col * 16);
            cp16(sb + doff, Ah + (size_t)(q0 + row) * LEN + kc * 64 + col * 8);
            cp16(sb + CX_A_TILE + doff,
                 Al + (size_t)(q0 + row) * LEN + kc * 64 + col * 8);
        }
        #pragma unroll
        for (int i = 0; i < 2; i++) {
            int c = tid + i * 256;
            int row = c >> 3;
            int col = c & 7;
            uint32_t doff = (uint32_t)(row * SC_STRIDE_B + col * 16);
            cp16(sb + 2 * CX_A_TILE + doff,
                 Vh + (size_t)(kc * 64 + row) * QKVS + col * 8);
            cp16(sb + 2 * CX_A_TILE + CX_V_TILE + doff,
                 Vl + (size_t)(kc * 64 + row) * QKVS + col * 8);
        }
        cp_commit();
    };

    #pragma unroll
    for (int s = 0; s < CX_STAGES - 1; s++) load_stage(s, s);

    const int wr = wid >> 1;       // 0-3 : 32 q rows
    const int wc = wid & 1;        // 0-1 : 32 d cols
    const int a_row = (lane & 15);
    const int a_ko  = (lane >> 4) * 8;
    // trans ldmatrix lane addressing on V [s][d]
    const int v_row = (lane & 7) + ((lane >> 3) & 1) * 8;
    const int v_cb  = (lane >> 4) * 16;

    float acc[2][4][4] = {};
    const int nk = LEN / 64;       // 8

    for (int kc = 0; kc < nk; kc++) {
        cp_wait<CX_STAGES - 2>();
        __syncthreads();

        if (kc + CX_STAGES - 1 < nk)
            load_stage((kc + CX_STAGES - 1) % CX_STAGES, kc + CX_STAGES - 1);
        else
            cp_commit();

        uint32_t sb = db + (uint32_t)(kc % CX_STAGES) * CX_STAGE_B;
        uint32_t sAh = sb, sAl = sb + CX_A_TILE;
        uint32_t sVh = sb + 2 * CX_A_TILE, sVl = sVh + CX_V_TILE;

        #pragma unroll
        for (int k16 = 0; k16 < 4; k16++) {
            uint32_t ah[2][4], al[2][4], bh[2][4], bl[2][4];
            #pragma unroll
            for (int mi = 0; mi < 2; mi++) {
                uint32_t off = (uint32_t)((wr * 32 + mi * 16 + a_row) * SC_STRIDE_B
                                          + (k16 * 16 + a_ko) * 2);
                ldsm4(ah[mi], sAh + off);
                ldsm4(al[mi], sAl + off);
            }
            #pragma unroll
            for (int nf = 0; nf < 2; nf++) {
                uint32_t off = (uint32_t)((k16 * 16 + v_row) * SC_STRIDE_B
                                          + (wc * 32 + nf * 16) * 2 + v_cb);
                ldsm4t(bh[nf], sVh + off);
                ldsm4t(bl[nf], sVl + off);
            }
            #pragma unroll
            for (int mi = 0; mi < 2; mi++) {
                #pragma unroll
                for (int ni = 0; ni < 4; ni++) {
                    int nf = ni >> 1, o = (ni & 1) * 2;
                    mma_bf16(acc[mi][ni], ah[mi], bh[nf][o], bh[nf][o + 1]);
                    mma_bf16(acc[mi][ni], ah[mi], bl[nf][o], bl[nf][o + 1]);
                    mma_bf16(acc[mi][ni], al[mi], bh[nf][o], bh[nf][o + 1]);
                }
            }
        }
    }

    const int tq = lane >> 2;
    const int tc = (lane & 3) * 2;
    #pragma unroll
    for (int mi = 0; mi < 2; mi++) {
        #pragma unroll
        for (int ni = 0; ni < 4; ni++) {
            int col = h * DK + wc * 32 + ni * 8 + tc;
            #pragma unroll
            for (int half = 0; half < 2; half++) {
                size_t row = (size_t)n * LEN + q0 + wr * 32 + mi * 16 + tq + half * 8;
                float v0 = acc[mi][ni][half * 2 + 0];
                float v1 = acc[mi][ni][half * 2 + 1];
                float ra, rb;
                uint32_t hv = pack_hi(v0, v1, &ra, &rb);
                *(uint32_t*)(Chi + row * DIM + col) = hv;
                *(uint32_t*)(Clo + row * DIM + col) = pack_bf(ra, rb);
            }
        }
    }
}

// ---------------------------------------------------------------------------
// Elementwise fp32 -> bf16 hi/lo split
// ---------------------------------------------------------------------------
__global__ __launch_bounds__(256) void split_kernel(
    const float4* __restrict__ X, uint2* __restrict__ Hh, uint2* __restrict__ Ll, int n4)
{
    int i = blockIdx.x * 256 + threadIdx.x;
    if (i >= n4) return;
    float4 v = X[i];
    float r0, r1, r2, r3;
    uint32_t h0 = pack_hi(v.x, v.y, &r0, &r1);
    uint32_t h1 = pack_hi(v.z, v.w, &r2, &r3);
    Hh[i] = make_uint2(h0, h1);
    Ll[i] = make_uint2(pack_bf(r0, r1), pack_bf(r2, r3));
}

// ---------------------------------------------------------------------------
// Transposed split: W[Kr,Nc] fp32 -> TH/TL [Nc,Kr] bf16
// ---------------------------------------------------------------------------
__global__ __launch_bounds__(256) void transpose_split_kernel(
    const float* __restrict__ W, __nv_bfloat16* __restrict__ TH,
    __nv_bfloat16* __restrict__ TL, int Kr, int Nc)
{
    __shared__ float t[32][33];
    int n0 = blockIdx.x * 32, k0 = blockIdx.y * 32;
    int tx = threadIdx.x, ty = threadIdx.y;     // 32 x 8
    #pragma unroll
    for (int i = 0; i < 4; i++)
        t[ty + i * 8][tx] = W[(size_t)(k0 + ty + i * 8) * Nc + n0 + tx];
    __syncthreads();
    #pragma unroll
    for (int i = 0; i < 4; i++) {
        int n = n0 + ty + i * 8;
        int k = k0 + tx;
        float v = t[tx][ty + i * 8];
        __nv_bfloat16 h = __float2bfloat16(v);
        TH[(size_t)n * Kr + k] = h;
        TL[(size_t)n * Kr + k] = __float2bfloat16(v - __bfloat162float(h));
    }
}

__global__ __launch_bounds__(256) void concat_bias_kernel(
    const float* __restrict__ a, const float* __restrict__ b,
    const float* __restrict__ c, float* __restrict__ o)
{
    int i = blockIdx.x * 256 + threadIdx.x;
    if (i < 1024) o[i] = a[i];
    else if (i < 2048) o[i] = b[i - 1024];
    else if (i < 3072) o[i] = c[i - 2048];
}

// ---------------------------------------------------------------------------
// LayerNorm over last dim (1024); optional bf16 hi/lo split output
// ---------------------------------------------------------------------------
__global__ __launch_bounds__(256) void layernorm_kernel(
    const float* __restrict__ X, const float* __restrict__ gg,
    const float* __restrict__ bb, float* __restrict__ Y,
    __nv_bfloat16* __restrict__ Yhi, __nv_bfloat16* __restrict__ Ylo)
{
    int row = blockIdx.x;
    int tid = threadIdx.x;
    const float4* Xp = (const float4*)(X + (size_t)row * DIM);
    float4 x = Xp[tid];
    __shared__ float red[8];

    float s = x.x + x.y + x.z + x.w;
    #pragma unroll
    for (int o = 16; o; o >>= 1) s += __shfl_xor_sync(0xffffffffu, s, o);
    if ((tid & 31) == 0) red[tid >> 5] = s;
    __syncthreads();
    float mean = (red[0] + red[1] + red[2] + red[3] +
                  red[4] + red[5] + red[6] + red[7]) * (1.0f / DIM);

    float d0 = x.x - mean, d1 = x.y - mean, d2 = x.z - mean, d3 = x.w - mean;
    float s2 = d0 * d0 + d1 * d1 + d2 * d2 + d3 * d3;
    __syncthreads();
    #pragma unroll
    for (int o = 16; o; o >>= 1) s2 += __shfl_xor_sync(0xffffffffu, s2, o);
    if ((tid & 31) == 0) red[tid >> 5] = s2;
    __syncthreads();
    float var = (red[0] + red[1] + red[2] + red[3] +
                 red[4] + red[5] + red[6] + red[7]) * (1.0f / DIM);
    float rs = rsqrtf(var + 1e-5f);

    float4 gv = ((const float4*)gg)[tid];
    float4 bv = ((const float4*)bb)[tid];
    float4 y;
    y.x = d0 * rs * gv.x + bv.x;
    y.y = d1 * rs * gv.y + bv.y;
    y.z = d2 * rs * gv.z + bv.z;
    y.w = d3 * rs * gv.w + bv.w;
    ((float4*)(Y + (size_t)row * DIM))[tid] = y;
    if (Yhi) {
        size_t base = (size_t)row * DIM + tid * 4;
        float r0, r1, r2, r3;
        uint32_t h0 = pack_hi(y.x, y.y, &r0, &r1);
        uint32_t h1 = pack_hi(y.z, y.w, &r2, &r3);
        *(uint2*)(Yhi + base) = make_uint2(h0, h1);
        *(uint2*)(Ylo + base) = make_uint2(pack_bf(r0, r1), pack_bf(r2, r3));
    }
}

// ---------------------------------------------------------------------------
// Launcher
// ---------------------------------------------------------------------------
extern "C" void kernel_launch(void* const* d_in, const int* in_sizes, int n_in,
                              void* d_out, int out_size)
{
    const float*         x    = (const float*)d_in[0];
    const unsigned char* mask = (const unsigned char*)d_in[1];
    const float* WQ = (const float*)d_in[2];
    const float* bQ = (const float*)d_in[3];
    const float* WK = (const float*)d_in[4];
    const float* bK = (const float*)d_in[5];
    const float* WV = (const float*)d_in[6];
    const float* bV = (const float*)d_in[7];
    const float* WO = (const float*)d_in[8];
    const float* bO = (const float*)d_in[9];
    const float* g0 = (const float*)d_in[10];
    const float* b0 = (const float*)d_in[11];
    const float* W1 = (const float*)d_in[12];
    const float* b1 = (const float*)d_in[13];
    const float* W2 = (const float*)d_in[14];
    const float* b2 = (const float*)d_in[15];
    const float* g1 = (const float*)d_in[16];
    const float* b1n = (const float*)d_in[17];
    float* out = (float*)d_out;

    float* base = nullptr;
    cudaGetSymbolAddress((void**)&base, g_scratch);
    float* S   = base + OFF_S;
    float* T0  = base + OFF_T0;
    float* Hf  = base + OFF_H;
    float* T1  = base + OFF_T1;
    float* bqkv = base + OFF_BQKV;
    __nv_bfloat16* SH    = (__nv_bfloat16*)(base + OFF_SH);
    __nv_bfloat16* SL    = (__nv_bfloat16*)(base + OFF_SL);
    __nv_bfloat16* QKVH  = (__nv_bfloat16*)(base + OFF_QKVH);
    __nv_bfloat16* QKVL  = (__nv_bfloat16*)(base + OFF_QKVL);
    __nv_bfloat16* XH  = (__nv_bfloat16*)(base + OFF_XH);
    __nv_bfloat16* XL  = (__nv_bfloat16*)(base + OFF_XL);
    __nv_bfloat16* WQKVH = (__nv_bfloat16*)(base + OFF_WQKVH);
    __nv_bfloat16* WQKVL = (__nv_bfloat16*)(base + OFF_WQKVL);
    __nv_bfloat16* WOH = (__nv_bfloat16*)(base + OFF_WOH);
    __nv_bfloat16* WOL = (__nv_bfloat16*)(base + OFF_WOL);
    __nv_bfloat16* W1H = (__nv_bfloat16*)(base + OFF_W1H);
    __nv_bfloat16* W1L = (__nv_bfloat16*)(base + OFF_W1L);
    __nv_bfloat16* W2H = (__nv_bfloat16*)(base + OFF_W2H);
    __nv_bfloat16* W2L = (__nv_bfloat16*)(base + OFF_W2L);
    __nv_bfloat16* CH  = (__nv_bfloat16*)(base + OFF_CH);
    __nv_bfloat16* CL  = (__nv_bfloat16*)(base + OFF_CL);
    __nv_bfloat16* HH  = (__nv_bfloat16*)(base + OFF_HH);
    __nv_bfloat16* HL  = (__nv_bfloat16*)(base + OFF_HL);
    __nv_bfloat16* FH  = (__nv_bfloat16*)(base + OFF_FH);
    __nv_bfloat16* FL  = (__nv_bfloat16*)(base + OFF_FL);

    cudaFuncSetAttribute(gemm_mma_kernel,
                         cudaFuncAttributeMaxDynamicSharedMemorySize, G_SMEM_DYN);
    cudaFuncSetAttribute(attn_scores_mma_kernel,
                         cudaFuncAttributeMaxDynamicSharedMemorySize, SC_SMEM);
    cudaFuncSetAttribute(attn_ctx_mma_kernel,
                         cudaFuncAttributeMaxDynamicSharedMemorySize, CX_SMEM);

    dim3 tb(32, 8);

    // Launches 0-4
    split_kernel<<<(TOK * DIM / 4 + 255) / 256, 256>>>(
        (const float4*)x, (uint2*)XH, (uint2*)XL, TOK * DIM / 4);
    transpose_split_kernel<<<dim3(DIM / 32, DIM / 32), tb>>>(
        WQ, WQKVH + (size_t)0 * DIM * DIM, WQKVL + (size_t)0 * DIM * DIM, DIM, DIM);
    transpose_split_kernel<<<dim3(DIM / 32, DIM / 32), tb>>>(
        WK, WQKVH + (size_t)1 * DIM * DIM, WQKVL + (size_t)1 * DIM * DIM, DIM, DIM);
    transpose_split_kernel<<<dim3(DIM / 32, DIM / 32), tb>>>(
        WV, WQKVH + (size_t)2 * DIM * DIM, WQKVL + (size_t)2 * DIM * DIM, DIM, DIM);
    concat_bias_kernel<<<12, 256>>>(bQ, bK, bV, bqkv);

    // Launch 5 (ncu-profiled): fused QKV GEMM -> bf16 hi/lo
    gemm_mma_kernel<<<dim3(QKVS / 128, TOK / 128), 512, G_SMEM_DYN>>>(
        XH, XL, WQKVH, WQKVL, bqkv, nullptr,
        nullptr, QKVH, QKVL, TOK, QKVS, DIM, 0);

    // Remaining weight transposes
    transpose_split_kernel<<<dim3(DIM / 32, DIM / 32), tb>>>(WO, WOH, WOL, DIM, DIM);
    transpose_split_kernel<<<dim3(FF / 32, DIM / 32), tb>>>(W1, W1H, W1L, DIM, FF);
    transpose_split_kernel<<<dim3(DIM / 32, FF / 32), tb>>>(W2, W2H, W2L, FF, DIM);

    // Attention (mma path)
    attn_scores_mma_kernel<<<dim3(LEN / 128, LEN / 128, NB * HEADS), 256, SC_SMEM>>>(
        QKVH, QKVL, mask, S);
    softmax_kernel<<<NB * HEADS * LEN, 128>>>(S, SH, SL);
    attn_ctx_mma_kernel<<<dim3(LEN / 128, NB * HEADS), 256, CX_SMEM>>>(
        SH, SL, QKVH, QKVL, CH, CL);

    dim3 gD(DIM / 128, TOK / 128);
    dim3 gF(FF / 128, TOK / 128);

    // O projection + residual(x), layernorm0 (emits split for FFN1)
    gemm_mma_kernel<<<gD, 512, G_SMEM_DYN>>>(CH, CL, WOH, WOL, bO, x,
                                             T0, nullptr, nullptr, TOK, DIM, DIM, 0);
    layernorm_kernel<<<TOK, 256>>>(T0, g0, b0, Hf, HH, HL);

    // FFN
    gemm_mma_kernel<<<gF, 512, G_SMEM_DYN>>>(HH, HL, W1H, W1L, b1, nullptr,
                                             nullptr, FH, FL, TOK, FF, DIM, 1);
    gemm_mma_kernel<<<gD, 512, G_SMEM_DYN>>>(FH, FL, W2H, W2L, b2, Hf,
                                             T1, nullptr, nullptr, TOK, DIM, FF, 0);

    // Final layernorm -> output
    layernorm_kernel<<<TOK, 256>>>(T1, g1, b1n, out, nullptr, nullptr);
}

// round 6
// speedup vs baseline: 2.4845x; 1.0691x over previous
#include <cuda_runtime.h>
#include <cuda_bf16.h>
#include <math.h>
#include <stdint.h>

// Problem constants
#define NB    16
#define LEN   512
#define DIM   1024
#define HEADS 16
#define DK    64
#define FF    4096
#define TOK   (NB * LEN)          // 8192 rows
#define QKVS  3072                // fused QKV row stride

// ---------------------------------------------------------------------------
// Scratch layout (units: floats)
// ---------------------------------------------------------------------------
#define MFe ((size_t)1 << 20)
#define OFF_QKVH  (0 * MFe)           // bf16 8192x3072
#define OFF_QKVL  (12 * MFe)
#define OFF_T0    (24 * MFe)          // fp32 8192x1024
#define OFF_H     (32 * MFe)
#define OFF_T1    (40 * MFe)
#define OFF_XH    (48 * MFe)          // bf16 8192x1024
#define OFF_XL    (52 * MFe)
#define OFF_WQKVH (56 * MFe)          // bf16 3072x1024
#define OFF_WQKVL (58 * MFe)
#define OFF_WOH   (60 * MFe)          // bf16 1024x1024 (0.5 MFe)
#define OFF_WOL   (OFF_WOH + MFe / 2)
#define OFF_W1H   (61 * MFe)          // bf16 4096x1024
#define OFF_W1L   (63 * MFe)
#define OFF_W2H   (65 * MFe)          // bf16 1024x4096
#define OFF_W2L   (67 * MFe)
#define OFF_CH    (69 * MFe)          // bf16 8192x1024
#define OFF_CL    (73 * MFe)
#define OFF_HH    (77 * MFe)
#define OFF_HL    (81 * MFe)
#define OFF_FH    (85 * MFe)          // bf16 8192x4096
#define OFF_FL    (101 * MFe)
#define OFF_BQKV  (117 * MFe)         // fp32 3072
#define SCRATCH_FLOATS (118 * MFe)

__device__ float g_scratch[SCRATCH_FLOATS];

// ---------------------------------------------------------------------------
// PTX helpers (sm_80-baseline: cp.async, ldmatrix, mma.sync)
// ---------------------------------------------------------------------------
__device__ __forceinline__ uint32_t s2u(const void* p) {
    uint32_t r;
    asm("{ .reg .u64 t; cvta.to.shared.u64 t, %1; cvt.u32.u64 %0, t; }"
        : "=r"(r) : "l"(p));
    return r;
}

__device__ __forceinline__ void cp16(uint32_t dst, const void* src) {
    asm volatile("cp.async.cg.shared.global [%0], [%1], 16;" :: "r"(dst), "l"(src));
}
__device__ __forceinline__ void cp_commit() {
    asm volatile("cp.async.commit_group;" ::: "memory");
}
template <int N> __device__ __forceinline__ void cp_wait() {
    asm volatile("cp.async.wait_group %0;" :: "n"(N) : "memory");
}

__device__ __forceinline__ void ldsm4(uint32_t* r, uint32_t addr) {
    asm volatile("ldmatrix.sync.aligned.m8n8.x4.shared.b16 {%0,%1,%2,%3}, [%4];"
                 : "=r"(r[0]), "=r"(r[1]), "=r"(r[2]), "=r"(r[3]) : "r"(addr));
}
__device__ __forceinline__ void ldsm4t(uint32_t* r, uint32_t addr) {
    asm volatile("ldmatrix.sync.aligned.m8n8.x4.trans.shared.b16 {%0,%1,%2,%3}, [%4];"
                 : "=r"(r[0]), "=r"(r[1]), "=r"(r[2]), "=r"(r[3]) : "r"(addr));
}

__device__ __forceinline__ void mma_bf16(float* d, const uint32_t* a,
                                         uint32_t b0, uint32_t b1) {
    asm volatile(
        "mma.sync.aligned.m16n8k16.row.col.f32.bf16.bf16.f32 "
        "{%0,%1,%2,%3}, {%4,%5,%6,%7}, {%8,%9}, {%0,%1,%2,%3};"
        : "+f"(d[0]), "+f"(d[1]), "+f"(d[2]), "+f"(d[3])
        : "r"(a[0]), "r"(a[1]), "r"(a[2]), "r"(a[3]), "r"(b0), "r"(b1));
}

__device__ __forceinline__ float gelu_exact(float v) {
    return 0.5f * v * (1.0f + erff(v * 0.70710678118654752f));
}

__device__ __forceinline__ uint32_t pack_hi(float a, float b, float* ra, float* rb) {
    __nv_bfloat16 ha = __float2bfloat16(a);
    __nv_bfloat16 hb = __float2bfloat16(b);
    *ra = a - __bfloat162float(ha);
    *rb = b - __bfloat162float(hb);
    return (uint32_t)__bfloat16_as_ushort(ha) |
           ((uint32_t)__bfloat16_as_ushort(hb) << 16);
}
__device__ __forceinline__ uint32_t pack_bf(float a, float b) {
    __nv_bfloat16 ha = __float2bfloat16(a);
    __nv_bfloat16 hb = __float2bfloat16(b);
    return (uint32_t)__bfloat16_as_ushort(ha) |
           ((uint32_t)__bfloat16_as_ushort(hb) << 16);
}

// ---------------------------------------------------------------------------
// bf16-split GEMM via mma.sync, 5-stage cp.async pipeline, 512 threads.
// CTA tile 128x128, BK=32, 16 warps (32x32 each).
// ---------------------------------------------------------------------------
#define G_STAGES 5
#define SA_STRIDE 40                          // bf16 units per smem row (80 B)
#define G_TILE_B (128 * SA_STRIDE * 2)        // 10240 B per 128x32 tile
#define G_STAGE_B (4 * G_TILE_B)              // 40960 B
#define G_SMEM_DYN (G_STAGES * G_STAGE_B)     // 204800 B

__device__ __forceinline__ void load_tile512(uint32_t sbase, const __nv_bfloat16* g,
                                             int K, int k0, int tid) {
    int row = tid >> 2;
    int col = tid & 3;
    cp16(sbase + (uint32_t)(row * (SA_STRIDE * 2) + col * 16),
         g + (size_t)row * K + k0 + col * 8);
}

extern __shared__ char g_dsm[];

__global__ void __launch_bounds__(512, 1) gemm_mma_kernel(
    const __nv_bfloat16* __restrict__ Ahi, const __nv_bfloat16* __restrict__ Alo,
    const __nv_bfloat16* __restrict__ Bhi, const __nv_bfloat16* __restrict__ Blo,
    const float* __restrict__ bias, const float* __restrict__ resid,
    float* __restrict__ outF,
    __nv_bfloat16* __restrict__ outHi, __nv_bfloat16* __restrict__ outLo,
    int M, int N, int K, int gelu)
{
    const int tid = threadIdx.x;
    const int wid = tid >> 5;
    const int lane = tid & 31;
    const int wr = wid >> 2;
    const int wc = wid & 3;
    const int bm = blockIdx.y * 128;
    const int bn = blockIdx.x * 128;

    uint32_t db = s2u(g_dsm);

    const __nv_bfloat16* Ah = Ahi + (size_t)bm * K;
    const __nv_bfloat16* Al = Alo + (size_t)bm * K;
    const __nv_bfloat16* Bh = Bhi + (size_t)bn * K;
    const __nv_bfloat16* Bl = Blo + (size_t)bn * K;

    float acc[2][4][4] = {};

    const int nk = K / 32;

    #pragma unroll
    for (int s = 0; s < G_STAGES - 1; s++) {
        if (s < nk) {
            uint32_t sb = db + (uint32_t)s * G_STAGE_B;
            load_tile512(sb + 0 * G_TILE_B, Ah, K, s * 32, tid);
            load_tile512(sb + 1 * G_TILE_B, Al, K, s * 32, tid);
            load_tile512(sb + 2 * G_TILE_B, Bh, K, s * 32, tid);
            load_tile512(sb + 3 * G_TILE_B, Bl, K, s * 32, tid);
        }
        cp_commit();
    }

    const int a_row = (lane & 15);
    const int a_ko  = (lane >> 4) * 8;
    const int b_row = ((lane >> 4) * 8) + (lane & 7);
    const int b_ko  = ((lane >> 3) & 1) * 8;

    for (int kt = 0; kt < nk; kt++) {
        cp_wait<G_STAGES - 2>();
        __syncthreads();

        int pf = kt + G_STAGES - 1;
        if (pf < nk) {
            uint32_t nb = db + (uint32_t)(pf % G_STAGES) * G_STAGE_B;
            int k0 = pf * 32;
            load_tile512(nb + 0 * G_TILE_B, Ah, K, k0, tid);
            load_tile512(nb + 1 * G_TILE_B, Al, K, k0, tid);
            load_tile512(nb + 2 * G_TILE_B, Bh, K, k0, tid);
            load_tile512(nb + 3 * G_TILE_B, Bl, K, k0, tid);
        }
        cp_commit();

        uint32_t sb = db + (uint32_t)(kt % G_STAGES) * G_STAGE_B;
        uint32_t sAh = sb + 0 * G_TILE_B;
        uint32_t sAl = sb + 1 * G_TILE_B;
        uint32_t sBh = sb + 2 * G_TILE_B;
        uint32_t sBl = sb + 3 * G_TILE_B;

        #pragma unroll
        for (int k16 = 0; k16 < 2; k16++) {
            uint32_t ah[2][4], al[2][4], bh[2][4], bl[2][4];
            #pragma unroll
            for (int mi = 0; mi < 2; mi++) {
                uint32_t off = (uint32_t)((wr * 32 + mi * 16 + a_row) * (SA_STRIDE * 2)
                                          + (k16 * 16 + a_ko) * 2);
                ldsm4(ah[mi], sAh + off);
                ldsm4(al[mi], sAl + off);
            }
            #pragma unroll
            for (int nf = 0; nf < 2; nf++) {
                uint32_t off = (uint32_t)((wc * 32 + nf * 16 + b_row) * (SA_STRIDE * 2)
                                          + (k16 * 16 + b_ko) * 2);
                ldsm4(bh[nf], sBh + off);
                ldsm4(bl[nf], sBl + off);
            }
            #pragma unroll
            for (int mi = 0; mi < 2; mi++) {
                #pragma unroll
                for (int ni = 0; ni < 4; ni++) {
                    int nf = ni >> 1, o = (ni & 1) * 2;
                    mma_bf16(acc[mi][ni], ah[mi], bh[nf][o], bh[nf][o + 1]);
                    mma_bf16(acc[mi][ni], ah[mi], bl[nf][o], bl[nf][o + 1]);
                    mma_bf16(acc[mi][ni], al[mi], bh[nf][o], bh[nf][o + 1]);
                }
            }
        }
    }

    const int tq = lane >> 2;
    const int tc = (lane & 3) * 2;
    #pragma unroll
    for (int mi = 0; mi < 2; mi++) {
        #pragma unroll
        for (int ni = 0; ni < 4; ni++) {
            int col = bn + wc * 32 + ni * 8 + tc;
            float bx = bias[col], by = bias[col + 1];
            #pragma unroll
            for (int half = 0; half < 2; half++) {
                int row = bm + wr * 32 + mi * 16 + tq + half * 8;
                float v0 = acc[mi][ni][half * 2 + 0] + bx;
                float v1 = acc[mi][ni][half * 2 + 1] + by;
                if (gelu) { v0 = gelu_exact(v0); v1 = gelu_exact(v1); }
                if (resid) {
                    float2 rv = *(const float2*)(resid + (size_t)row * N + col);
                    v0 += rv.x; v1 += rv.y;
                }
                if (outF)
                    *(float2*)(outF + (size_t)row * N + col) = make_float2(v0, v1);
                if (outHi) {
                    float ra, rb;
                    uint32_t hv = pack_hi(v0, v1, &ra, &rb);
                    *(uint32_t*)(outHi + (size_t)row * N + col) = hv;
                    *(uint32_t*)(outLo + (size_t)row * N + col) = pack_bf(ra, rb);
                }
            }
        }
    }
}

// ---------------------------------------------------------------------------
// Fused flash attention: scores + online softmax + P.V in one kernel.
// Grid (LEN/128, NB*HEADS); 256 threads (8 warps, 16 q-rows each).
// KV processed in 4 chunks of 128, double-buffered cp.async.
// ---------------------------------------------------------------------------
#define FA_STRIDE 144                          // bytes per smem row (64 bf16 + pad)
#define FA_TILE (128 * FA_STRIDE)              // 18432
#define FA_QBASE 0
#define FA_KVBASE (2 * FA_TILE)                // after Qh,Ql
#define FA_BUF_B (4 * FA_TILE)                 // Kh,Kl,Vh,Vl per buffer
#define FA_SMEM (2 * FA_TILE + 2 * FA_BUF_B)   // 184320

__global__ void __launch_bounds__(256, 1) flash_attn_kernel(
    const __nv_bfloat16* __restrict__ QKVH, const __nv_bfloat16* __restrict__ QKVL,
    const unsigned char* __restrict__ mask,
    __nv_bfloat16* __restrict__ Chi, __nv_bfloat16* __restrict__ Clo)
{
    const int tid = threadIdx.x;
    const int wid = tid >> 5;
    const int lane = tid & 31;
    const int b = blockIdx.y;
    const int n = b >> 4;
    const int h = b & 15;
    const int q0 = blockIdx.x * 128;

    uint32_t db = s2u(g_dsm);
    uint32_t sQh = db + FA_QBASE, sQl = sQh + FA_TILE;

    const __nv_bfloat16* Qh = QKVH + (size_t)n * LEN * QKVS + h * DK;
    const __nv_bfloat16* Ql = QKVL + (size_t)n * LEN * QKVS + h * DK;
    const __nv_bfloat16* Kh = QKVH + (size_t)n * LEN * QKVS + DIM + h * DK;
    const __nv_bfloat16* Kl = QKVL + (size_t)n * LEN * QKVS + DIM + h * DK;
    const __nv_bfloat16* Vh = QKVH + (size_t)n * LEN * QKVS + 2 * DIM + h * DK;
    const __nv_bfloat16* Vl = QKVL + (size_t)n * LEN * QKVS + 2 * DIM + h * DK;

    // Load Q tile (128 x 64 hi/lo): 4 chunks per thread per tensor
    #pragma unroll
    for (int i = 0; i < 4; i++) {
        int c = tid + i * 256;
        int row = c >> 3;
        int col = c & 7;
        uint32_t doff = (uint32_t)(row * FA_STRIDE + col * 16);
        cp16(sQh + doff, Qh + (size_t)(q0 + row) * QKVS + col * 8);
        cp16(sQl + doff, Ql + (size_t)(q0 + row) * QKVS + col * 8);
    }
    // Load KV chunk 0
    auto load_kv = [&](int chunk) {
        uint32_t sb = db + FA_KVBASE + (uint32_t)(chunk & 1) * FA_BUF_B;
        #pragma unroll
        for (int i = 0; i < 4; i++) {
            int c = tid + i * 256;
            int row = c >> 3;
            int col = c & 7;
            uint32_t doff = (uint32_t)(row * FA_STRIDE + col * 16);
            size_t goff = (size_t)(chunk * 128 + row) * QKVS + col * 8;
            cp16(sb + doff, Kh + goff);
            cp16(sb + FA_TILE + doff, Kl + goff);
            cp16(sb + 2 * FA_TILE + doff, Vh + goff);
            cp16(sb + 3 * FA_TILE + doff, Vl + goff);
        }
    };
    load_kv(0);
    cp_commit();

    const int a_row = (lane & 15);
    const int a_ko  = (lane >> 4) * 8;
    const int b_row = ((lane >> 4) * 8) + (lane & 7);
    const int b_ko  = ((lane >> 3) & 1) * 8;
    const int v_row = (lane & 7) + ((lane >> 3) & 1) * 8;
    const int v_cb  = (lane >> 4) * 16;
    const int tq = lane >> 2;
    const int tc = (lane & 3) * 2;

    const int r0 = q0 + wid * 16 + tq;
    const int r1 = r0 + 8;
    const unsigned char* mp = mask + (size_t)n * LEN * LEN;

    uint32_t qh[4][4], ql[4][4];
    float o_acc[8][4] = {};
    float m_run0 = -INFINITY, m_run1 = -INFINITY;
    float l0 = 0.0f, l1 = 0.0f;

    for (int c = 0; c < 4; c++) {
        if (c + 1 < 4) load_kv(c + 1);
        cp_commit();
        cp_wait<1>();
        __syncthreads();

        if (c == 0) {
            #pragma unroll
            for (int k16 = 0; k16 < 4; k16++) {
                uint32_t off = (uint32_t)((wid * 16 + a_row) * FA_STRIDE
                                          + (k16 * 16 + a_ko) * 2);
                ldsm4(qh[k16], sQh + off);
                ldsm4(ql[k16], sQl + off);
            }
        }

        uint32_t sb = db + FA_KVBASE + (uint32_t)(c & 1) * FA_BUF_B;
        uint32_t sKhh = sb, sKll = sb + FA_TILE;
        uint32_t sVhh = sb + 2 * FA_TILE, sVll = sb + 3 * FA_TILE;

        // --- scores: 16 x 128 per warp ---
        float s[16][4] = {};
        #pragma unroll
        for (int k16 = 0; k16 < 4; k16++) {
            #pragma unroll
            for (int nf = 0; nf < 8; nf++) {
                uint32_t bh[4], bl[4];
                uint32_t off = (uint32_t)((nf * 16 + b_row) * FA_STRIDE
                                          + (k16 * 16 + b_ko) * 2);
                ldsm4(bh, sKhh + off);
                ldsm4(bl, sKll + off);
                #pragma unroll
                for (int o = 0; o < 2; o++) {
                    int ni = nf * 2 + o;
                    mma_bf16(s[ni], qh[k16], bh[o * 2], bh[o * 2 + 1]);
                    mma_bf16(s[ni], qh[k16], bl[o * 2], bl[o * 2 + 1]);
                    mma_bf16(s[ni], ql[k16], bh[o * 2], bh[o * 2 + 1]);
                }
            }
        }

        // --- scale + mask ---
        const unsigned char* mr0 = mp + (size_t)r0 * LEN + c * 128 + tc;
        const unsigned char* mr1 = mp + (size_t)r1 * LEN + c * 128 + tc;
        #pragma unroll
        for (int ni = 0; ni < 16; ni++) {
            uchar2 m0v = *(const uchar2*)(mr0 + ni * 8);
            uchar2 m1v = *(const uchar2*)(mr1 + ni * 8);
            s[ni][0] = m0v.x ? -INFINITY : s[ni][0] * 0.125f;
            s[ni][1] = m0v.y ? -INFINITY : s[ni][1] * 0.125f;
            s[ni][2] = m1v.x ? -INFINITY : s[ni][2] * 0.125f;
            s[ni][3] = m1v.y ? -INFINITY : s[ni][3] * 0.125f;
        }

        // --- row max (reduce over quad lanes) ---
        float rm0 = -INFINITY, rm1 = -INFINITY;
        #pragma unroll
        for (int ni = 0; ni < 16; ni++) {
            rm0 = fmaxf(rm0, fmaxf(s[ni][0], s[ni][1]));
            rm1 = fmaxf(rm1, fmaxf(s[ni][2], s[ni][3]));
        }
        rm0 = fmaxf(rm0, __shfl_xor_sync(0xffffffffu, rm0, 1));
        rm0 = fmaxf(rm0, __shfl_xor_sync(0xffffffffu, rm0, 2));
        rm1 = fmaxf(rm1, __shfl_xor_sync(0xffffffffu, rm1, 1));
        rm1 = fmaxf(rm1, __shfl_xor_sync(0xffffffffu, rm1, 2));

        float mn0 = fmaxf(m_run0, rm0);
        float mn1 = fmaxf(m_run1, rm1);
        bool dead0 = (mn0 == -INFINITY);
        bool dead1 = (mn1 == -INFINITY);
        float alpha0 = dead0 ? 1.0f : __expf(m_run0 - mn0);
        float alpha1 = dead1 ? 1.0f : __expf(m_run1 - mn1);

        // --- p = exp(s - m), partial row sums ---
        float ps0 = 0.0f, ps1 = 0.0f;
        #pragma unroll
        for (int ni = 0; ni < 16; ni++) {
            s[ni][0] = dead0 ? 0.0f : __expf(s[ni][0] - mn0);
            s[ni][1] = dead0 ? 0.0f : __expf(s[ni][1] - mn0);
            s[ni][2] = dead1 ? 0.0f : __expf(s[ni][2] - mn1);
            s[ni][3] = dead1 ? 0.0f : __expf(s[ni][3] - mn1);
            ps0 += s[ni][0] + s[ni][1];
            ps1 += s[ni][2] + s[ni][3];
        }
        ps0 += __shfl_xor_sync(0xffffffffu, ps0, 1);
        ps0 += __shfl_xor_sync(0xffffffffu, ps0, 2);
        ps1 += __shfl_xor_sync(0xffffffffu, ps1, 1);
        ps1 += __shfl_xor_sync(0xffffffffu, ps1, 2);

        l0 = l0 * alpha0 + ps0;
        l1 = l1 * alpha1 + ps1;
        m_run0 = mn0;
        m_run1 = mn1;

        #pragma unroll
        for (int ni = 0; ni < 8; ni++) {
            o_acc[ni][0] *= alpha0; o_acc[ni][1] *= alpha0;
            o_acc[ni][2] *= alpha1; o_acc[ni][3] *= alpha1;
        }

        // --- P . V (P fragments built in registers from s) ---
        #pragma unroll
        for (int j = 0; j < 8; j++) {
            uint32_t ah[4], al[4];
            float ra, rb;
            ah[0] = pack_hi(s[2 * j][0],     s[2 * j][1],     &ra, &rb); al[0] = pack_bf(ra, rb);
            ah[1] = pack_hi(s[2 * j][2],     s[2 * j][3],     &ra, &rb); al[1] = pack_bf(ra, rb);
            ah[2] = pack_hi(s[2 * j + 1][0], s[2 * j + 1][1], &ra, &rb); al[2] = pack_bf(ra, rb);
            ah[3] = pack_hi(s[2 * j + 1][2], s[2 * j + 1][3], &ra, &rb); al[3] = pack_bf(ra, rb);
            #pragma unroll
            for (int nf = 0; nf < 4; nf++) {
                uint32_t bh[4], bl[4];
                uint32_t off = (uint32_t)((j * 16 + v_row) * FA_STRIDE
                                          + (nf * 16) * 2 + v_cb);
                ldsm4t(bh, sVhh + off);
                ldsm4t(bl, sVll + off);
                #pragma unroll
                for (int o = 0; o < 2; o++) {
                    int ni = nf * 2 + o;
                    mma_bf16(o_acc[ni], ah, bh[o * 2], bh[o * 2 + 1]);
                    mma_bf16(o_acc[ni], ah, bl[o * 2], bl[o * 2 + 1]);
                    mma_bf16(o_acc[ni], al, bh[o * 2], bh[o * 2 + 1]);
                }
            }
        }
        __syncthreads();
    }

    // --- finalize: divide by l, write ctx as bf16 hi/lo ---
    float inv0 = (l0 > 0.0f) ? 1.0f / l0 : 0.0f;
    float inv1 = (l1 > 0.0f) ? 1.0f / l1 : 0.0f;
    size_t row0 = (size_t)n * LEN + r0;
    size_t row1 = (size_t)n * LEN + r1;
    #pragma unroll
    for (int ni = 0; ni < 8; ni++) {
        int col = h * DK + ni * 8 + tc;
        float ra, rb;
        uint32_t hv0 = pack_hi(o_acc[ni][0] * inv0, o_acc[ni][1] * inv0, &ra, &rb);
        uint32_t lv0 = pack_bf(ra, rb);
        *(uint32_t*)(Chi + row0 * DIM + col) = hv0;
        *(uint32_t*)(Clo + row0 * DIM + col) = lv0;
        uint32_t hv1 = pack_hi(o_acc[ni][2] * inv1, o_acc[ni][3] * inv1, &ra, &rb);
        uint32_t lv1 = pack_bf(ra, rb);
        *(uint32_t*)(Chi + row1 * DIM + col) = hv1;
        *(uint32_t*)(Clo + row1 * DIM + col) = lv1;
    }
}

// ---------------------------------------------------------------------------
// Elementwise fp32 -> bf16 hi/lo split
// ---------------------------------------------------------------------------
__global__ __launch_bounds__(256) void split_kernel(
    const float4* __restrict__ X, uint2* __restrict__ Hh, uint2* __restrict__ Ll, int n4)
{
    int i = blockIdx.x * 256 + threadIdx.x;
    if (i >= n4) return;
    float4 v = X[i];
    float r0, r1, r2, r3;
    uint32_t h0 = pack_hi(v.x, v.y, &r0, &r1);
    uint32_t h1 = pack_hi(v.z, v.w, &r2, &r3);
    Hh[i] = make_uint2(h0, h1);
    Ll[i] = make_uint2(pack_bf(r0, r1), pack_bf(r2, r3));
}

// ---------------------------------------------------------------------------
// Transposed split: W[Kr,Nc] fp32 -> TH/TL [Nc,Kr] bf16
// ---------------------------------------------------------------------------
__device__ __forceinline__ void tsplit_body(
    const float* __restrict__ W, __nv_bfloat16* __restrict__ TH,
    __nv_bfloat16* __restrict__ TL, int Kr, int Nc)
{
    __shared__ float t[32][33];
    int n0 = blockIdx.x * 32, k0 = blockIdx.y * 32;
    int tx = threadIdx.x, ty = threadIdx.y;     // 32 x 8
    #pragma unroll
    for (int i = 0; i < 4; i++)
        t[ty + i * 8][tx] = W[(size_t)(k0 + ty + i * 8) * Nc + n0 + tx];
    __syncthreads();
    #pragma unroll
    for (int i = 0; i < 4; i++) {
        int n = n0 + ty + i * 8;
        int k = k0 + tx;
        float v = t[tx][ty + i * 8];
        __nv_bfloat16 h = __float2bfloat16(v);
        TH[(size_t)n * Kr + k] = h;
        TL[(size_t)n * Kr + k] = __float2bfloat16(v - __bfloat162float(h));
    }
}

__global__ __launch_bounds__(256) void transpose_split_kernel(
    const float* __restrict__ W, __nv_bfloat16* __restrict__ TH,
    __nv_bfloat16* __restrict__ TL, int Kr, int Nc)
{
    tsplit_body(W, TH, TL, Kr, Nc);
}

// Combined QKV weight transpose (grid.z selects Q/K/V)
__global__ __launch_bounds__(256) void transpose_split_qkv_kernel(
    const float* __restrict__ WQ, const float* __restrict__ WK,
    const float* __restrict__ WV,
    __nv_bfloat16* __restrict__ TH, __nv_bfloat16* __restrict__ TL)
{
    int z = blockIdx.z;
    const float* W = (z == 0) ? WQ : (z == 1) ? WK : WV;
    tsplit_body(W, TH + (size_t)z * DIM * DIM, TL + (size_t)z * DIM * DIM, DIM, DIM);
}

__global__ __launch_bounds__(256) void concat_bias_kernel(
    const float* __restrict__ a, const float* __restrict__ b,
    const float* __restrict__ c, float* __restrict__ o)
{
    int i = blockIdx.x * 256 + threadIdx.x;
    if (i < 1024) o[i] = a[i];
    else if (i < 2048) o[i] = b[i - 1024];
    else if (i < 3072) o[i] = c[i - 2048];
}

// ---------------------------------------------------------------------------
// LayerNorm over last dim (1024); optional bf16 hi/lo split output
// ---------------------------------------------------------------------------
__global__ __launch_bounds__(256) void layernorm_kernel(
    const float* __restrict__ X, const float* __restrict__ gg,
    const float* __restrict__ bb, float* __restrict__ Y,
    __nv_bfloat16* __restrict__ Yhi, __nv_bfloat16* __restrict__ Ylo)
{
    int row = blockIdx.x;
    int tid = threadIdx.x;
    const float4* Xp = (const float4*)(X + (size_t)row * DIM);
    float4 x = Xp[tid];
    __shared__ float red[8];

    float s = x.x + x.y + x.z + x.w;
    #pragma unroll
    for (int o = 16; o; o >>= 1) s += __shfl_xor_sync(0xffffffffu, s, o);
    if ((tid & 31) == 0) red[tid >> 5] = s;
    __syncthreads();
    float mean = (red[0] + red[1] + red[2] + red[3] +
                  red[4] + red[5] + red[6] + red[7]) * (1.0f / DIM);

    float d0 = x.x - mean, d1 = x.y - mean, d2 = x.z - mean, d3 = x.w - mean;
    float s2 = d0 * d0 + d1 * d1 + d2 * d2 + d3 * d3;
    __syncthreads();
    #pragma unroll
    for (int o = 16; o; o >>= 1) s2 += __shfl_xor_sync(0xffffffffu, s2, o);
    if ((tid & 31) == 0) red[tid >> 5] = s2;
    __syncthreads();
    float var = (red[0] + red[1] + red[2] + red[3] +
                 red[4] + red[5] + red[6] + red[7]) * (1.0f / DIM);
    float rs = rsqrtf(var + 1e-5f);

    float4 gv = ((const float4*)gg)[tid];
    float4 bv = ((const float4*)bb)[tid];
    float4 y;
    y.x = d0 * rs * gv.x + bv.x;
    y.y = d1 * rs * gv.y + bv.y;
    y.z = d2 * rs * gv.z + bv.z;
    y.w = d3 * rs * gv.w + bv.w;
    ((float4*)(Y + (size_t)row * DIM))[tid] = y;
    if (Yhi) {
        size_t base = (size_t)row * DIM + tid * 4;
        float r0, r1, r2, r3;
        uint32_t h0 = pack_hi(y.x, y.y, &r0, &r1);
        uint32_t h1 = pack_hi(y.z, y.w, &r2, &r3);
        *(uint2*)(Yhi + base) = make_uint2(h0, h1);
        *(uint2*)(Ylo + base) = make_uint2(pack_bf(r0, r1), pack_bf(r2, r3));
    }
}

// ---------------------------------------------------------------------------
// Launcher
// ---------------------------------------------------------------------------
extern "C" void kernel_launch(void* const* d_in, const int* in_sizes, int n_in,
                              void* d_out, int out_size)
{
    const float*         x    = (const float*)d_in[0];
    const unsigned char* mask = (const unsigned char*)d_in[1];
    const float* WQ = (const float*)d_in[2];
    const float* bQ = (const float*)d_in[3];
    const float* WK = (const float*)d_in[4];
    const float* bK = (const float*)d_in[5];
    const float* WV = (const float*)d_in[6];
    const float* bV = (const float*)d_in[7];
    const float* WO = (const float*)d_in[8];
    const float* bO = (const float*)d_in[9];
    const float* g0 = (const float*)d_in[10];
    const float* b0 = (const float*)d_in[11];
    const float* W1 = (const float*)d_in[12];
    const float* b1 = (const float*)d_in[13];
    const float* W2 = (const float*)d_in[14];
    const float* b2 = (const float*)d_in[15];
    const float* g1 = (const float*)d_in[16];
    const float* b1n = (const float*)d_in[17];
    float* out = (float*)d_out;

    float* base = nullptr;
    cudaGetSymbolAddress((void**)&base, g_scratch);
    float* T0  = base + OFF_T0;
    float* Hf  = base + OFF_H;
    float* T1  = base + OFF_T1;
    float* bqkv = base + OFF_BQKV;
    __nv_bfloat16* QKVH  = (__nv_bfloat16*)(base + OFF_QKVH);
    __nv_bfloat16* QKVL  = (__nv_bfloat16*)(base + OFF_QKVL);
    __nv_bfloat16* XH  = (__nv_bfloat16*)(base + OFF_XH);
    __nv_bfloat16* XL  = (__nv_bfloat16*)(base + OFF_XL);
    __nv_bfloat16* WQKVH = (__nv_bfloat16*)(base + OFF_WQKVH);
    __nv_bfloat16* WQKVL = (__nv_bfloat16*)(base + OFF_WQKVL);
    __nv_bfloat16* WOH = (__nv_bfloat16*)(base + OFF_WOH);
    __nv_bfloat16* WOL = (__nv_bfloat16*)(base + OFF_WOL);
    __nv_bfloat16* W1H = (__nv_bfloat16*)(base + OFF_W1H);
    __nv_bfloat16* W1L = (__nv_bfloat16*)(base + OFF_W1L);
    __nv_bfloat16* W2H = (__nv_bfloat16*)(base + OFF_W2H);
    __nv_bfloat16* W2L = (__nv_bfloat16*)(base + OFF_W2L);
    __nv_bfloat16* CH  = (__nv_bfloat16*)(base + OFF_CH);
    __nv_bfloat16* CL  = (__nv_bfloat16*)(base + OFF_CL);
    __nv_bfloat16* HH  = (__nv_bfloat16*)(base + OFF_HH);
    __nv_bfloat16* HL  = (__nv_bfloat16*)(base + OFF_HL);
    __nv_bfloat16* FH  = (__nv_bfloat16*)(base + OFF_FH);
    __nv_bfloat16* FL  = (__nv_bfloat16*)(base + OFF_FL);

    cudaFuncSetAttribute(gemm_mma_kernel,
                         cudaFuncAttributeMaxDynamicSharedMemorySize, G_SMEM_DYN);
    cudaFuncSetAttribute(flash_attn_kernel,
                         cudaFuncAttributeMaxDynamicSharedMemorySize, FA_SMEM);

    dim3 tb(32, 8);

    // 0: split x   1: combined QKV weight transpose   2: bias concat
    split_kernel<<<(TOK * DIM / 4 + 255) / 256, 256>>>(
        (const float4*)x, (uint2*)XH, (uint2*)XL, TOK * DIM / 4);
    transpose_split_qkv_kernel<<<dim3(DIM / 32, DIM / 32, 3), tb>>>(
        WQ, WK, WV, WQKVH, WQKVL);
    concat_bias_kernel<<<12, 256>>>(bQ, bK, bV, bqkv);

    // 3: fused QKV GEMM -> bf16 hi/lo  (targeted ncu slot)
    gemm_mma_kernel<<<dim3(QKVS / 128, TOK / 128), 512, G_SMEM_DYN>>>(
        XH, XL, WQKVH, WQKVL, bqkv, nullptr,
        nullptr, QKVH, QKVL, TOK, QKVS, DIM, 0);

    // 4: fused flash attention -> ctx bf16 hi/lo
    flash_attn_kernel<<<dim3(LEN / 128, NB * HEADS), 256, FA_SMEM>>>(
        QKVH, QKVL, mask, CH, CL);

    // 5-7: remaining weight transposes
    transpose_split_kernel<<<dim3(DIM / 32, DIM / 32), tb>>>(WO, WOH, WOL, DIM, DIM);
    transpose_split_kernel<<<dim3(FF / 32, DIM / 32), tb>>>(W1, W1H, W1L, DIM, FF);
    transpose_split_kernel<<<dim3(DIM / 32, FF / 32), tb>>>(W2, W2H, W2L, FF, DIM);

    dim3 gD(DIM / 128, TOK / 128);
    dim3 gF(FF / 128, TOK / 128);

    // 8: O projection + residual(x);  9: layernorm0 (emits split for FFN1)
    gemm_mma_kernel<<<gD, 512, G_SMEM_DYN>>>(CH, CL, WOH, WOL, bO, x,
                                             T0, nullptr, nullptr, TOK, DIM, DIM, 0);
    layernorm_kernel<<<TOK, 256>>>(T0, g0, b0, Hf, HH, HL);

    // 10-11: FFN
    gemm_mma_kernel<<<gF, 512, G_SMEM_DYN>>>(HH, HL, W1H, W1L, b1, nullptr,
                                             nullptr, FH, FL, TOK, FF, DIM, 1);
    gemm_mma_kernel<<<gD, 512, G_SMEM_DYN>>>(FH, FL, W2H, W2L, b2, Hf,
                                             T1, nullptr, nullptr, TOK, DIM, FF, 0);

    // 12: final layernorm -> output
    layernorm_kernel<<<TOK, 256>>>(T1, g1, b1n, out, nullptr, nullptr);
}

// round 8
// speedup vs baseline: 2.7491x; 1.1065x over previous
#include <cuda_runtime.h>
#include <cuda_bf16.h>
#include <math.h>
#include <stdint.h>

// Problem constants
#define NB    16
#define LEN   512
#define DIM   1024
#define HEADS 16
#define DK    64
#define FF    4096
#define TOK   (NB * LEN)          // 8192 rows
#define QKVS  3072                // fused QKV row stride

// ---------------------------------------------------------------------------
// Scratch layout (units: floats)
// ---------------------------------------------------------------------------
#define MFe ((size_t)1 << 20)
#define OFF_QKVH  (0 * MFe)           // bf16 8192x3072
#define OFF_QKVL  (12 * MFe)
#define OFF_T0    (24 * MFe)          // fp32 8192x1024
#define OFF_H     (32 * MFe)
#define OFF_T1    (40 * MFe)
#define OFF_XH    (48 * MFe)          // bf16 8192x1024
#define OFF_XL    (52 * MFe)
#define OFF_WQKVH (56 * MFe)          // bf16 3072x1024
#define OFF_WQKVL (58 * MFe)
#define OFF_WOH   (60 * MFe)          // bf16 1024x1024 (0.5 MFe)
#define OFF_WOL   (OFF_WOH + MFe / 2)
#define OFF_W1H   (61 * MFe)          // bf16 4096x1024
#define OFF_W1L   (63 * MFe)
#define OFF_W2H   (65 * MFe)          // bf16 1024x4096
#define OFF_W2L   (67 * MFe)
#define OFF_CH    (69 * MFe)          // bf16 8192x1024
#define OFF_CL    (73 * MFe)
#define OFF_HH    (77 * MFe)
#define OFF_HL    (81 * MFe)
#define OFF_FH    (85 * MFe)          // bf16 8192x4096
#define OFF_FL    (101 * MFe)
#define OFF_BQKV  (117 * MFe)         // fp32 3072
#define SCRATCH_FLOATS (118 * MFe)

__device__ float g_scratch[SCRATCH_FLOATS];

// ---------------------------------------------------------------------------
// PTX helpers (sm_80-baseline: cp.async, ldmatrix, mma.sync)
// ---------------------------------------------------------------------------
__device__ __forceinline__ uint32_t s2u(const void* p) {
    uint32_t r;
    asm("{ .reg .u64 t; cvta.to.shared.u64 t, %1; cvt.u32.u64 %0, t; }"
        : "=r"(r) : "l"(p));
    return r;
}

__device__ __forceinline__ void cp16(uint32_t dst, const void* src) {
    asm volatile("cp.async.cg.shared.global [%0], [%1], 16;" :: "r"(dst), "l"(src));
}
__device__ __forceinline__ void cp_commit() {
    asm volatile("cp.async.commit_group;" ::: "memory");
}
template <int N> __device__ __forceinline__ void cp_wait() {
    asm volatile("cp.async.wait_group %0;" :: "n"(N) : "memory");
}

__device__ __forceinline__ void ldsm4(uint32_t* r, uint32_t addr) {
    asm volatile("ldmatrix.sync.aligned.m8n8.x4.shared.b16 {%0,%1,%2,%3}, [%4];"
                 : "=r"(r[0]), "=r"(r[1]), "=r"(r[2]), "=r"(r[3]) : "r"(addr));
}
__device__ __forceinline__ void ldsm4t(uint32_t* r, uint32_t addr) {
    asm volatile("ldmatrix.sync.aligned.m8n8.x4.trans.shared.b16 {%0,%1,%2,%3}, [%4];"
                 : "=r"(r[0]), "=r"(r[1]), "=r"(r[2]), "=r"(r[3]) : "r"(addr));
}

__device__ __forceinline__ void mma_bf16(float* d, const uint32_t* a,
                                         uint32_t b0, uint32_t b1) {
    asm volatile(
        "mma.sync.aligned.m16n8k16.row.col.f32.bf16.bf16.f32 "
        "{%0,%1,%2,%3}, {%4,%5,%6,%7}, {%8,%9}, {%0,%1,%2,%3};"
        : "+f"(d[0]), "+f"(d[1]), "+f"(d[2]), "+f"(d[3])
        : "r"(a[0]), "r"(a[1]), "r"(a[2]), "r"(a[3]), "r"(b0), "r"(b1));
}

__device__ __forceinline__ float gelu_exact(float v) {
    return 0.5f * v * (1.0f + erff(v * 0.70710678118654752f));
}

__device__ __forceinline__ uint32_t pack_hi(float a, float b, float* ra, float* rb) {
    __nv_bfloat16 ha = __float2bfloat16(a);
    __nv_bfloat16 hb = __float2bfloat16(b);
    *ra = a - __bfloat162float(ha);
    *rb = b - __bfloat162float(hb);
    return (uint32_t)__bfloat16_as_ushort(ha) |
           ((uint32_t)__bfloat16_as_ushort(hb) << 16);
}
__device__ __forceinline__ uint32_t pack_bf(float a, float b) {
    __nv_bfloat16 ha = __float2bfloat16(a);
    __nv_bfloat16 hb = __float2bfloat16(b);
    return (uint32_t)__bfloat16_as_ushort(ha) |
           ((uint32_t)__bfloat16_as_ushort(hb) << 16);
}

// ---------------------------------------------------------------------------
// bf16-split GEMM via mma.sync: 256 threads, 2-stage, 2 CTAs/SM.
// CTA tile 128x128, BK=32, 8 warps (64x32 each).
// ---------------------------------------------------------------------------
#define G_STAGES 2
#define SA_STRIDE 40                          // bf16 units per smem row (80 B)
#define G_TILE_B (128 * SA_STRIDE * 2)        // 10240 B per 128x32 tile
#define G_STAGE_B (4 * G_TILE_B)              // 40960 B
#define G_SMEM_DYN (G_STAGES * G_STAGE_B)     // 81920 B

__device__ __forceinline__ void load_tile256(uint32_t sbase, const __nv_bfloat16* g,
                                             int K, int k0, int tid) {
    #pragma unroll
    for (int i = 0; i < 2; i++) {
        int c = tid + i * 256;                // 0..511 : 128 rows x 4 chunks
        int row = c >> 2;
        int col = c & 3;
        cp16(sbase + (uint32_t)(row * (SA_STRIDE * 2) + col * 16),
             g + (size_t)row * K + k0 + col * 8);
    }
}

extern __shared__ char g_dsm[];

__global__ void __launch_bounds__(256, 2) gemm_mma_kernel(
    const __nv_bfloat16* __restrict__ Ahi, const __nv_bfloat16* __restrict__ Alo,
    const __nv_bfloat16* __restrict__ Bhi, const __nv_bfloat16* __restrict__ Blo,
    const float* __restrict__ bias, const float* __restrict__ resid,
    float* __restrict__ outF,
    __nv_bfloat16* __restrict__ outHi, __nv_bfloat16* __restrict__ outLo,
    int M, int N, int K, int gelu)
{
    const int tid = threadIdx.x;
    const int wid = tid >> 5;
    const int lane = tid & 31;
    const int wr = wid >> 2;       // warp row 0-1 (64 rows each)
    const int wc = wid & 3;        // warp col 0-3 (32 cols each)
    const int bm = blockIdx.y * 128;
    const int bn = blockIdx.x * 128;

    uint32_t db = s2u(g_dsm);

    const __nv_bfloat16* Ah = Ahi + (size_t)bm * K;
    const __nv_bfloat16* Al = Alo + (size_t)bm * K;
    const __nv_bfloat16* Bh = Bhi + (size_t)bn * K;
    const __nv_bfloat16* Bl = Blo + (size_t)bn * K;

    float acc[4][4][4] = {};

    const int nk = K / 32;

    // Prologue: stage 0
    {
        uint32_t sb = db;
        load_tile256(sb + 0 * G_TILE_B, Ah, K, 0, tid);
        load_tile256(sb + 1 * G_TILE_B, Al, K, 0, tid);
        load_tile256(sb + 2 * G_TILE_B, Bh, K, 0, tid);
        load_tile256(sb + 3 * G_TILE_B, Bl, K, 0, tid);
        cp_commit();
    }

    const int a_row = (lane & 15);
    const int a_ko  = (lane >> 4) * 8;
    const int b_row = ((lane >> 4) * 8) + (lane & 7);
    const int b_ko  = ((lane >> 3) & 1) * 8;

    for (int kt = 0; kt < nk; kt++) {
        // All committed groups (== stage kt's loads) must be complete.
        cp_wait<0>();
        __syncthreads();

        // Prefetch kt+1 into the buffer freed by kt-1; overlaps compute of kt.
        if (kt + 1 < nk) {
            uint32_t nb = db + (uint32_t)((kt + 1) & 1) * G_STAGE_B;
            int k0 = (kt + 1) * 32;
            load_tile256(nb + 0 * G_TILE_B, Ah, K, k0, tid);
            load_tile256(nb + 1 * G_TILE_B, Al, K, k0, tid);
            load_tile256(nb + 2 * G_TILE_B, Bh, K, k0, tid);
            load_tile256(nb + 3 * G_TILE_B, Bl, K, k0, tid);
            cp_commit();
        }

        uint32_t sb = db + (uint32_t)(kt & 1) * G_STAGE_B;
        uint32_t sAh = sb + 0 * G_TILE_B;
        uint32_t sAl = sb + 1 * G_TILE_B;
        uint32_t sBh = sb + 2 * G_TILE_B;
        uint32_t sBl = sb + 3 * G_TILE_B;

        #pragma unroll
        for (int k16 = 0; k16 < 2; k16++) {
            uint32_t ah[4][4], al[4][4], bh[2][4], bl[2][4];
            #pragma unroll
            for (int mi = 0; mi < 4; mi++) {
                uint32_t off = (uint32_t)((wr * 64 + mi * 16 + a_row) * (SA_STRIDE * 2)
                                          + (k16 * 16 + a_ko) * 2);
                ldsm4(ah[mi], sAh + off);
                ldsm4(al[mi], sAl + off);
            }
            #pragma unroll
            for (int nf = 0; nf < 2; nf++) {
                uint32_t off = (uint32_t)((wc * 32 + nf * 16 + b_row) * (SA_STRIDE * 2)
                                          + (k16 * 16 + b_ko) * 2);
                ldsm4(bh[nf], sBh + off);
                ldsm4(bl[nf], sBl + off);
            }
            #pragma unroll
            for (int mi = 0; mi < 4; mi++) {
                #pragma unroll
                for (int ni = 0; ni < 4; ni++) {
                    int nf = ni >> 1, o = (ni & 1) * 2;
                    mma_bf16(acc[mi][ni], ah[mi], bh[nf][o], bh[nf][o + 1]);
                    mma_bf16(acc[mi][ni], ah[mi], bl[nf][o], bl[nf][o + 1]);
                    mma_bf16(acc[mi][ni], al[mi], bh[nf][o], bh[nf][o + 1]);
                }
            }
        }
    }

    // Epilogue
    const int tq = lane >> 2;
    const int tc = (lane & 3) * 2;
    #pragma unroll
    for (int mi = 0; mi < 4; mi++) {
        #pragma unroll
        for (int ni = 0; ni < 4; ni++) {
            int col = bn + wc * 32 + ni * 8 + tc;
            float bx = bias[col], by = bias[col + 1];
            #pragma unroll
            for (int half = 0; half < 2; half++) {
                int row = bm + wr * 64 + mi * 16 + tq + half * 8;
                float v0 = acc[mi][ni][half * 2 + 0] + bx;
                float v1 = acc[mi][ni][half * 2 + 1] + by;
                if (gelu) { v0 = gelu_exact(v0); v1 = gelu_exact(v1); }
                if (resid) {
                    float2 rv = *(const float2*)(resid + (size_t)row * N + col);
                    v0 += rv.x; v1 += rv.y;
                }
                if (outF)
                    *(float2*)(outF + (size_t)row * N + col) = make_float2(v0, v1);
                if (outHi) {
                    float ra, rb;
                    uint32_t hv = pack_hi(v0, v1, &ra, &rb);
                    *(uint32_t*)(outHi + (size_t)row * N + col) = hv;
                    *(uint32_t*)(outLo + (size_t)row * N + col) = pack_bf(ra, rb);
                }
            }
        }
    }
}

// ---------------------------------------------------------------------------
// Fused flash attention: scores + online softmax + P.V in one kernel.
// Grid (LEN/128, NB*HEADS); 256 threads (8 warps, 16 q-rows each).
// KV processed in 4 chunks of 128, double-buffered cp.async.
// ---------------------------------------------------------------------------
#define FA_STRIDE 144                          // bytes per smem row (64 bf16 + pad)
#define FA_TILE (128 * FA_STRIDE)              // 18432
#define FA_QBASE 0
#define FA_KVBASE (2 * FA_TILE)                // after Qh,Ql
#define FA_BUF_B (4 * FA_TILE)                 // Kh,Kl,Vh,Vl per buffer
#define FA_SMEM (2 * FA_TILE + 2 * FA_BUF_B)   // 184320

__global__ void __launch_bounds__(256, 1) flash_attn_kernel(
    const __nv_bfloat16* __restrict__ QKVH, const __nv_bfloat16* __restrict__ QKVL,
    const unsigned char* __restrict__ mask,
    __nv_bfloat16* __restrict__ Chi, __nv_bfloat16* __restrict__ Clo)
{
    const int tid = threadIdx.x;
    const int wid = tid >> 5;
    const int lane = tid & 31;
    const int b = blockIdx.y;
    const int n = b >> 4;
    const int h = b & 15;
    const int q0 = blockIdx.x * 128;

    uint32_t db = s2u(g_dsm);
    uint32_t sQh = db + FA_QBASE, sQl = sQh + FA_TILE;

    const __nv_bfloat16* Qh = QKVH + (size_t)n * LEN * QKVS + h * DK;
    const __nv_bfloat16* Ql = QKVL + (size_t)n * LEN * QKVS + h * DK;
    const __nv_bfloat16* Kh = QKVH + (size_t)n * LEN * QKVS + DIM + h * DK;
    const __nv_bfloat16* Kl = QKVL + (size_t)n * LEN * QKVS + DIM + h * DK;
    const __nv_bfloat16* Vh = QKVH + (size_t)n * LEN * QKVS + 2 * DIM + h * DK;
    const __nv_bfloat16* Vl = QKVL + (size_t)n * LEN * QKVS + 2 * DIM + h * DK;

    #pragma unroll
    for (int i = 0; i < 4; i++) {
        int c = tid + i * 256;
        int row = c >> 3;
        int col = c & 7;
        uint32_t doff = (uint32_t)(row * FA_STRIDE + col * 16);
        cp16(sQh + doff, Qh + (size_t)(q0 + row) * QKVS + col * 8);
        cp16(sQl + doff, Ql + (size_t)(q0 + row) * QKVS + col * 8);
    }
    auto load_kv = [&](int chunk) {
        uint32_t sb = db + FA_KVBASE + (uint32_t)(chunk & 1) * FA_BUF_B;
        #pragma unroll
        for (int i = 0; i < 4; i++) {
            int c = tid + i * 256;
            int row = c >> 3;
            int col = c & 7;
            uint32_t doff = (uint32_t)(row * FA_STRIDE + col * 16);
            size_t goff = (size_t)(chunk * 128 + row) * QKVS + col * 8;
            cp16(sb + doff, Kh + goff);
            cp16(sb + FA_TILE + doff, Kl + goff);
            cp16(sb + 2 * FA_TILE + doff, Vh + goff);
            cp16(sb + 3 * FA_TILE + doff, Vl + goff);
        }
    };
    load_kv(0);
    cp_commit();

    const int a_row = (lane & 15);
    const int a_ko  = (lane >> 4) * 8;
    const int b_row = ((lane >> 4) * 8) + (lane & 7);
    const int b_ko  = ((lane >> 3) & 1) * 8;
    const int v_row = (lane & 7) + ((lane >> 3) & 1) * 8;
    const int v_cb  = (lane >> 4) * 16;
    const int tq = lane >> 2;
    const int tc = (lane & 3) * 2;

    const int r0 = q0 + wid * 16 + tq;
    const int r1 = r0 + 8;
    const unsigned char* mp = mask + (size_t)n * LEN * LEN;

    uint32_t qh[4][4], ql[4][4];
    float o_acc[8][4] = {};
    float m_run0 = -INFINITY, m_run1 = -INFINITY;
    float l0 = 0.0f, l1 = 0.0f;

    for (int c = 0; c < 4; c++) {
        if (c + 1 < 4) load_kv(c + 1);
        cp_commit();
        cp_wait<1>();
        __syncthreads();

        if (c == 0) {
            #pragma unroll
            for (int k16 = 0; k16 < 4; k16++) {
                uint32_t off = (uint32_t)((wid * 16 + a_row) * FA_STRIDE
                                          + (k16 * 16 + a_ko) * 2);
                ldsm4(qh[k16], sQh + off);
                ldsm4(ql[k16], sQl + off);
            }
        }

        uint32_t sb = db + FA_KVBASE + (uint32_t)(c & 1) * FA_BUF_B;
        uint32_t sKhh = sb, sKll = sb + FA_TILE;
        uint32_t sVhh = sb + 2 * FA_TILE, sVll = sb + 3 * FA_TILE;

        float s[16][4] = {};
        #pragma unroll
        for (int k16 = 0; k16 < 4; k16++) {
            #pragma unroll
            for (int nf = 0; nf < 8; nf++) {
                uint32_t bh[4], bl[4];
                uint32_t off = (uint32_t)((nf * 16 + b_row) * FA_STRIDE
                                          + (k16 * 16 + b_ko) * 2);
                ldsm4(bh, sKhh + off);
                ldsm4(bl, sKll + off);
                #pragma unroll
                for (int o = 0; o < 2; o++) {
                    int ni = nf * 2 + o;
                    mma_bf16(s[ni], qh[k16], bh[o * 2], bh[o * 2 + 1]);
                    mma_bf16(s[ni], qh[k16], bl[o * 2], bl[o * 2 + 1]);
                    mma_bf16(s[ni], ql[k16], bh[o * 2], bh[o * 2 + 1]);
                }
            }
        }

        const unsigned char* mr0 = mp + (size_t)r0 * LEN + c * 128 + tc;
        const unsigned char* mr1 = mp + (size_t)r1 * LEN + c * 128 + tc;
        #pragma unroll
        for (int ni = 0; ni < 16; ni++) {
            uchar2 m0v = *(const uchar2*)(mr0 + ni * 8);
            uchar2 m1v = *(const uchar2*)(mr1 + ni * 8);
            s[ni][0] = m0v.x ? -INFINITY : s[ni][0] * 0.125f;
            s[ni][1] = m0v.y ? -INFINITY : s[ni][1] * 0.125f;
            s[ni][2] = m1v.x ? -INFINITY : s[ni][2] * 0.125f;
            s[ni][3] = m1v.y ? -INFINITY : s[ni][3] * 0.125f;
        }

        float rm0 = -INFINITY, rm1 = -INFINITY;
        #pragma unroll
        for (int ni = 0; ni < 16; ni++) {
            rm0 = fmaxf(rm0, fmaxf(s[ni][0], s[ni][1]));
            rm1 = fmaxf(rm1, fmaxf(s[ni][2], s[ni][3]));
        }
        rm0 = fmaxf(rm0, __shfl_xor_sync(0xffffffffu, rm0, 1));
        rm0 = fmaxf(rm0, __shfl_xor_sync(0xffffffffu, rm0, 2));
        rm1 = fmaxf(rm1, __shfl_xor_sync(0xffffffffu, rm1, 1));
        rm1 = fmaxf(rm1, __shfl_xor_sync(0xffffffffu, rm1, 2));

        float mn0 = fmaxf(m_run0, rm0);
        float mn1 = fmaxf(m_run1, rm1);
        bool dead0 = (mn0 == -INFINITY);
        bool dead1 = (mn1 == -INFINITY);
        float alpha0 = dead0 ? 1.0f : __expf(m_run0 - mn0);
        float alpha1 = dead1 ? 1.0f : __expf(m_run1 - mn1);

        float ps0 = 0.0f, ps1 = 0.0f;
        #pragma unroll
        for (int ni = 0; ni < 16; ni++) {
            s[ni][0] = dead0 ? 0.0f : __expf(s[ni][0] - mn0);
            s[ni][1] = dead0 ? 0.0f : __expf(s[ni][1] - mn0);
            s[ni][2] = dead1 ? 0.0f : __expf(s[ni][2] - mn1);
            s[ni][3] = dead1 ? 0.0f : __expf(s[ni][3] - mn1);
            ps0 += s[ni][0] + s[ni][1];
            ps1 += s[ni][2] + s[ni][3];
        }
        ps0 += __shfl_xor_sync(0xffffffffu, ps0, 1);
        ps0 += __shfl_xor_sync(0xffffffffu, ps0, 2);
        ps1 += __shfl_xor_sync(0xffffffffu, ps1, 1);
        ps1 += __shfl_xor_sync(0xffffffffu, ps1, 2);

        l0 = l0 * alpha0 + ps0;
        l1 = l1 * alpha1 + ps1;
        m_run0 = mn0;
        m_run1 = mn1;

        #pragma unroll
        for (int ni = 0; ni < 8; ni++) {
            o_acc[ni][0] *= alpha0; o_acc[ni][1] *= alpha0;
            o_acc[ni][2] *= alpha1; o_acc[ni][3] *= alpha1;
        }

        #pragma unroll
        for (int j = 0; j < 8; j++) {
            uint32_t ah[4], al[4];
            float ra, rb;
            ah[0] = pack_hi(s[2 * j][0],     s[2 * j][1],     &ra, &rb); al[0] = pack_bf(ra, rb);
            ah[1] = pack_hi(s[2 * j][2],     s[2 * j][3],     &ra, &rb); al[1] = pack_bf(ra, rb);
            ah[2] = pack_hi(s[2 * j + 1][0], s[2 * j + 1][1], &ra, &rb); al[2] = pack_bf(ra, rb);
            ah[3] = pack_hi(s[2 * j + 1][2], s[2 * j + 1][3], &ra, &rb); al[3] = pack_bf(ra, rb);
            #pragma unroll
            for (int nf = 0; nf < 4; nf++) {
                uint32_t bh[4], bl[4];
                uint32_t off = (uint32_t)((j * 16 + v_row) * FA_STRIDE
                                          + (nf * 16) * 2 + v_cb);
                ldsm4t(bh, sVhh + off);
                ldsm4t(bl, sVll + off);
                #pragma unroll
                for (int o = 0; o < 2; o++) {
                    int ni = nf * 2 + o;
                    mma_bf16(o_acc[ni], ah, bh[o * 2], bh[o * 2 + 1]);
                    mma_bf16(o_acc[ni], ah, bl[o * 2], bl[o * 2 + 1]);
                    mma_bf16(o_acc[ni], al, bh[o * 2], bh[o * 2 + 1]);
                }
            }
        }
        __syncthreads();
    }

    float inv0 = (l0 > 0.0f) ? 1.0f / l0 : 0.0f;
    float inv1 = (l1 > 0.0f) ? 1.0f / l1 : 0.0f;
    size_t row0 = (size_t)n * LEN + r0;
    size_t row1 = (size_t)n * LEN + r1;
    #pragma unroll
    for (int ni = 0; ni < 8; ni++) {
        int col = h * DK + ni * 8 + tc;
        float ra, rb;
        uint32_t hv0 = pack_hi(o_acc[ni][0] * inv0, o_acc[ni][1] * inv0, &ra, &rb);
        uint32_t lv0 = pack_bf(ra, rb);
        *(uint32_t*)(Chi + row0 * DIM + col) = hv0;
        *(uint32_t*)(Clo + row0 * DIM + col) = lv0;
        uint32_t hv1 = pack_hi(o_acc[ni][2] * inv1, o_acc[ni][3] * inv1, &ra, &rb);
        uint32_t lv1 = pack_bf(ra, rb);
        *(uint32_t*)(Chi + row1 * DIM + col) = hv1;
        *(uint32_t*)(Clo + row1 * DIM + col) = lv1;
    }
}

// ---------------------------------------------------------------------------
// Elementwise fp32 -> bf16 hi/lo split
// ---------------------------------------------------------------------------
__global__ __launch_bounds__(256) void split_kernel(
    const float4* __restrict__ X, uint2* __restrict__ Hh, uint2* __restrict__ Ll, int n4)
{
    int i = blockIdx.x * 256 + threadIdx.x;
    if (i >= n4) return;
    float4 v = X[i];
    float r0, r1, r2, r3;
    uint32_t h0 = pack_hi(v.x, v.y, &r0, &r1);
    uint32_t h1 = pack_hi(v.z, v.w, &r2, &r3);
    Hh[i] = make_uint2(h0, h1);
    Ll[i] = make_uint2(pack_bf(r0, r1), pack_bf(r2, r3));
}

// ---------------------------------------------------------------------------
// Transposed split: W[Kr,Nc] fp32 -> TH/TL [Nc,Kr] bf16
// ---------------------------------------------------------------------------
__device__ __forceinline__ void tsplit_body(
    const float* __restrict__ W, __nv_bfloat16* __restrict__ TH,
    __nv_bfloat16* __restrict__ TL, int Kr, int Nc)
{
    __shared__ float t[32][33];
    int n0 = blockIdx.x * 32, k0 = blockIdx.y * 32;
    int tx = threadIdx.x, ty = threadIdx.y;     // 32 x 8
    #pragma unroll
    for (int i = 0; i < 4; i++)
        t[ty + i * 8][tx] = W[(size_t)(k0 + ty + i * 8) * Nc + n0 + tx];
    __syncthreads();
    #pragma unroll
    for (int i = 0; i < 4; i++) {
        int n = n0 + ty + i * 8;
        int k = k0 + tx;
        float v = t[tx][ty + i * 8];
        __nv_bfloat16 h = __float2bfloat16(v);
        TH[(size_t)n * Kr + k] = h;
        TL[(size_t)n * Kr + k] = __float2bfloat16(v - __bfloat162float(h));
    }
}

__global__ __launch_bounds__(256) void transpose_split_kernel(
    const float* __restrict__ W, __nv_bfloat16* __restrict__ TH,
    __nv_bfloat16* __restrict__ TL, int Kr, int Nc)
{
    tsplit_body(W, TH, TL, Kr, Nc);
}

__global__ __launch_bounds__(256) void transpose_split_qkv_kernel(
    const float* __restrict__ WQ, const float* __restrict__ WK,
    const float* __restrict__ WV,
    __nv_bfloat16* __restrict__ TH, __nv_bfloat16* __restrict__ TL)
{
    int z = blockIdx.z;
    const float* W = (z == 0) ? WQ : (z == 1) ? WK : WV;
    tsplit_body(W, TH + (size_t)z * DIM * DIM, TL + (size_t)z * DIM * DIM, DIM, DIM);
}

__global__ __launch_bounds__(256) void concat_bias_kernel(
    const float* __restrict__ a, const float* __restrict__ b,
    const float* __restrict__ c, float* __restrict__ o)
{
    int i = blockIdx.x * 256 + threadIdx.x;
    if (i < 1024) o[i] = a[i];
    else if (i < 2048) o[i] = b[i - 1024];
    else if (i < 3072) o[i] = c[i - 2048];
}

// ---------------------------------------------------------------------------
// LayerNorm over last dim (1024); optional bf16 hi/lo split output
// ---------------------------------------------------------------------------
__global__ __launch_bounds__(256) void layernorm_kernel(
    const float* __restrict__ X, const float* __restrict__ gg,
    const float* __restrict__ bb, float* __restrict__ Y,
    __nv_bfloat16* __restrict__ Yhi, __nv_bfloat16* __restrict__ Ylo)
{
    int row = blockIdx.x;
    int tid = threadIdx.x;
    const float4* Xp = (const float4*)(X + (size_t)row * DIM);
    float4 x = Xp[tid];
    __shared__ float red[8];

    float s = x.x + x.y + x.z + x.w;
    #pragma unroll
    for (int o = 16; o; o >>= 1) s += __shfl_xor_sync(0xffffffffu, s, o);
    if ((tid & 31) == 0) red[tid >> 5] = s;
    __syncthreads();
    float mean = (red[0] + red[1] + red[2] + red[3] +
                  red[4] + red[5] + red[6] + red[7]) * (1.0f / DIM);

    float d0 = x.x - mean, d1 = x.y - mean, d2 = x.z - mean, d3 = x.w - mean;
    float s2 = d0 * d0 + d1 * d1 + d2 * d2 + d3 * d3;
    __syncthreads();
    #pragma unroll
    for (int o = 16; o; o >>= 1) s2 += __shfl_xor_sync(0xffffffffu, s2, o);
    if ((tid & 31) == 0) red[tid >> 5] = s2;
    __syncthreads();
    float var = (red[0] + red[1] + red[2] + red[3] +
                 red[4] + red[5] + red[6] + red[7]) * (1.0f / DIM);
    float rs = rsqrtf(var + 1e-5f);

    float4 gv = ((const float4*)gg)[tid];
    float4 bv = ((const float4*)bb)[tid];
    float4 y;
    y.x = d0 * rs * gv.x + bv.x;
    y.y = d1 * rs * gv.y + bv.y;
    y.z = d2 * rs * gv.z + bv.z;
    y.w = d3 * rs * gv.w + bv.w;
    ((float4*)(Y + (size_t)row * DIM))[tid] = y;
    if (Yhi) {
        size_t base = (size_t)row * DIM + tid * 4;
        float r0, r1, r2, r3;
        uint32_t h0 = pack_hi(y.x, y.y, &r0, &r1);
        uint32_t h1 = pack_hi(y.z, y.w, &r2, &r3);
        *(uint2*)(Yhi + base) = make_uint2(h0, h1);
        *(uint2*)(Ylo + base) = make_uint2(pack_bf(r0, r1), pack_bf(r2, r3));
    }
}

// ---------------------------------------------------------------------------
// Launcher
// ---------------------------------------------------------------------------
extern "C" void kernel_launch(void* const* d_in, const int* in_sizes, int n_in,
                              void* d_out, int out_size)
{
    const float*         x    = (const float*)d_in[0];
    const unsigned char* mask = (const unsigned char*)d_in[1];
    const float* WQ = (const float*)d_in[2];
    const float* bQ = (const float*)d_in[3];
    const float* WK = (const float*)d_in[4];
    const float* bK = (const float*)d_in[5];
    const float* WV = (const float*)d_in[6];
    const float* bV = (const float*)d_in[7];
    const float* WO = (const float*)d_in[8];
    const float* bO = (const float*)d_in[9];
    const float* g0 = (const float*)d_in[10];
    const float* b0 = (const float*)d_in[11];
    const float* W1 = (const float*)d_in[12];
    const float* b1 = (const float*)d_in[13];
    const float* W2 = (const float*)d_in[14];
    const float* b2 = (const float*)d_in[15];
    const float* g1 = (const float*)d_in[16];
    const float* b1n = (const float*)d_in[17];
    float* out = (float*)d_out;

    float* base = nullptr;
    cudaGetSymbolAddress((void**)&base, g_scratch);
    float* T0  = base + OFF_T0;
    float* Hf  = base + OFF_H;
    float* T1  = base + OFF_T1;
    float* bqkv = base + OFF_BQKV;
    __nv_bfloat16* QKVH  = (__nv_bfloat16*)(base + OFF_QKVH);
    __nv_bfloat16* QKVL  = (__nv_bfloat16*)(base + OFF_QKVL);
    __nv_bfloat16* XH  = (__nv_bfloat16*)(base + OFF_XH);
    __nv_bfloat16* XL  = (__nv_bfloat16*)(base + OFF_XL);
    __nv_bfloat16* WQKVH = (__nv_bfloat16*)(base + OFF_WQKVH);
    __nv_bfloat16* WQKVL = (__nv_bfloat16*)(base + OFF_WQKVL);
    __nv_bfloat16* WOH = (__nv_bfloat16*)(base + OFF_WOH);
    __nv_bfloat16* WOL = (__nv_bfloat16*)(base + OFF_WOL);
    __nv_bfloat16* W1H = (__nv_bfloat16*)(base + OFF_W1H);
    __nv_bfloat16* W1L = (__nv_bfloat16*)(base + OFF_W1L);
    __nv_bfloat16* W2H = (__nv_bfloat16*)(base + OFF_W2H);
    __nv_bfloat16* W2L = (__nv_bfloat16*)(base + OFF_W2L);
    __nv_bfloat16* CH  = (__nv_bfloat16*)(base + OFF_CH);
    __nv_bfloat16* CL  = (__nv_bfloat16*)(base + OFF_CL);
    __nv_bfloat16* HH  = (__nv_bfloat16*)(base + OFF_HH);
    __nv_bfloat16* HL  = (__nv_bfloat16*)(base + OFF_HL);
    __nv_bfloat16* FH  = (__nv_bfloat16*)(base + OFF_FH);
    __nv_bfloat16* FL  = (__nv_bfloat16*)(base + OFF_FL);

    cudaFuncSetAttribute(gemm_mma_kernel,
                         cudaFuncAttributeMaxDynamicSharedMemorySize, G_SMEM_DYN);
    cudaFuncSetAttribute(flash_attn_kernel,
                         cudaFuncAttributeMaxDynamicSharedMemorySize, FA_SMEM);

    dim3 tb(32, 8);

    // 0: split x   1: combined QKV weight transpose   2: bias concat
    split_kernel<<<(TOK * DIM / 4 + 255) / 256, 256>>>(
        (const float4*)x, (uint2*)XH, (uint2*)XL, TOK * DIM / 4);
    transpose_split_qkv_kernel<<<dim3(DIM / 32, DIM / 32, 3), tb>>>(
        WQ, WK, WV, WQKVH, WQKVL);
    concat_bias_kernel<<<12, 256>>>(bQ, bK, bV, bqkv);

    // 3: fused QKV GEMM -> bf16 hi/lo  (targeted ncu slot)
    gemm_mma_kernel<<<dim3(QKVS / 128, TOK / 128), 256, G_SMEM_DYN>>>(
        XH, XL, WQKVH, WQKVL, bqkv, nullptr,
        nullptr, QKVH, QKVL, TOK, QKVS, DIM, 0);

    // 4: fused flash attention -> ctx bf16 hi/lo
    flash_attn_kernel<<<dim3(LEN / 128, NB * HEADS), 256, FA_SMEM>>>(
        QKVH, QKVL, mask, CH, CL);

    // 5-7: remaining weight transposes
    transpose_split_kernel<<<dim3(DIM / 32, DIM / 32), tb>>>(WO, WOH, WOL, DIM, DIM);
    transpose_split_kernel<<<dim3(FF / 32, DIM / 32), tb>>>(W1, W1H, W1L, DIM, FF);
    transpose_split_kernel<<<dim3(DIM / 32, FF / 32), tb>>>(W2, W2H, W2L, FF, DIM);

    dim3 gD(DIM / 128, TOK / 128);
    dim3 gF(FF / 128, TOK / 128);

    // 8: O projection + residual(x);  9: layernorm0 (emits split for FFN1)
    gemm_mma_kernel<<<gD, 256, G_SMEM_DYN>>>(CH, CL, WOH, WOL, bO, x,
                                             T0, nullptr, nullptr, TOK, DIM, DIM, 0);
    layernorm_kernel<<<TOK, 256>>>(T0, g0, b0, Hf, HH, HL);

    // 10-11: FFN
    gemm_mma_kernel<<<gF, 256, G_SMEM_DYN>>>(HH, HL, W1H, W1L, b1, nullptr,
                                             nullptr, FH, FL, TOK, FF, DIM, 1);
    gemm_mma_kernel<<<gD, 256, G_SMEM_DYN>>>(FH, FL, W2H, W2L, b2, Hf,
                                             T1, nullptr, nullptr, TOK, DIM, FF, 0);

    // 12: final layernorm -> output
    layernorm_kernel<<<TOK, 256>>>(T1, g1, b1n, out, nullptr, nullptr);
}

// round 9
// speedup vs baseline: 2.8765x; 1.0463x over previous
#include <cuda_runtime.h>
#include <cuda_bf16.h>
#include <math.h>
#include <stdint.h>

// Problem constants
#define NB    16
#define LEN   512
#define DIM   1024
#define HEADS 16
#define DK    64
#define FF    4096
#define TOK   (NB * LEN)          // 8192 rows
#define QKVS  3072                // fused QKV row stride

// ---------------------------------------------------------------------------
// Scratch layout (units: floats)
// ---------------------------------------------------------------------------
#define MFe ((size_t)1 << 20)
#define OFF_QKVH  (0 * MFe)           // bf16 8192x3072
#define OFF_QKVL  (12 * MFe)
#define OFF_T0    (24 * MFe)          // fp32 8192x1024
#define OFF_H     (32 * MFe)
#define OFF_T1    (40 * MFe)
#define OFF_XH    (48 * MFe)          // bf16 8192x1024
#define OFF_XL    (52 * MFe)
#define OFF_WQKVH (56 * MFe)          // bf16 3072x1024
#define OFF_WQKVL (58 * MFe)
#define OFF_WOH   (60 * MFe)          // bf16 1024x1024 (0.5 MFe)
#define OFF_WOL   (OFF_WOH + MFe / 2)
#define OFF_W1H   (61 * MFe)          // bf16 4096x1024
#define OFF_W1L   (63 * MFe)
#define OFF_W2H   (65 * MFe)          // bf16 1024x4096
#define OFF_W2L   (67 * MFe)
#define OFF_CH    (69 * MFe)          // bf16 8192x1024
#define OFF_CL    (73 * MFe)
#define OFF_HH    (77 * MFe)
#define OFF_HL    (81 * MFe)
#define OFF_FH    (85 * MFe)          // bf16 8192x4096
#define OFF_FL    (101 * MFe)
#define OFF_BQKV  (117 * MFe)         // fp32 3072
#define SCRATCH_FLOATS (118 * MFe)

__device__ float g_scratch[SCRATCH_FLOATS];

// ---------------------------------------------------------------------------
// PTX helpers (sm_80-baseline: cp.async, ldmatrix, mma.sync)
// ---------------------------------------------------------------------------
__device__ __forceinline__ uint32_t s2u(const void* p) {
    uint32_t r;
    asm("{ .reg .u64 t; cvta.to.shared.u64 t, %1; cvt.u32.u64 %0, t; }"
        : "=r"(r) : "l"(p));
    return r;
}

__device__ __forceinline__ void cp16(uint32_t dst, const void* src) {
    asm volatile("cp.async.cg.shared.global [%0], [%1], 16;" :: "r"(dst), "l"(src));
}
__device__ __forceinline__ void cp_commit() {
    asm volatile("cp.async.commit_group;" ::: "memory");
}
template <int N> __device__ __forceinline__ void cp_wait() {
    asm volatile("cp.async.wait_group %0;" :: "n"(N) : "memory");
}

__device__ __forceinline__ void ldsm4(uint32_t* r, uint32_t addr) {
    asm volatile("ldmatrix.sync.aligned.m8n8.x4.shared.b16 {%0,%1,%2,%3}, [%4];"
                 : "=r"(r[0]), "=r"(r[1]), "=r"(r[2]), "=r"(r[3]) : "r"(addr));
}
__device__ __forceinline__ void ldsm4t(uint32_t* r, uint32_t addr) {
    asm volatile("ldmatrix.sync.aligned.m8n8.x4.trans.shared.b16 {%0,%1,%2,%3}, [%4];"
                 : "=r"(r[0]), "=r"(r[1]), "=r"(r[2]), "=r"(r[3]) : "r"(addr));
}

__device__ __forceinline__ void mma_bf16(float* d, const uint32_t* a,
                                         uint32_t b0, uint32_t b1) {
    asm volatile(
        "mma.sync.aligned.m16n8k16.row.col.f32.bf16.bf16.f32 "
        "{%0,%1,%2,%3}, {%4,%5,%6,%7}, {%8,%9}, {%0,%1,%2,%3};"
        : "+f"(d[0]), "+f"(d[1]), "+f"(d[2]), "+f"(d[3])
        : "r"(a[0]), "r"(a[1]), "r"(a[2]), "r"(a[3]), "r"(b0), "r"(b1));
}

__device__ __forceinline__ float gelu_exact(float v) {
    return 0.5f * v * (1.0f + erff(v * 0.70710678118654752f));
}

__device__ __forceinline__ uint32_t pack_hi(float a, float b, float* ra, float* rb) {
    __nv_bfloat16 ha = __float2bfloat16(a);
    __nv_bfloat16 hb = __float2bfloat16(b);
    *ra = a - __bfloat162float(ha);
    *rb = b - __bfloat162float(hb);
    return (uint32_t)__bfloat16_as_ushort(ha) |
           ((uint32_t)__bfloat16_as_ushort(hb) << 16);
}
__device__ __forceinline__ uint32_t pack_bf(float a, float b) {
    __nv_bfloat16 ha = __float2bfloat16(a);
    __nv_bfloat16 hb = __float2bfloat16(b);
    return (uint32_t)__bfloat16_as_ushort(ha) |
           ((uint32_t)__bfloat16_as_ushort(hb) << 16);
}

// ---------------------------------------------------------------------------
// bf16-split GEMM via mma.sync: 128 threads, CTA tile 128x64, BK=32,
// 4 warps (64x32 each, 2x2), 2-stage, 3 CTAs/SM.
// ---------------------------------------------------------------------------
#define SA_STRIDE 40                           // bf16 units per smem row (80 B)
#define GA_TILE_B (128 * SA_STRIDE * 2)        // 10240 (128x32 tile)
#define GB_TILE_B (64 * SA_STRIDE * 2)         // 5120  (64x32 tile)
#define G_STAGE_B (2 * GA_TILE_B + 2 * GB_TILE_B)  // 30720
#define G_SMEM_DYN (2 * G_STAGE_B)             // 61440

__device__ __forceinline__ void load_stageA(uint32_t sbase, const __nv_bfloat16* g,
                                            int K, int k0, int tid) {
    #pragma unroll
    for (int i = 0; i < 4; i++) {
        int c = tid + i * 128;                 // 0..511 : 128 rows x 4 chunks
        int row = c >> 2;
        int col = c & 3;
        cp16(sbase + (uint32_t)(row * (SA_STRIDE * 2) + col * 16),
             g + (size_t)row * K + k0 + col * 8);
    }
}
__device__ __forceinline__ void load_stageB(uint32_t sbase, const __nv_bfloat16* g,
                                            int K, int k0, int tid) {
    #pragma unroll
    for (int i = 0; i < 2; i++) {
        int c = tid + i * 128;                 // 0..255 : 64 rows x 4 chunks
        int row = c >> 2;
        int col = c & 3;
        cp16(sbase + (uint32_t)(row * (SA_STRIDE * 2) + col * 16),
             g + (size_t)row * K + k0 + col * 8);
    }
}

extern __shared__ char g_dsm[];

__global__ void __launch_bounds__(128, 3) gemm_mma_kernel(
    const __nv_bfloat16* __restrict__ Ahi, const __nv_bfloat16* __restrict__ Alo,
    const __nv_bfloat16* __restrict__ Bhi, const __nv_bfloat16* __restrict__ Blo,
    const float* __restrict__ bias, const float* __restrict__ resid,
    float* __restrict__ outF,
    __nv_bfloat16* __restrict__ outHi, __nv_bfloat16* __restrict__ outLo,
    int M, int N, int K, int gelu)
{
    const int tid = threadIdx.x;
    const int wid = tid >> 5;
    const int lane = tid & 31;
    const int wr = wid >> 1;       // warp row 0-1 (64 rows each)
    const int wc = wid & 1;        // warp col 0-1 (32 cols each)
    const int bm = blockIdx.y * 128;
    const int bn = blockIdx.x * 64;

    uint32_t db = s2u(g_dsm);

    const __nv_bfloat16* Ah = Ahi + (size_t)bm * K;
    const __nv_bfloat16* Al = Alo + (size_t)bm * K;
    const __nv_bfloat16* Bh = Bhi + (size_t)bn * K;
    const __nv_bfloat16* Bl = Blo + (size_t)bn * K;

    float acc[4][4][4] = {};

    const int nk = K / 32;

    // Prologue: stage 0
    {
        uint32_t sb = db;
        load_stageA(sb, Ah, K, 0, tid);
        load_stageA(sb + GA_TILE_B, Al, K, 0, tid);
        load_stageB(sb + 2 * GA_TILE_B, Bh, K, 0, tid);
        load_stageB(sb + 2 * GA_TILE_B + GB_TILE_B, Bl, K, 0, tid);
        cp_commit();
    }

    const int a_row = (lane & 15);
    const int a_ko  = (lane >> 4) * 8;
    const int b_row = ((lane >> 4) * 8) + (lane & 7);
    const int b_ko  = ((lane >> 3) & 1) * 8;

    for (int kt = 0; kt < nk; kt++) {
        cp_wait<0>();
        __syncthreads();

        if (kt + 1 < nk) {
            uint32_t nb = db + (uint32_t)((kt + 1) & 1) * G_STAGE_B;
            int k0 = (kt + 1) * 32;
            load_stageA(nb, Ah, K, k0, tid);
            load_stageA(nb + GA_TILE_B, Al, K, k0, tid);
            load_stageB(nb + 2 * GA_TILE_B, Bh, K, k0, tid);
            load_stageB(nb + 2 * GA_TILE_B + GB_TILE_B, Bl, K, k0, tid);
            cp_commit();
        }

        uint32_t sb = db + (uint32_t)(kt & 1) * G_STAGE_B;
        uint32_t sAh = sb;
        uint32_t sAl = sb + GA_TILE_B;
        uint32_t sBh = sb + 2 * GA_TILE_B;
        uint32_t sBl = sb + 2 * GA_TILE_B + GB_TILE_B;

        #pragma unroll
        for (int k16 = 0; k16 < 2; k16++) {
            uint32_t bh[2][4], bl[2][4];
            #pragma unroll
            for (int nf = 0; nf < 2; nf++) {
                uint32_t off = (uint32_t)((wc * 32 + nf * 16 + b_row) * (SA_STRIDE * 2)
                                          + (k16 * 16 + b_ko) * 2);
                ldsm4(bh[nf], sBh + off);
                ldsm4(bl[nf], sBl + off);
            }
            #pragma unroll
            for (int mi = 0; mi < 4; mi++) {
                uint32_t ah[4], al[4];
                uint32_t off = (uint32_t)((wr * 64 + mi * 16 + a_row) * (SA_STRIDE * 2)
                                          + (k16 * 16 + a_ko) * 2);
                ldsm4(ah, sAh + off);
                ldsm4(al, sAl + off);
                #pragma unroll
                for (int ni = 0; ni < 4; ni++) {
                    int nf = ni >> 1, o = (ni & 1) * 2;
                    mma_bf16(acc[mi][ni], ah, bh[nf][o], bh[nf][o + 1]);
                    mma_bf16(acc[mi][ni], ah, bl[nf][o], bl[nf][o + 1]);
                    mma_bf16(acc[mi][ni], al, bh[nf][o], bh[nf][o + 1]);
                }
            }
        }
    }

    // Epilogue
    const int tq = lane >> 2;
    const int tc = (lane & 3) * 2;
    #pragma unroll
    for (int mi = 0; mi < 4; mi++) {
        #pragma unroll
        for (int ni = 0; ni < 4; ni++) {
            int col = bn + wc * 32 + ni * 8 + tc;
            float bx = bias[col], by = bias[col + 1];
            #pragma unroll
            for (int half = 0; half < 2; half++) {
                int row = bm + wr * 64 + mi * 16 + tq + half * 8;
                float v0 = acc[mi][ni][half * 2 + 0] + bx;
                float v1 = acc[mi][ni][half * 2 + 1] + by;
                if (gelu) { v0 = gelu_exact(v0); v1 = gelu_exact(v1); }
                if (resid) {
                    float2 rv = *(const float2*)(resid + (size_t)row * N + col);
                    v0 += rv.x; v1 += rv.y;
                }
                if (outF)
                    *(float2*)(outF + (size_t)row * N + col) = make_float2(v0, v1);
                if (outHi) {
                    float ra, rb;
                    uint32_t hv = pack_hi(v0, v1, &ra, &rb);
                    *(uint32_t*)(outHi + (size_t)row * N + col) = hv;
                    *(uint32_t*)(outLo + (size_t)row * N + col) = pack_bf(ra, rb);
                }
            }
        }
    }
}

// ---------------------------------------------------------------------------
// Fused flash attention: scores + online softmax + P.V in one kernel.
// Grid (LEN/128, NB*HEADS); 256 threads (8 warps, 16 q-rows each).
// KV processed in 8 chunks of 64, double-buffered cp.async; 2 CTAs/SM.
// ---------------------------------------------------------------------------
#define FA_STRIDE 144                          // bytes per smem row (64 bf16 + pad)
#define FA_QTILE (128 * FA_STRIDE)             // 18432
#define FA_KTILE (64 * FA_STRIDE)              // 9216
#define FA_KVBASE (2 * FA_QTILE)               // after Qh,Ql
#define FA_BUF_B (4 * FA_KTILE)                // Kh,Kl,Vh,Vl per buffer = 36864
#define FA_SMEM (2 * FA_QTILE + 2 * FA_BUF_B)  // 110592

__global__ void __launch_bounds__(256, 2) flash_attn_kernel(
    const __nv_bfloat16* __restrict__ QKVH, const __nv_bfloat16* __restrict__ QKVL,
    const unsigned char* __restrict__ mask,
    __nv_bfloat16* __restrict__ Chi, __nv_bfloat16* __restrict__ Clo)
{
    const int tid = threadIdx.x;
    const int wid = tid >> 5;
    const int lane = tid & 31;
    const int b = blockIdx.y;
    const int n = b >> 4;
    const int h = b & 15;
    const int q0 = blockIdx.x * 128;

    uint32_t db = s2u(g_dsm);
    uint32_t sQh = db, sQl = db + FA_QTILE;

    const __nv_bfloat16* Qh = QKVH + (size_t)n * LEN * QKVS + h * DK;
    const __nv_bfloat16* Ql = QKVL + (size_t)n * LEN * QKVS + h * DK;
    const __nv_bfloat16* Kh = QKVH + (size_t)n * LEN * QKVS + DIM + h * DK;
    const __nv_bfloat16* Kl = QKVL + (size_t)n * LEN * QKVS + DIM + h * DK;
    const __nv_bfloat16* Vh = QKVH + (size_t)n * LEN * QKVS + 2 * DIM + h * DK;
    const __nv_bfloat16* Vl = QKVL + (size_t)n * LEN * QKVS + 2 * DIM + h * DK;

    // Load Q tile (128 x 64 hi/lo)
    #pragma unroll
    for (int i = 0; i < 4; i++) {
        int c = tid + i * 256;
        int row = c >> 3;
        int col = c & 7;
        uint32_t doff = (uint32_t)(row * FA_STRIDE + col * 16);
        cp16(sQh + doff, Qh + (size_t)(q0 + row) * QKVS + col * 8);
        cp16(sQl + doff, Ql + (size_t)(q0 + row) * QKVS + col * 8);
    }
    // KV chunk loader: 64 rows x 64 cols, 4 tiles (Kh,Kl,Vh,Vl)
    auto load_kv = [&](int chunk) {
        uint32_t sb = db + FA_KVBASE + (uint32_t)(chunk & 1) * FA_BUF_B;
        #pragma unroll
        for (int i = 0; i < 2; i++) {
            int c = tid + i * 256;
            int row = c >> 3;                   // 0..63
            int col = c & 7;
            uint32_t doff = (uint32_t)(row * FA_STRIDE + col * 16);
            size_t goff = (size_t)(chunk * 64 + row) * QKVS + col * 8;
            cp16(sb + doff, Kh + goff);
            cp16(sb + FA_KTILE + doff, Kl + goff);
            cp16(sb + 2 * FA_KTILE + doff, Vh + goff);
            cp16(sb + 3 * FA_KTILE + doff, Vl + goff);
        }
    };
    load_kv(0);
    cp_commit();

    const int a_row = (lane & 15);
    const int a_ko  = (lane >> 4) * 8;
    const int b_row = ((lane >> 4) * 8) + (lane & 7);
    const int b_ko  = ((lane >> 3) & 1) * 8;
    const int v_row = (lane & 7) + ((lane >> 3) & 1) * 8;
    const int v_cb  = (lane >> 4) * 16;
    const int tq = lane >> 2;
    const int tc = (lane & 3) * 2;

    const int r0 = q0 + wid * 16 + tq;
    const int r1 = r0 + 8;
    const unsigned char* mp = mask + (size_t)n * LEN * LEN;

    uint32_t qh[4][4], ql[4][4];
    float o_acc[8][4] = {};
    float m_run0 = -INFINITY, m_run1 = -INFINITY;
    float l0 = 0.0f, l1 = 0.0f;

    for (int c = 0; c < 8; c++) {
        if (c + 1 < 8) load_kv(c + 1);
        cp_commit();
        cp_wait<1>();
        __syncthreads();

        if (c == 0) {
            #pragma unroll
            for (int k16 = 0; k16 < 4; k16++) {
                uint32_t off = (uint32_t)((wid * 16 + a_row) * FA_STRIDE
                                          + (k16 * 16 + a_ko) * 2);
                ldsm4(qh[k16], sQh + off);
                ldsm4(ql[k16], sQl + off);
            }
        }

        uint32_t sb = db + FA_KVBASE + (uint32_t)(c & 1) * FA_BUF_B;
        uint32_t sKhh = sb, sKll = sb + FA_KTILE;
        uint32_t sVhh = sb + 2 * FA_KTILE, sVll = sb + 3 * FA_KTILE;

        // --- scores: 16 q x 64 k per warp ---
        float s[8][4] = {};
        #pragma unroll
        for (int k16 = 0; k16 < 4; k16++) {
            #pragma unroll
            for (int nf = 0; nf < 4; nf++) {
                uint32_t bh[4], bl[4];
                uint32_t off = (uint32_t)((nf * 16 + b_row) * FA_STRIDE
                                          + (k16 * 16 + b_ko) * 2);
                ldsm4(bh, sKhh + off);
                ldsm4(bl, sKll + off);
                #pragma unroll
                for (int o = 0; o < 2; o++) {
                    int ni = nf * 2 + o;
                    mma_bf16(s[ni], qh[k16], bh[o * 2], bh[o * 2 + 1]);
                    mma_bf16(s[ni], qh[k16], bl[o * 2], bl[o * 2 + 1]);
                    mma_bf16(s[ni], ql[k16], bh[o * 2], bh[o * 2 + 1]);
                }
            }
        }

        // --- scale + mask ---
        const unsigned char* mr0 = mp + (size_t)r0 * LEN + c * 64 + tc;
        const unsigned char* mr1 = mp + (size_t)r1 * LEN + c * 64 + tc;
        #pragma unroll
        for (int ni = 0; ni < 8; ni++) {
            uchar2 m0v = *(const uchar2*)(mr0 + ni * 8);
            uchar2 m1v = *(const uchar2*)(mr1 + ni * 8);
            s[ni][0] = m0v.x ? -INFINITY : s[ni][0] * 0.125f;
            s[ni][1] = m0v.y ? -INFINITY : s[ni][1] * 0.125f;
            s[ni][2] = m1v.x ? -INFINITY : s[ni][2] * 0.125f;
            s[ni][3] = m1v.y ? -INFINITY : s[ni][3] * 0.125f;
        }

        // --- online softmax update ---
        float rm0 = -INFINITY, rm1 = -INFINITY;
        #pragma unroll
        for (int ni = 0; ni < 8; ni++) {
            rm0 = fmaxf(rm0, fmaxf(s[ni][0], s[ni][1]));
            rm1 = fmaxf(rm1, fmaxf(s[ni][2], s[ni][3]));
        }
        rm0 = fmaxf(rm0, __shfl_xor_sync(0xffffffffu, rm0, 1));
        rm0 = fmaxf(rm0, __shfl_xor_sync(0xffffffffu, rm0, 2));
        rm1 = fmaxf(rm1, __shfl_xor_sync(0xffffffffu, rm1, 1));
        rm1 = fmaxf(rm1, __shfl_xor_sync(0xffffffffu, rm1, 2));

        float mn0 = fmaxf(m_run0, rm0);
        float mn1 = fmaxf(m_run1, rm1);
        bool dead0 = (mn0 == -INFINITY);
        bool dead1 = (mn1 == -INFINITY);
        float alpha0 = dead0 ? 1.0f : __expf(m_run0 - mn0);
        float alpha1 = dead1 ? 1.0f : __expf(m_run1 - mn1);

        float ps0 = 0.0f, ps1 = 0.0f;
        #pragma unroll
        for (int ni = 0; ni < 8; ni++) {
            s[ni][0] = dead0 ? 0.0f : __expf(s[ni][0] - mn0);
            s[ni][1] = dead0 ? 0.0f : __expf(s[ni][1] - mn0);
            s[ni][2] = dead1 ? 0.0f : __expf(s[ni][2] - mn1);
            s[ni][3] = dead1 ? 0.0f : __expf(s[ni][3] - mn1);
            ps0 += s[ni][0] + s[ni][1];
            ps1 += s[ni][2] + s[ni][3];
        }
        ps0 += __shfl_xor_sync(0xffffffffu, ps0, 1);
        ps0 += __shfl_xor_sync(0xffffffffu, ps0, 2);
        ps1 += __shfl_xor_sync(0xffffffffu, ps1, 1);
        ps1 += __shfl_xor_sync(0xffffffffu, ps1, 2);

        l0 = l0 * alpha0 + ps0;
        l1 = l1 * alpha1 + ps1;
        m_run0 = mn0;
        m_run1 = mn1;

        #pragma unroll
        for (int ni = 0; ni < 8; ni++) {
            o_acc[ni][0] *= alpha0; o_acc[ni][1] *= alpha0;
            o_acc[ni][2] *= alpha1; o_acc[ni][3] *= alpha1;
        }

        // --- P . V (P fragments built in registers) ---
        #pragma unroll
        for (int j = 0; j < 4; j++) {
            uint32_t ah[4], al[4];
            float ra, rb;
            ah[0] = pack_hi(s[2 * j][0],     s[2 * j][1],     &ra, &rb); al[0] = pack_bf(ra, rb);
            ah[1] = pack_hi(s[2 * j][2],     s[2 * j][3],     &ra, &rb); al[1] = pack_bf(ra, rb);
            ah[2] = pack_hi(s[2 * j + 1][0], s[2 * j + 1][1], &ra, &rb); al[2] = pack_bf(ra, rb);
            ah[3] = pack_hi(s[2 * j + 1][2], s[2 * j + 1][3], &ra, &rb); al[3] = pack_bf(ra, rb);
            #pragma unroll
            for (int nf = 0; nf < 4; nf++) {
                uint32_t bh[4], bl[4];
                uint32_t off = (uint32_t)((j * 16 + v_row) * FA_STRIDE
                                          + (nf * 16) * 2 + v_cb);
                ldsm4t(bh, sVhh + off);
                ldsm4t(bl, sVll + off);
                #pragma unroll
                for (int o = 0; o < 2; o++) {
                    int ni = nf * 2 + o;
                    mma_bf16(o_acc[ni], ah, bh[o * 2], bh[o * 2 + 1]);
                    mma_bf16(o_acc[ni], ah, bl[o * 2], bl[o * 2 + 1]);
                    mma_bf16(o_acc[ni], al, bh[o * 2], bh[o * 2 + 1]);
                }
            }
        }
        __syncthreads();
    }

    // --- finalize ---
    float inv0 = (l0 > 0.0f) ? 1.0f / l0 : 0.0f;
    float inv1 = (l1 > 0.0f) ? 1.0f / l1 : 0.0f;
    size_t row0 = (size_t)n * LEN + r0;
    size_t row1 = (size_t)n * LEN + r1;
    #pragma unroll
    for (int ni = 0; ni < 8; ni++) {
        int col = h * DK + ni * 8 + tc;
        float ra, rb;
        uint32_t hv0 = pack_hi(o_acc[ni][0] * inv0, o_acc[ni][1] * inv0, &ra, &rb);
        uint32_t lv0 = pack_bf(ra, rb);
        *(uint32_t*)(Chi + row0 * DIM + col) = hv0;
        *(uint32_t*)(Clo + row0 * DIM + col) = lv0;
        uint32_t hv1 = pack_hi(o_acc[ni][2] * inv1, o_acc[ni][3] * inv1, &ra, &rb);
        uint32_t lv1 = pack_bf(ra, rb);
        *(uint32_t*)(Chi + row1 * DIM + col) = hv1;
        *(uint32_t*)(Clo + row1 * DIM + col) = lv1;
    }
}

// ---------------------------------------------------------------------------
// Elementwise fp32 -> bf16 hi/lo split
// ---------------------------------------------------------------------------
__global__ __launch_bounds__(256) void split_kernel(
    const float4* __restrict__ X, uint2* __restrict__ Hh, uint2* __restrict__ Ll, int n4)
{
    int i = blockIdx.x * 256 + threadIdx.x;
    if (i >= n4) return;
    float4 v = X[i];
    float r0, r1, r2, r3;
    uint32_t h0 = pack_hi(v.x, v.y, &r0, &r1);
    uint32_t h1 = pack_hi(v.z, v.w, &r2, &r3);
    Hh[i] = make_uint2(h0, h1);
    Ll[i] = make_uint2(pack_bf(r0, r1), pack_bf(r2, r3));
}

// ---------------------------------------------------------------------------
// Transposed split: W[Kr,Nc] fp32 -> TH/TL [Nc,Kr] bf16
// ---------------------------------------------------------------------------
__device__ __forceinline__ void tsplit_body(
    const float* __restrict__ W, __nv_bfloat16* __restrict__ TH,
    __nv_bfloat16* __restrict__ TL, int Kr, int Nc)
{
    __shared__ float t[32][33];
    int n0 = blockIdx.x * 32, k0 = blockIdx.y * 32;
    int tx = threadIdx.x, ty = threadIdx.y;     // 32 x 8
    #pragma unroll
    for (int i = 0; i < 4; i++)
        t[ty + i * 8][tx] = W[(size_t)(k0 + ty + i * 8) * Nc + n0 + tx];
    __syncthreads();
    #pragma unroll
    for (int i = 0; i < 4; i++) {
        int n = n0 + ty + i * 8;
        int k = k0 + tx;
        float v = t[tx][ty + i * 8];
        __nv_bfloat16 h = __float2bfloat16(v);
        TH[(size_t)n * Kr + k] = h;
        TL[(size_t)n * Kr + k] = __float2bfloat16(v - __bfloat162float(h));
    }
}

__global__ __launch_bounds__(256) void transpose_split_kernel(
    const float* __restrict__ W, __nv_bfloat16* __restrict__ TH,
    __nv_bfloat16* __restrict__ TL, int Kr, int Nc)
{
    tsplit_body(W, TH, TL, Kr, Nc);
}

__global__ __launch_bounds__(256) void transpose_split_qkv_kernel(
    const float* __restrict__ WQ, const float* __restrict__ WK,
    const float* __restrict__ WV,
    __nv_bfloat16* __restrict__ TH, __nv_bfloat16* __restrict__ TL)
{
    int z = blockIdx.z;
    const float* W = (z == 0) ? WQ : (z == 1) ? WK : WV;
    tsplit_body(W, TH + (size_t)z * DIM * DIM, TL + (size_t)z * DIM * DIM, DIM, DIM);
}

__global__ __launch_bounds__(256) void concat_bias_kernel(
    const float* __restrict__ a, const float* __restrict__ b,
    const float* __restrict__ c, float* __restrict__ o)
{
    int i = blockIdx.x * 256 + threadIdx.x;
    if (i < 1024) o[i] = a[i];
    else if (i < 2048) o[i] = b[i - 1024];
    else if (i < 3072) o[i] = c[i - 2048];
}

// ---------------------------------------------------------------------------
// LayerNorm over last dim (1024); optional bf16 hi/lo split output
// ---------------------------------------------------------------------------
__global__ __launch_bounds__(256) void layernorm_kernel(
    const float* __restrict__ X, const float* __restrict__ gg,
    const float* __restrict__ bb, float* __restrict__ Y,
    __nv_bfloat16* __restrict__ Yhi, __nv_bfloat16* __restrict__ Ylo)
{
    int row = blockIdx.x;
    int tid = threadIdx.x;
    const float4* Xp = (const float4*)(X + (size_t)row * DIM);
    float4 x = Xp[tid];
    __shared__ float red[8];

    float s = x.x + x.y + x.z + x.w;
    #pragma unroll
    for (int o = 16; o; o >>= 1) s += __shfl_xor_sync(0xffffffffu, s, o);
    if ((tid & 31) == 0) red[tid >> 5] = s;
    __syncthreads();
    float mean = (red[0] + red[1] + red[2] + red[3] +
                  red[4] + red[5] + red[6] + red[7]) * (1.0f / DIM);

    float d0 = x.x - mean, d1 = x.y - mean, d2 = x.z - mean, d3 = x.w - mean;
    float s2 = d0 * d0 + d1 * d1 + d2 * d2 + d3 * d3;
    __syncthreads();
    #pragma unroll
    for (int o = 16; o; o >>= 1) s2 += __shfl_xor_sync(0xffffffffu, s2, o);
    if ((tid & 31) == 0) red[tid >> 5] = s2;
    __syncthreads();
    float var = (red[0] + red[1] + red[2] + red[3] +
                 red[4] + red[5] + red[6] + red[7]) * (1.0f / DIM);
    float rs = rsqrtf(var + 1e-5f);

    float4 gv = ((const float4*)gg)[tid];
    float4 bv = ((const float4*)bb)[tid];
    float4 y;
    y.x = d0 * rs * gv.x + bv.x;
    y.y = d1 * rs * gv.y + bv.y;
    y.z = d2 * rs * gv.z + bv.z;
    y.w = d3 * rs * gv.w + bv.w;
    ((float4*)(Y + (size_t)row * DIM))[tid] = y;
    if (Yhi) {
        size_t base = (size_t)row * DIM + tid * 4;
        float r0, r1, r2, r3;
        uint32_t h0 = pack_hi(y.x, y.y, &r0, &r1);
        uint32_t h1 = pack_hi(y.z, y.w, &r2, &r3);
        *(uint2*)(Yhi + base) = make_uint2(h0, h1);
        *(uint2*)(Ylo + base) = make_uint2(pack_bf(r0, r1), pack_bf(r2, r3));
    }
}

// ---------------------------------------------------------------------------
// Launcher
// ---------------------------------------------------------------------------
extern "C" void kernel_launch(void* const* d_in, const int* in_sizes, int n_in,
                              void* d_out, int out_size)
{
    const float*         x    = (const float*)d_in[0];
    const unsigned char* mask = (const unsigned char*)d_in[1];
    const float* WQ = (const float*)d_in[2];
    const float* bQ = (const float*)d_in[3];
    const float* WK = (const float*)d_in[4];
    const float* bK = (const float*)d_in[5];
    const float* WV = (const float*)d_in[6];
    const float* bV = (const float*)d_in[7];
    const float* WO = (const float*)d_in[8];
    const float* bO = (const float*)d_in[9];
    const float* g0 = (const float*)d_in[10];
    const float* b0 = (const float*)d_in[11];
    const float* W1 = (const float*)d_in[12];
    const float* b1 = (const float*)d_in[13];
    const float* W2 = (const float*)d_in[14];
    const float* b2 = (const float*)d_in[15];
    const float* g1 = (const float*)d_in[16];
    const float* b1n = (const float*)d_in[17];
    float* out = (float*)d_out;

    float* base = nullptr;
    cudaGetSymbolAddress((void**)&base, g_scratch);
    float* T0  = base + OFF_T0;
    float* Hf  = base + OFF_H;
    float* T1  = base + OFF_T1;
    float* bqkv = base + OFF_BQKV;
    __nv_bfloat16* QKVH  = (__nv_bfloat16*)(base + OFF_QKVH);
    __nv_bfloat16* QKVL  = (__nv_bfloat16*)(base + OFF_QKVL);
    __nv_bfloat16* XH  = (__nv_bfloat16*)(base + OFF_XH);
    __nv_bfloat16* XL  = (__nv_bfloat16*)(base + OFF_XL);
    __nv_bfloat16* WQKVH = (__nv_bfloat16*)(base + OFF_WQKVH);
    __nv_bfloat16* WQKVL = (__nv_bfloat16*)(base + OFF_WQKVL);
    __nv_bfloat16* WOH = (__nv_bfloat16*)(base + OFF_WOH);
    __nv_bfloat16* WOL = (__nv_bfloat16*)(base + OFF_WOL);
    __nv_bfloat16* W1H = (__nv_bfloat16*)(base + OFF_W1H);
    __nv_bfloat16* W1L = (__nv_bfloat16*)(base + OFF_W1L);
    __nv_bfloat16* W2H = (__nv_bfloat16*)(base + OFF_W2H);
    __nv_bfloat16* W2L = (__nv_bfloat16*)(base + OFF_W2L);
    __nv_bfloat16* CH  = (__nv_bfloat16*)(base + OFF_CH);
    __nv_bfloat16* CL  = (__nv_bfloat16*)(base + OFF_CL);
    __nv_bfloat16* HH  = (__nv_bfloat16*)(base + OFF_HH);
    __nv_bfloat16* HL  = (__nv_bfloat16*)(base + OFF_HL);
    __nv_bfloat16* FH  = (__nv_bfloat16*)(base + OFF_FH);
    __nv_bfloat16* FL  = (__nv_bfloat16*)(base + OFF_FL);

    cudaFuncSetAttribute(gemm_mma_kernel,
                         cudaFuncAttributeMaxDynamicSharedMemorySize, G_SMEM_DYN);
    cudaFuncSetAttribute(flash_attn_kernel,
                         cudaFuncAttributeMaxDynamicSharedMemorySize, FA_SMEM);

    dim3 tb(32, 8);

    // 0: split x   1: combined QKV weight transpose   2: bias concat
    split_kernel<<<(TOK * DIM / 4 + 255) / 256, 256>>>(
        (const float4*)x, (uint2*)XH, (uint2*)XL, TOK * DIM / 4);
    transpose_split_qkv_kernel<<<dim3(DIM / 32, DIM / 32, 3), tb>>>(
        WQ, WK, WV, WQKVH, WQKVL);
    concat_bias_kernel<<<12, 256>>>(bQ, bK, bV, bqkv);

    // 3: fused QKV GEMM -> bf16 hi/lo  (targeted ncu slot)
    gemm_mma_kernel<<<dim3(QKVS / 64, TOK / 128), 128, G_SMEM_DYN>>>(
        XH, XL, WQKVH, WQKVL, bqkv, nullptr,
        nullptr, QKVH, QKVL, TOK, QKVS, DIM, 0);

    // 4: fused flash attention -> ctx bf16 hi/lo
    flash_attn_kernel<<<dim3(LEN / 128, NB * HEADS), 256, FA_SMEM>>>(
        QKVH, QKVL, mask, CH, CL);

    // 5-7: remaining weight transposes
    transpose_split_kernel<<<dim3(DIM / 32, DIM / 32), tb>>>(WO, WOH, WOL, DIM, DIM);
    transpose_split_kernel<<<dim3(FF / 32, DIM / 32), tb>>>(W1, W1H, W1L, DIM, FF);
    transpose_split_kernel<<<dim3(DIM / 32, FF / 32), tb>>>(W2, W2H, W2L, FF, DIM);

    dim3 gD(DIM / 64, TOK / 128);
    dim3 gF(FF / 64, TOK / 128);

    // 8: O projection + residual(x);  9: layernorm0 (emits split for FFN1)
    gemm_mma_kernel<<<gD, 128, G_SMEM_DYN>>>(CH, CL, WOH, WOL, bO, x,
                                             T0, nullptr, nullptr, TOK, DIM, DIM, 0);
    layernorm_kernel<<<TOK, 256>>>(T0, g0, b0, Hf, HH, HL);

    // 10-11: FFN
    gemm_mma_kernel<<<gF, 128, G_SMEM_DYN>>>(HH, HL, W1H, W1L, b1, nullptr,
                                             nullptr, FH, FL, TOK, FF, DIM, 1);
    gemm_mma_kernel<<<gD, 128, G_SMEM_DYN>>>(FH, FL, W2H, W2L, b2, Hf,
                                             T1, nullptr, nullptr, TOK, DIM, FF, 0);

    // 12: final layernorm -> output
    layernorm_kernel<<<TOK, 256>>>(T1, g1, b1n, out, nullptr, nullptr);
}